// round 1
// baseline (speedup 1.0000x reference)
#include <cuda_runtime.h>
#include <math.h>

// Problem dims (fixed by the dataset)
#define BB 2
#define NN_ 4096
#define DD 512
#define HH 8
#define DK 64

// Scratch (device globals — no allocation allowed)
__device__ float g_qp[BB * NN_ * DD];
__device__ float g_kp[BB * NN_ * DD];
__device__ float g_vp[BB * NN_ * DD];
__device__ float g_feat[BB * NN_ * DD];

// ---------------------------------------------------------------------------
// Generic register-blocked SGEMM.
//   BT=true : C = alpha * A(MxK,lda) @ B(NxK,ldb)^T   (NT)
//   BT=false: C = alpha * A(MxK,lda) @ B(KxN,ldb)     (NN)
// Batched over blockIdx.z via (b = z/H, h = z%H) strides.
// Optional residual R (row-major, ldr) added in epilogue (only used batch=1).
// All dims assumed divisible by the tile sizes (true for this problem).
// ---------------------------------------------------------------------------
template<int BM, int BN, int BK, int TM, int TN, bool BT>
__global__ void __launch_bounds__((BM / TM) * (BN / TN))
gemm_k(int M, int N, int K,
       const float* __restrict__ A, int lda, long long sAb, long long sAh,
       const float* __restrict__ Bm, int ldb, long long sBb, long long sBh,
       float* __restrict__ C, int ldc, long long sCb, long long sCh,
       const float* __restrict__ R, int ldr,
       float alpha, int H)
{
    constexpr int THREADS = (BM / TM) * (BN / TN);
    const int z = blockIdx.z;
    const int bz = z / H;
    const int hz = z - bz * H;
    A  += (long long)bz * sAb + (long long)hz * sAh;
    Bm += (long long)bz * sBb + (long long)hz * sBh;
    C  += (long long)bz * sCb + (long long)hz * sCh;

    __shared__ float As[BK][BM + 4];
    __shared__ float Bs[BK][BN + 4];

    const int tid = threadIdx.x;
    const int tx = tid % (BN / TN);
    const int ty = tid / (BN / TN);
    const int m0 = blockIdx.y * BM;
    const int n0 = blockIdx.x * BN;

    float acc[TM][TN];
#pragma unroll
    for (int i = 0; i < TM; i++)
#pragma unroll
        for (int j = 0; j < TN; j++) acc[i][j] = 0.0f;

    for (int k0 = 0; k0 < K; k0 += BK) {
        // ---- load A tile: BM x BK (stored transposed in shared) ----
        for (int i = tid; i < BM * BK / 4; i += THREADS) {
            int r  = i / (BK / 4);
            int kq = i % (BK / 4);
            float4 t4 = *reinterpret_cast<const float4*>(
                A + (long long)(m0 + r) * lda + k0 + kq * 4);
            As[kq * 4 + 0][r] = t4.x;
            As[kq * 4 + 1][r] = t4.y;
            As[kq * 4 + 2][r] = t4.z;
            As[kq * 4 + 3][r] = t4.w;
        }
        // ---- load B tile ----
        if (BT) {
            for (int i = tid; i < BN * BK / 4; i += THREADS) {
                int r  = i / (BK / 4);
                int kq = i % (BK / 4);
                float4 t4 = *reinterpret_cast<const float4*>(
                    Bm + (long long)(n0 + r) * ldb + k0 + kq * 4);
                Bs[kq * 4 + 0][r] = t4.x;
                Bs[kq * 4 + 1][r] = t4.y;
                Bs[kq * 4 + 2][r] = t4.z;
                Bs[kq * 4 + 3][r] = t4.w;
            }
        } else {
            for (int i = tid; i < BK * BN / 4; i += THREADS) {
                int kk = i / (BN / 4);
                int cq = i % (BN / 4);
                float4 t4 = *reinterpret_cast<const float4*>(
                    Bm + (long long)(k0 + kk) * ldb + n0 + cq * 4);
                *reinterpret_cast<float4*>(&Bs[kk][cq * 4]) = t4;
            }
        }
        __syncthreads();

#pragma unroll
        for (int kk = 0; kk < BK; kk++) {
            float a[TM], bv[TN];
#pragma unroll
            for (int i = 0; i < TM; i++) a[i] = As[kk][ty * TM + i];
#pragma unroll
            for (int j = 0; j < TN; j++) bv[j] = Bs[kk][tx * TN + j];
#pragma unroll
            for (int i = 0; i < TM; i++)
#pragma unroll
                for (int j = 0; j < TN; j++) acc[i][j] += a[i] * bv[j];
        }
        __syncthreads();
    }

    // ---- epilogue ----
#pragma unroll
    for (int i = 0; i < TM; i++) {
        const int row = m0 + ty * TM + i;
        const long long crow = (long long)row * ldc;
#pragma unroll
        for (int j = 0; j < TN; j += 4) {
            const int col = n0 + tx * TN + j;
            float4 o;
            o.x = alpha * acc[i][j + 0];
            o.y = alpha * acc[i][j + 1];
            o.z = alpha * acc[i][j + 2];
            o.w = alpha * acc[i][j + 3];
            if (R != nullptr) {
                float4 r4 = *reinterpret_cast<const float4*>(
                    R + (long long)row * ldr + col);
                o.x += r4.x; o.y += r4.y; o.z += r4.z; o.w += r4.w;
            }
            *reinterpret_cast<float4*>(C + crow + col) = o;
        }
    }
}

// ---------------------------------------------------------------------------
// In-place row softmax: one block (256 threads) per 4096-element row.
// ---------------------------------------------------------------------------
__global__ void softmax_rows(float* __restrict__ attn)
{
    const long long row = blockIdx.x;
    float4* p = reinterpret_cast<float4*>(attn + row * (long long)NN_);
    const int t = threadIdx.x;
    const int lane = t & 31, warp = t >> 5;
    __shared__ float red[32];

    float4 vv[4];
    float m = -INFINITY;
#pragma unroll
    for (int i = 0; i < 4; i++) {
        vv[i] = p[t + i * 256];
        m = fmaxf(m, fmaxf(fmaxf(vv[i].x, vv[i].y), fmaxf(vv[i].z, vv[i].w)));
    }
    // block max
#pragma unroll
    for (int o = 16; o > 0; o >>= 1) m = fmaxf(m, __shfl_xor_sync(~0u, m, o));
    if (lane == 0) red[warp] = m;
    __syncthreads();
    if (warp == 0) {
        float x = (lane < 8) ? red[lane] : -INFINITY;
#pragma unroll
        for (int o = 16; o > 0; o >>= 1) x = fmaxf(x, __shfl_xor_sync(~0u, x, o));
        if (lane == 0) red[0] = x;
    }
    __syncthreads();
    m = red[0];
    __syncthreads();

    float s = 0.0f;
#pragma unroll
    for (int i = 0; i < 4; i++) {
        vv[i].x = __expf(vv[i].x - m);
        vv[i].y = __expf(vv[i].y - m);
        vv[i].z = __expf(vv[i].z - m);
        vv[i].w = __expf(vv[i].w - m);
        s += vv[i].x + vv[i].y + vv[i].z + vv[i].w;
    }
#pragma unroll
    for (int o = 16; o > 0; o >>= 1) s += __shfl_xor_sync(~0u, s, o);
    if (lane == 0) red[warp] = s;
    __syncthreads();
    if (warp == 0) {
        float x = (lane < 8) ? red[lane] : 0.0f;
#pragma unroll
        for (int o = 16; o > 0; o >>= 1) x += __shfl_xor_sync(~0u, x, o);
        if (lane == 0) red[0] = x;
    }
    __syncthreads();
    const float inv = 1.0f / red[0];

#pragma unroll
    for (int i = 0; i < 4; i++) {
        vv[i].x *= inv; vv[i].y *= inv; vv[i].z *= inv; vv[i].w *= inv;
        p[t + i * 256] = vv[i];
    }
}

// ---------------------------------------------------------------------------
// In-place row LayerNorm: one block (256 threads) per 512-element row.
// ---------------------------------------------------------------------------
__global__ void layernorm_rows(float* __restrict__ y,
                               const float* __restrict__ gamma,
                               const float* __restrict__ beta)
{
    const long long base = (long long)blockIdx.x * DD;
    const int t = threadIdx.x;
    const int lane = t & 31, warp = t >> 5;
    __shared__ float red[32];

    float x0 = y[base + t];
    float x1 = y[base + t + 256];

    float s = x0 + x1;
#pragma unroll
    for (int o = 16; o > 0; o >>= 1) s += __shfl_xor_sync(~0u, s, o);
    if (lane == 0) red[warp] = s;
    __syncthreads();
    if (warp == 0) {
        float x = (lane < 8) ? red[lane] : 0.0f;
#pragma unroll
        for (int o = 16; o > 0; o >>= 1) x += __shfl_xor_sync(~0u, x, o);
        if (lane == 0) red[0] = x;
    }
    __syncthreads();
    const float mu = red[0] * (1.0f / DD);
    __syncthreads();

    const float d0 = x0 - mu, d1 = x1 - mu;
    float v = d0 * d0 + d1 * d1;
#pragma unroll
    for (int o = 16; o > 0; o >>= 1) v += __shfl_xor_sync(~0u, v, o);
    if (lane == 0) red[warp] = v;
    __syncthreads();
    if (warp == 0) {
        float x = (lane < 8) ? red[lane] : 0.0f;
#pragma unroll
        for (int o = 16; o > 0; o >>= 1) x += __shfl_xor_sync(~0u, x, o);
        if (lane == 0) red[0] = x;
    }
    __syncthreads();
    const float r = rsqrtf(red[0] * (1.0f / DD) + 1e-5f);

    y[base + t]       = d0 * r * gamma[t]       + beta[t];
    y[base + t + 256] = d1 * r * gamma[t + 256] + beta[t + 256];
}

// ---------------------------------------------------------------------------
extern "C" void kernel_launch(void* const* d_in, const int* in_sizes, int n_in,
                              void* d_out, int out_size)
{
    const float* q    = (const float*)d_in[0];
    const float* k    = (const float*)d_in[1];
    const float* v    = (const float*)d_in[2];
    const float* w_q  = (const float*)d_in[3];
    const float* w_k  = (const float*)d_in[4];
    const float* w_v  = (const float*)d_in[5];
    const float* w_fc = (const float*)d_in[6];
    const float* gam  = (const float*)d_in[7];
    const float* bet  = (const float*)d_in[8];

    float* out  = (float*)d_out;                          // [B,N,D]
    float* attn = out + (long long)BB * NN_ * DD;         // [B,H,N,N]

    float *qp, *kp, *vp, *feat;
    cudaGetSymbolAddress((void**)&qp,   g_qp);
    cudaGetSymbolAddress((void**)&kp,   g_kp);
    cudaGetSymbolAddress((void**)&vp,   g_vp);
    cudaGetSymbolAddress((void**)&feat, g_feat);

    const int M  = BB * NN_;           // 8192
    const long long sBND = (long long)NN_ * DD;        // per-batch stride in proj tensors
    const long long sAttnH = (long long)NN_ * NN_;     // per-head stride in attn
    const long long sAttnB = (long long)HH * NN_ * NN_;

    // 1) projections: [8192,512] @ [512,512]^T
    {
        dim3 grid(DD / 128, M / 128, 1);
        gemm_k<128,128,16,8,8,true><<<grid, 256>>>(M, DD, DD,
            q, DD, 0, 0, w_q, DD, 0, 0, qp, DD, 0, 0, nullptr, 0, 1.0f, 1);
        gemm_k<128,128,16,8,8,true><<<grid, 256>>>(M, DD, DD,
            k, DD, 0, 0, w_k, DD, 0, 0, kp, DD, 0, 0, nullptr, 0, 1.0f, 1);
        gemm_k<128,128,16,8,8,true><<<grid, 256>>>(M, DD, DD,
            v, DD, 0, 0, w_v, DD, 0, 0, vp, DD, 0, 0, nullptr, 0, 1.0f, 1);
    }

    // 2) scores = Kp @ Qp^T * 1/sqrt(dk)   (note the reference's q/k swap)
    {
        dim3 grid(NN_ / 128, NN_ / 128, BB * HH);
        gemm_k<128,128,16,8,8,true><<<grid, 256>>>(NN_, NN_, DK,
            kp, DD, sBND, DK,
            qp, DD, sBND, DK,
            attn, NN_, sAttnB, sAttnH,
            nullptr, 0, 0.125f, HH);
    }

    // 3) softmax in place over rows of attn
    softmax_rows<<<BB * HH * NN_, 256>>>(attn);

    // 4) feat = attn @ Vp   (NN form, N=64 per head)
    {
        dim3 grid(1, NN_ / 128, BB * HH);
        gemm_k<128,64,16,8,4,false><<<grid, 256>>>(NN_, DK, NN_,
            attn, NN_, sAttnB, sAttnH,
            vp, DD, sBND, DK,
            feat, DD, sBND, DK,
            nullptr, 0, 1.0f, HH);
    }

    // 5) y = feat @ w_fc^T + q  -> out region
    {
        dim3 grid(DD / 128, M / 128, 1);
        gemm_k<128,128,16,8,8,true><<<grid, 256>>>(M, DD, DD,
            feat, DD, 0, 0, w_fc, DD, 0, 0, out, DD, 0, 0, q, DD, 1.0f, 1);
    }

    // 6) LayerNorm in place
    layernorm_rows<<<M, 256>>>(out, gam, bet);
}

// round 4
// speedup vs baseline: 1.6792x; 1.6792x over previous
#include <cuda_runtime.h>
#include <cuda_bf16.h>
#include <math.h>
#include <stdint.h>

// Problem dims (fixed by the dataset)
#define BB 2
#define NN_ 4096
#define DD 512
#define HH 8
#define DK 64

// ---------------------------------------------------------------------------
// Scratch (device globals — no allocation allowed)
// ---------------------------------------------------------------------------
__device__ float g_qp[BB * NN_ * DD];
__device__ float g_kp[BB * NN_ * DD];
__device__ float g_vp[BB * NN_ * DD];
__device__ float g_feat[BB * NN_ * DD];

__device__ __nv_bfloat16 g_qp_hi[BB * NN_ * DD];
__device__ __nv_bfloat16 g_qp_lo[BB * NN_ * DD];
__device__ __nv_bfloat16 g_kp_hi[BB * NN_ * DD];
__device__ __nv_bfloat16 g_kp_lo[BB * NN_ * DD];
__device__ __nv_bfloat16 g_vpt_hi[BB * HH * DK * NN_];   // [bh, d, token]
__device__ __nv_bfloat16 g_vpt_lo[BB * HH * DK * NN_];

// ---------------------------------------------------------------------------
// PTX helpers (arch-portable: cp.async / ldmatrix / mma.sync only)
// ---------------------------------------------------------------------------
__device__ __forceinline__ uint32_t smem_u32(const void* p) {
    uint32_t a;
    asm("{ .reg .u64 t; cvta.to.shared.u64 t, %1; cvt.u32.u64 %0, t; }"
        : "=r"(a) : "l"(p));
    return a;
}

#define CP16(dst, src) \
    asm volatile("cp.async.cg.shared.global [%0], [%1], 16;" :: "r"(dst), "l"(src))
#define CP_COMMIT() asm volatile("cp.async.commit_group;" ::: "memory")
#define CP_WAIT0()  asm volatile("cp.async.wait_group 0;" ::: "memory")

__device__ __forceinline__ void ldsm4(uint32_t& r0, uint32_t& r1, uint32_t& r2, uint32_t& r3,
                                      uint32_t addr) {
    asm volatile("ldmatrix.sync.aligned.m8n8.x4.shared.b16 {%0,%1,%2,%3}, [%4];"
                 : "=r"(r0), "=r"(r1), "=r"(r2), "=r"(r3) : "r"(addr));
}

__device__ __forceinline__ void mma16816(float* c,
                                         uint32_t a0, uint32_t a1, uint32_t a2, uint32_t a3,
                                         uint32_t b0, uint32_t b1) {
    asm volatile(
        "mma.sync.aligned.m16n8k16.row.col.f32.bf16.bf16.f32 "
        "{%0,%1,%2,%3}, {%4,%5,%6,%7}, {%8,%9}, {%0,%1,%2,%3};"
        : "+f"(c[0]), "+f"(c[1]), "+f"(c[2]), "+f"(c[3])
        : "r"(a0), "r"(a1), "r"(a2), "r"(a3), "r"(b0), "r"(b1));
}

// ---------------------------------------------------------------------------
// SIMT register-blocked SGEMM (projections / fc)
// ---------------------------------------------------------------------------
template<int BM, int BN, int BK, int TM, int TN, bool BT>
__global__ void __launch_bounds__((BM / TM) * (BN / TN))
gemm_k(int M, int N, int K,
       const float* __restrict__ A, int lda,
       const float* __restrict__ Bm, int ldb,
       float* __restrict__ C, int ldc,
       const float* __restrict__ R, int ldr,
       float alpha)
{
    constexpr int THREADS = (BM / TM) * (BN / TN);
    __shared__ float As[BK][BM + 4];
    __shared__ float Bs[BK][BN + 4];

    const int tid = threadIdx.x;
    const int tx = tid % (BN / TN);
    const int ty = tid / (BN / TN);
    const int m0 = blockIdx.y * BM;
    const int n0 = blockIdx.x * BN;

    float acc[TM][TN];
#pragma unroll
    for (int i = 0; i < TM; i++)
#pragma unroll
        for (int j = 0; j < TN; j++) acc[i][j] = 0.0f;

    for (int k0 = 0; k0 < K; k0 += BK) {
        for (int i = tid; i < BM * BK / 4; i += THREADS) {
            int r  = i / (BK / 4);
            int kq = i % (BK / 4);
            float4 t4 = *reinterpret_cast<const float4*>(
                A + (long long)(m0 + r) * lda + k0 + kq * 4);
            As[kq * 4 + 0][r] = t4.x; As[kq * 4 + 1][r] = t4.y;
            As[kq * 4 + 2][r] = t4.z; As[kq * 4 + 3][r] = t4.w;
        }
        if (BT) {
            for (int i = tid; i < BN * BK / 4; i += THREADS) {
                int r  = i / (BK / 4);
                int kq = i % (BK / 4);
                float4 t4 = *reinterpret_cast<const float4*>(
                    Bm + (long long)(n0 + r) * ldb + k0 + kq * 4);
                Bs[kq * 4 + 0][r] = t4.x; Bs[kq * 4 + 1][r] = t4.y;
                Bs[kq * 4 + 2][r] = t4.z; Bs[kq * 4 + 3][r] = t4.w;
            }
        } else {
            for (int i = tid; i < BK * BN / 4; i += THREADS) {
                int kk = i / (BN / 4);
                int cq = i % (BN / 4);
                float4 t4 = *reinterpret_cast<const float4*>(
                    Bm + (long long)(k0 + kk) * ldb + n0 + cq * 4);
                *reinterpret_cast<float4*>(&Bs[kk][cq * 4]) = t4;
            }
        }
        __syncthreads();

#pragma unroll
        for (int kk = 0; kk < BK; kk++) {
            float a[TM], bv[TN];
#pragma unroll
            for (int i = 0; i < TM; i++) a[i] = As[kk][ty * TM + i];
#pragma unroll
            for (int j = 0; j < TN; j++) bv[j] = Bs[kk][tx * TN + j];
#pragma unroll
            for (int i = 0; i < TM; i++)
#pragma unroll
                for (int j = 0; j < TN; j++) acc[i][j] += a[i] * bv[j];
        }
        __syncthreads();
    }

#pragma unroll
    for (int i = 0; i < TM; i++) {
        const int row = m0 + ty * TM + i;
        const long long crow = (long long)row * ldc;
#pragma unroll
        for (int j = 0; j < TN; j += 4) {
            const int col = n0 + tx * TN + j;
            float4 o;
            o.x = alpha * acc[i][j + 0];
            o.y = alpha * acc[i][j + 1];
            o.z = alpha * acc[i][j + 2];
            o.w = alpha * acc[i][j + 3];
            if (R != nullptr) {
                float4 r4 = *reinterpret_cast<const float4*>(
                    R + (long long)row * ldr + col);
                o.x += r4.x; o.y += r4.y; o.z += r4.z; o.w += r4.w;
            }
            *reinterpret_cast<float4*>(C + crow + col) = o;
        }
    }
}

// ---------------------------------------------------------------------------
// fp32 -> bf16 hi/lo split
// ---------------------------------------------------------------------------
__device__ __forceinline__ void split1(float x, __nv_bfloat16& h, __nv_bfloat16& l) {
    h = __float2bfloat16(x);
    l = __float2bfloat16(x - __bfloat162float(h));
}

__global__ void split_k(const float* __restrict__ x,
                        __nv_bfloat16* __restrict__ hi,
                        __nv_bfloat16* __restrict__ lo, int n4)
{
    int i = blockIdx.x * blockDim.x + threadIdx.x;
    if (i >= n4) return;
    float4 v = reinterpret_cast<const float4*>(x)[i];
    __nv_bfloat16 h[4], l[4];
    split1(v.x, h[0], l[0]); split1(v.y, h[1], l[1]);
    split1(v.z, h[2], l[2]); split1(v.w, h[3], l[3]);
    uint2 ph, pl;
    ph.x = ((uint32_t)*(uint16_t*)&h[1] << 16) | *(uint16_t*)&h[0];
    ph.y = ((uint32_t)*(uint16_t*)&h[3] << 16) | *(uint16_t*)&h[2];
    pl.x = ((uint32_t)*(uint16_t*)&l[1] << 16) | *(uint16_t*)&l[0];
    pl.y = ((uint32_t)*(uint16_t*)&l[3] << 16) | *(uint16_t*)&l[2];
    reinterpret_cast<uint2*>(hi)[i] = ph;
    reinterpret_cast<uint2*>(lo)[i] = pl;
}

// vp [B, N, D] fp32 -> vpT hi/lo [B*H, DK, N] bf16
__global__ void vtrans_split(const float* __restrict__ vp,
                             __nv_bfloat16* __restrict__ hi,
                             __nv_bfloat16* __restrict__ lo)
{
    __shared__ float tile[32][33];
    const int j0 = blockIdx.x * 32;
    const int c0 = blockIdx.y * 32;
    const int b  = blockIdx.z;
    const int tx = threadIdx.x, ty = threadIdx.y;
    for (int rr = ty; rr < 32; rr += 8)
        tile[rr][tx] = vp[((long long)(b * NN_ + j0 + rr)) * DD + c0 + tx];
    __syncthreads();
    for (int rr = ty; rr < 32; rr += 8) {
        int c = c0 + rr;
        int h = c >> 6, dl = c & 63;
        long long idx = ((long long)(b * HH + h) * DK + dl) * NN_ + j0 + tx;
        float x = tile[tx][rr];
        __nv_bfloat16 hh, ll;
        split1(x, hh, ll);
        hi[idx] = hh;
        lo[idx] = ll;
    }
}

// ---------------------------------------------------------------------------
// scores = 0.125 * Kp @ Qp^T per (b,h) via mma.sync bf16 hi/lo split.
// BM=BN=128, K=64 resident. 8 warps (2M x 4N), warp tile 64x32.
// smem rows padded to 144B (multiple of 16B, conflict-reduced).
// ---------------------------------------------------------------------------
#define SC_SMEM 73728
#define SC_AHI 0u
#define SC_ALO 18432u
#define SC_BHI 36864u
#define SC_BLO 55296u

__global__ void __launch_bounds__(256)
scores_mma(const __nv_bfloat16* __restrict__ Ahi, const __nv_bfloat16* __restrict__ Alo,
           const __nv_bfloat16* __restrict__ Bhi, const __nv_bfloat16* __restrict__ Blo,
           float* __restrict__ C)
{
    extern __shared__ char smem[];
    const int tid = threadIdx.x;
    const int wid = tid >> 5;
    const int lane = tid & 31;
    const uint32_t sb = smem_u32(smem);

    const int n0 = blockIdx.x * 128;
    const int m0 = blockIdx.y * 128;
    const int bh = blockIdx.z;
    const int b = bh >> 3, h = bh & 7;

    const long long arow = (long long)(b * NN_ + m0);
    const long long brow = (long long)(b * NN_ + n0);
    const int coff = h * DK;

    // load all 4 operand tiles: 128 rows x 8 x 16B each (FULL 128B rows)
    for (int i = tid; i < 1024; i += 256) {
        int r = i >> 3, c = i & 7;
        uint32_t d = (uint32_t)(r * 144 + c * 16);
        CP16(sb + SC_AHI + d, (const char*)(Ahi + (arow + r) * DD + coff + c * 8));
        CP16(sb + SC_ALO + d, (const char*)(Alo + (arow + r) * DD + coff + c * 8));
        CP16(sb + SC_BHI + d, (const char*)(Bhi + (brow + r) * DD + coff + c * 8));
        CP16(sb + SC_BLO + d, (const char*)(Blo + (brow + r) * DD + coff + c * 8));
    }
    CP_COMMIT(); CP_WAIT0();
    __syncthreads();

    const int wm = (wid >> 2) * 64;
    const int wn = (wid & 3) * 32;
    float acc[4][4][4];
#pragma unroll
    for (int i = 0; i < 4; i++)
#pragma unroll
        for (int j = 0; j < 4; j++)
#pragma unroll
            for (int c = 0; c < 4; c++) acc[i][j][c] = 0.0f;

#pragma unroll
    for (int prod = 0; prod < 3; prod++) {
        const uint32_t Ab = sb + ((prod == 1) ? SC_ALO : SC_AHI);
        const uint32_t Bb = sb + ((prod == 2) ? SC_BLO : SC_BHI);
#pragma unroll
        for (int kc = 0; kc < 4; kc++) {
            const uint32_t colA = (uint32_t)(kc * 32 + ((lane >> 4) & 1) * 16);
            const uint32_t colB = (uint32_t)(kc * 32 + ((lane >> 3) & 1) * 16);
            uint32_t bf[8];
#pragma unroll
            for (int j = 0; j < 2; j++) {
                int n = wn + j * 16 + ((lane >> 4) & 1) * 8 + (lane & 7);
                ldsm4(bf[j * 4 + 0], bf[j * 4 + 1], bf[j * 4 + 2], bf[j * 4 + 3],
                      Bb + (uint32_t)(n * 144) + colB);
            }
#pragma unroll
            for (int mi = 0; mi < 4; mi++) {
                uint32_t a0, a1, a2, a3;
                int m = wm + mi * 16 + (lane & 15);
                ldsm4(a0, a1, a2, a3, Ab + (uint32_t)(m * 144) + colA);
#pragma unroll
                for (int j = 0; j < 2; j++) {
                    mma16816(acc[mi][2 * j],     a0, a1, a2, a3, bf[j * 4 + 0], bf[j * 4 + 1]);
                    mma16816(acc[mi][2 * j + 1], a0, a1, a2, a3, bf[j * 4 + 2], bf[j * 4 + 3]);
                }
            }
        }
    }

    // epilogue: stage to smem (stride 132 floats), then coalesced fp32 stores
    __syncthreads();
    float* stg = (float*)smem;
#pragma unroll
    for (int mi = 0; mi < 4; mi++) {
#pragma unroll
        for (int ni = 0; ni < 4; ni++) {
            int r = wm + mi * 16 + (lane >> 2);
            int cc = wn + ni * 8 + (lane & 3) * 2;
            stg[r * 132 + cc]           = 0.125f * acc[mi][ni][0];
            stg[r * 132 + cc + 1]       = 0.125f * acc[mi][ni][1];
            stg[(r + 8) * 132 + cc]     = 0.125f * acc[mi][ni][2];
            stg[(r + 8) * 132 + cc + 1] = 0.125f * acc[mi][ni][3];
        }
    }
    __syncthreads();
    const long long cbase = (long long)bh * NN_ * NN_;
    for (int idx = tid; idx < 4096; idx += 256) {
        int r = idx >> 5, c4 = idx & 31;
        float4 v = *reinterpret_cast<float4*>(stg + r * 132 + c4 * 4);
        *reinterpret_cast<float4*>(C + cbase + (long long)(m0 + r) * NN_ + n0 + c4 * 4) = v;
    }
}

// ---------------------------------------------------------------------------
// feat = attn @ Vp per (b,h). Reads fp32 attn directly, splits in-register.
// BM=128, BN=64, K=4096 (k-chunks of 32), double-buffered. 8 warps 4M x 2N.
// smem rows padded to 80B.
// ---------------------------------------------------------------------------
#define AV_SMEM 61440
#define AV_STAGE 30720u
#define AV_AHI 0u
#define AV_ALO 10240u
#define AV_BHI 20480u
#define AV_BLO 25600u

__global__ void __launch_bounds__(256)
av_mma(const float* __restrict__ attn,
       const __nv_bfloat16* __restrict__ Vhi, const __nv_bfloat16* __restrict__ Vlo,
       float* __restrict__ C)
{
    extern __shared__ char smem[];
    const int tid = threadIdx.x;
    const int wid = tid >> 5;
    const int lane = tid & 31;
    const uint32_t sb = smem_u32(smem);

    const int m0 = blockIdx.y * 128;
    const int bh = blockIdx.z;
    const int b = bh >> 3, h = bh & 7;

    const float* Abase = attn + (long long)bh * NN_ * NN_ + (long long)m0 * NN_;
    const long long vrow = (long long)bh * DK;

    const int wm = (wid >> 1) * 32;
    const int wn = (wid & 1) * 32;

    float acc[2][4][4];
#pragma unroll
    for (int i = 0; i < 2; i++)
#pragma unroll
        for (int j = 0; j < 4; j++)
#pragma unroll
            for (int c = 0; c < 4; c++) acc[i][j][c] = 0.0f;

    // per-thread A fp32 elements: flat f = tid + q*256; r=f>>3, c4=f&7
    const int ar_r[4]  = { tid >> 3, (tid + 256) >> 3, (tid + 512) >> 3, (tid + 768) >> 3 };
    const int ar_c4[4] = { tid & 7,  tid & 7,          tid & 7,          tid & 7 };

    float4 ar[4];
#pragma unroll
    for (int q = 0; q < 4; q++)
        ar[q] = *reinterpret_cast<const float4*>(Abase + (long long)ar_r[q] * NN_ + ar_c4[q] * 4);

    for (int chunk = 0; chunk < 128; chunk++) {
        const uint32_t st = sb + (uint32_t)(chunk & 1) * AV_STAGE;
        const int k0 = chunk * 32;

        // cp.async V tiles (hi+lo): 64 rows x 4 x 16B x 2 = 512 ops
        for (int i = tid; i < 512; i += 256) {
            int op = i >> 8, rr = (i & 255) >> 2, cc = i & 3;
            const __nv_bfloat16* src = (op ? Vlo : Vhi) + (vrow + rr) * NN_ + k0 + cc * 8;
            CP16(st + (op ? AV_BLO : AV_BHI) + (uint32_t)(rr * 80 + cc * 16), (const char*)src);
        }
        CP_COMMIT();

        // convert A fp32 regs -> hi/lo bf16, STS
#pragma unroll
        for (int q = 0; q < 4; q++) {
            __nv_bfloat16 hh[4], ll[4];
            split1(ar[q].x, hh[0], ll[0]); split1(ar[q].y, hh[1], ll[1]);
            split1(ar[q].z, hh[2], ll[2]); split1(ar[q].w, hh[3], ll[3]);
            uint2 ph, pl;
            ph.x = ((uint32_t)*(uint16_t*)&hh[1] << 16) | *(uint16_t*)&hh[0];
            ph.y = ((uint32_t)*(uint16_t*)&hh[3] << 16) | *(uint16_t*)&hh[2];
            pl.x = ((uint32_t)*(uint16_t*)&ll[1] << 16) | *(uint16_t*)&ll[0];
            pl.y = ((uint32_t)*(uint16_t*)&ll[3] << 16) | *(uint16_t*)&ll[2];
            uint32_t d = (uint32_t)(ar_r[q] * 80 + ar_c4[q] * 8);
            *reinterpret_cast<uint2*>(smem + (st - sb) + AV_AHI + d) = ph;
            *reinterpret_cast<uint2*>(smem + (st - sb) + AV_ALO + d) = pl;
        }

        // prefetch next chunk's A while MMA runs
        if (chunk < 127) {
#pragma unroll
            for (int q = 0; q < 4; q++)
                ar[q] = *reinterpret_cast<const float4*>(
                    Abase + (long long)ar_r[q] * NN_ + k0 + 32 + ar_c4[q] * 4);
        }

        CP_WAIT0();
        __syncthreads();

#pragma unroll
        for (int prod = 0; prod < 3; prod++) {
            const uint32_t Ab = st + ((prod == 1) ? AV_ALO : AV_AHI);
            const uint32_t Bb = st + ((prod == 2) ? AV_BLO : AV_BHI);
#pragma unroll
            for (int kc = 0; kc < 2; kc++) {
                const uint32_t colA = (uint32_t)(kc * 32 + ((lane >> 4) & 1) * 16);
                const uint32_t colB = (uint32_t)(kc * 32 + ((lane >> 3) & 1) * 16);
                uint32_t bf[8];
#pragma unroll
                for (int j = 0; j < 2; j++) {
                    int n = wn + j * 16 + ((lane >> 4) & 1) * 8 + (lane & 7);
                    ldsm4(bf[j * 4 + 0], bf[j * 4 + 1], bf[j * 4 + 2], bf[j * 4 + 3],
                          Bb + (uint32_t)(n * 80) + colB);
                }
#pragma unroll
                for (int mi = 0; mi < 2; mi++) {
                    uint32_t a0, a1, a2, a3;
                    int m = wm + mi * 16 + (lane & 15);
                    ldsm4(a0, a1, a2, a3, Ab + (uint32_t)(m * 80) + colA);
#pragma unroll
                    for (int j = 0; j < 2; j++) {
                        mma16816(acc[mi][2 * j],     a0, a1, a2, a3, bf[j * 4 + 0], bf[j * 4 + 1]);
                        mma16816(acc[mi][2 * j + 1], a0, a1, a2, a3, bf[j * 4 + 2], bf[j * 4 + 3]);
                    }
                }
            }
        }
        __syncthreads();
    }

    // epilogue: stage (stride 68), then coalesced stores
    float* stg = (float*)smem;
#pragma unroll
    for (int mi = 0; mi < 2; mi++) {
#pragma unroll
        for (int ni = 0; ni < 4; ni++) {
            int r = wm + mi * 16 + (lane >> 2);
            int cc = wn + ni * 8 + (lane & 3) * 2;
            stg[r * 68 + cc]           = acc[mi][ni][0];
            stg[r * 68 + cc + 1]       = acc[mi][ni][1];
            stg[(r + 8) * 68 + cc]     = acc[mi][ni][2];
            stg[(r + 8) * 68 + cc + 1] = acc[mi][ni][3];
        }
    }
    __syncthreads();
    for (int idx = tid; idx < 2048; idx += 256) {
        int r = idx >> 4, c4 = idx & 15;
        float4 v = *reinterpret_cast<float4*>(stg + r * 68 + c4 * 4);
        *reinterpret_cast<float4*>(C + (long long)(b * NN_ + m0 + r) * DD + h * DK + c4 * 4) = v;
    }
}

// ---------------------------------------------------------------------------
// In-place row softmax (fp32)
// ---------------------------------------------------------------------------
__global__ void softmax_rows(float* __restrict__ attn)
{
    const long long row = blockIdx.x;
    float4* p = reinterpret_cast<float4*>(attn + row * (long long)NN_);
    const int t = threadIdx.x;
    const int lane = t & 31, warp = t >> 5;
    __shared__ float red[32];

    float4 vv[4];
    float m = -INFINITY;
#pragma unroll
    for (int i = 0; i < 4; i++) {
        vv[i] = p[t + i * 256];
        m = fmaxf(m, fmaxf(fmaxf(vv[i].x, vv[i].y), fmaxf(vv[i].z, vv[i].w)));
    }
#pragma unroll
    for (int o = 16; o > 0; o >>= 1) m = fmaxf(m, __shfl_xor_sync(~0u, m, o));
    if (lane == 0) red[warp] = m;
    __syncthreads();
    if (warp == 0) {
        float x = (lane < 8) ? red[lane] : -INFINITY;
#pragma unroll
        for (int o = 16; o > 0; o >>= 1) x = fmaxf(x, __shfl_xor_sync(~0u, x, o));
        if (lane == 0) red[0] = x;
    }
    __syncthreads();
    m = red[0];
    __syncthreads();

    float s = 0.0f;
#pragma unroll
    for (int i = 0; i < 4; i++) {
        vv[i].x = __expf(vv[i].x - m);
        vv[i].y = __expf(vv[i].y - m);
        vv[i].z = __expf(vv[i].z - m);
        vv[i].w = __expf(vv[i].w - m);
        s += vv[i].x + vv[i].y + vv[i].z + vv[i].w;
    }
#pragma unroll
    for (int o = 16; o > 0; o >>= 1) s += __shfl_xor_sync(~0u, s, o);
    if (lane == 0) red[warp] = s;
    __syncthreads();
    if (warp == 0) {
        float x = (lane < 8) ? red[lane] : 0.0f;
#pragma unroll
        for (int o = 16; o > 0; o >>= 1) x += __shfl_xor_sync(~0u, x, o);
        if (lane == 0) red[0] = x;
    }
    __syncthreads();
    const float inv = 1.0f / red[0];

#pragma unroll
    for (int i = 0; i < 4; i++) {
        vv[i].x *= inv; vv[i].y *= inv; vv[i].z *= inv; vv[i].w *= inv;
        p[t + i * 256] = vv[i];
    }
}

// ---------------------------------------------------------------------------
// In-place row LayerNorm
// ---------------------------------------------------------------------------
__global__ void layernorm_rows(float* __restrict__ y,
                               const float* __restrict__ gamma,
                               const float* __restrict__ beta)
{
    const long long base = (long long)blockIdx.x * DD;
    const int t = threadIdx.x;
    const int lane = t & 31, warp = t >> 5;
    __shared__ float red[32];

    float x0 = y[base + t];
    float x1 = y[base + t + 256];

    float s = x0 + x1;
#pragma unroll
    for (int o = 16; o > 0; o >>= 1) s += __shfl_xor_sync(~0u, s, o);
    if (lane == 0) red[warp] = s;
    __syncthreads();
    if (warp == 0) {
        float x = (lane < 8) ? red[lane] : 0.0f;
#pragma unroll
        for (int o = 16; o > 0; o >>= 1) x += __shfl_xor_sync(~0u, x, o);
        if (lane == 0) red[0] = x;
    }
    __syncthreads();
    const float mu = red[0] * (1.0f / DD);
    __syncthreads();

    const float d0 = x0 - mu, d1 = x1 - mu;
    float v = d0 * d0 + d1 * d1;
#pragma unroll
    for (int o = 16; o > 0; o >>= 1) v += __shfl_xor_sync(~0u, v, o);
    if (lane == 0) red[warp] = v;
    __syncthreads();
    if (warp == 0) {
        float x = (lane < 8) ? red[lane] : 0.0f;
#pragma unroll
        for (int o = 16; o > 0; o >>= 1) x += __shfl_xor_sync(~0u, x, o);
        if (lane == 0) red[0] = x;
    }
    __syncthreads();
    const float r = rsqrtf(red[0] * (1.0f / DD) + 1e-5f);

    y[base + t]       = d0 * r * gamma[t]       + beta[t];
    y[base + t + 256] = d1 * r * gamma[t + 256] + beta[t + 256];
}

// ---------------------------------------------------------------------------
extern "C" void kernel_launch(void* const* d_in, const int* in_sizes, int n_in,
                              void* d_out, int out_size)
{
    const float* q    = (const float*)d_in[0];
    const float* k    = (const float*)d_in[1];
    const float* v    = (const float*)d_in[2];
    const float* w_q  = (const float*)d_in[3];
    const float* w_k  = (const float*)d_in[4];
    const float* w_v  = (const float*)d_in[5];
    const float* w_fc = (const float*)d_in[6];
    const float* gam  = (const float*)d_in[7];
    const float* bet  = (const float*)d_in[8];

    float* out  = (float*)d_out;                          // [B,N,D]
    float* attn = out + (long long)BB * NN_ * DD;         // [B,H,N,N]

    float *qp, *kp, *vp, *feat;
    cudaGetSymbolAddress((void**)&qp,   g_qp);
    cudaGetSymbolAddress((void**)&kp,   g_kp);
    cudaGetSymbolAddress((void**)&vp,   g_vp);
    cudaGetSymbolAddress((void**)&feat, g_feat);
    __nv_bfloat16 *qph, *qpl, *kph, *kpl, *vth, *vtl;
    cudaGetSymbolAddress((void**)&qph, g_qp_hi);
    cudaGetSymbolAddress((void**)&qpl, g_qp_lo);
    cudaGetSymbolAddress((void**)&kph, g_kp_hi);
    cudaGetSymbolAddress((void**)&kpl, g_kp_lo);
    cudaGetSymbolAddress((void**)&vth, g_vpt_hi);
    cudaGetSymbolAddress((void**)&vtl, g_vpt_lo);

    cudaFuncSetAttribute(scores_mma, cudaFuncAttributeMaxDynamicSharedMemorySize, SC_SMEM);
    cudaFuncSetAttribute(av_mma,     cudaFuncAttributeMaxDynamicSharedMemorySize, AV_SMEM);

    const int M = BB * NN_;   // 8192

    // 1) projections (SIMT fp32)
    {
        dim3 grid(DD / 128, M / 128, 1);
        gemm_k<128,128,16,8,8,true><<<grid, 256>>>(M, DD, DD, q, DD, w_q, DD, qp, DD, nullptr, 0, 1.0f);
        gemm_k<128,128,16,8,8,true><<<grid, 256>>>(M, DD, DD, k, DD, w_k, DD, kp, DD, nullptr, 0, 1.0f);
        gemm_k<128,128,16,8,8,true><<<grid, 256>>>(M, DD, DD, v, DD, w_v, DD, vp, DD, nullptr, 0, 1.0f);
    }

    // 2) hi/lo splits
    {
        const int n4 = M * DD / 4;
        split_k<<<(n4 + 255) / 256, 256>>>(qp, qph, qpl, n4);
        split_k<<<(n4 + 255) / 256, 256>>>(kp, kph, kpl, n4);
        vtrans_split<<<dim3(NN_ / 32, DD / 32, BB), dim3(32, 8)>>>(vp, vth, vtl);
    }

    // 3) scores = 0.125 * Kp @ Qp^T (tensor cores via mma.sync)
    scores_mma<<<dim3(NN_ / 128, NN_ / 128, BB * HH), 256, SC_SMEM>>>(kph, kpl, qph, qpl, attn);

    // 4) softmax in place
    softmax_rows<<<BB * HH * NN_, 256>>>(attn);

    // 5) feat = attn @ Vp (tensor cores via mma.sync)
    av_mma<<<dim3(1, NN_ / 128, BB * HH), 256, AV_SMEM>>>(attn, vth, vtl, feat);

    // 6) y = feat @ w_fc^T + q
    {
        dim3 grid(DD / 128, M / 128, 1);
        gemm_k<128,128,16,8,8,true><<<grid, 256>>>(M, DD, DD, feat, DD, w_fc, DD, out, DD, q, DD, 1.0f);
    }

    // 7) LayerNorm
    layernorm_rows<<<M, 256>>>(out, gam, bet);
}

// round 5
// speedup vs baseline: 2.4528x; 1.4608x over previous
#include <cuda_runtime.h>
#include <cuda_bf16.h>
#include <math.h>
#include <stdint.h>

#define BB 2
#define NN_ 4096
#define DD 512
#define HH 8
#define DK 64

typedef __nv_bfloat16 bf16;

// ---------------------------------------------------------------------------
// Scratch (device globals — no allocation allowed)
// ---------------------------------------------------------------------------
__device__ float g_vp[BB * NN_ * DD];
__device__ float g_feat[BB * NN_ * DD];
__device__ float g_rowsum[BB * HH * NN_];

__device__ bf16 g_xq_hi[BB * NN_ * DD]; __device__ bf16 g_xq_lo[BB * NN_ * DD];
__device__ bf16 g_xk_hi[BB * NN_ * DD]; __device__ bf16 g_xk_lo[BB * NN_ * DD];
__device__ bf16 g_xv_hi[BB * NN_ * DD]; __device__ bf16 g_xv_lo[BB * NN_ * DD];
__device__ bf16 g_wq_hi[DD * DD]; __device__ bf16 g_wq_lo[DD * DD];
__device__ bf16 g_wk_hi[DD * DD]; __device__ bf16 g_wk_lo[DD * DD];
__device__ bf16 g_wv_hi[DD * DD]; __device__ bf16 g_wv_lo[DD * DD];
__device__ bf16 g_wf_hi[DD * DD]; __device__ bf16 g_wf_lo[DD * DD];
__device__ bf16 g_qp_hi[BB * NN_ * DD]; __device__ bf16 g_qp_lo[BB * NN_ * DD];
__device__ bf16 g_kp_hi[BB * NN_ * DD]; __device__ bf16 g_kp_lo[BB * NN_ * DD];
__device__ bf16 g_vpt_hi[BB * HH * DK * NN_]; __device__ bf16 g_vpt_lo[BB * HH * DK * NN_];
__device__ bf16 g_ft_hi[BB * NN_ * DD]; __device__ bf16 g_ft_lo[BB * NN_ * DD];

// ---------------------------------------------------------------------------
// PTX helpers (arch-portable: cp.async / ldmatrix / mma.sync only)
// ---------------------------------------------------------------------------
__device__ __forceinline__ uint32_t smem_u32(const void* p) {
    uint32_t a;
    asm("{ .reg .u64 t; cvta.to.shared.u64 t, %1; cvt.u32.u64 %0, t; }"
        : "=r"(a) : "l"(p));
    return a;
}

#define CP16(dst, src) \
    asm volatile("cp.async.cg.shared.global [%0], [%1], 16;" :: "r"(dst), "l"(src))
#define CP_COMMIT() asm volatile("cp.async.commit_group;" ::: "memory")
#define CP_WAIT0()  asm volatile("cp.async.wait_group 0;" ::: "memory")
#define CP_WAIT1()  asm volatile("cp.async.wait_group 1;" ::: "memory")

__device__ __forceinline__ void ldsm4(uint32_t& r0, uint32_t& r1, uint32_t& r2, uint32_t& r3,
                                      uint32_t addr) {
    asm volatile("ldmatrix.sync.aligned.m8n8.x4.shared.b16 {%0,%1,%2,%3}, [%4];"
                 : "=r"(r0), "=r"(r1), "=r"(r2), "=r"(r3) : "r"(addr));
}

__device__ __forceinline__ void mma16816(float* c,
                                         uint32_t a0, uint32_t a1, uint32_t a2, uint32_t a3,
                                         uint32_t b0, uint32_t b1) {
    asm volatile(
        "mma.sync.aligned.m16n8k16.row.col.f32.bf16.bf16.f32 "
        "{%0,%1,%2,%3}, {%4,%5,%6,%7}, {%8,%9}, {%0,%1,%2,%3};"
        : "+f"(c[0]), "+f"(c[1]), "+f"(c[2]), "+f"(c[3])
        : "r"(a0), "r"(a1), "r"(a2), "r"(a3), "r"(b0), "r"(b1));
}

__device__ __forceinline__ void split1(float x, bf16& h, bf16& l) {
    h = __float2bfloat16(x);
    l = __float2bfloat16(x - __bfloat162float(h));
}

// ---------------------------------------------------------------------------
// fp32 -> bf16 hi/lo split (elementwise)
// ---------------------------------------------------------------------------
__global__ void split_k(const float* __restrict__ x,
                        bf16* __restrict__ hi, bf16* __restrict__ lo, int n4)
{
    int i = blockIdx.x * blockDim.x + threadIdx.x;
    if (i >= n4) return;
    float4 v = reinterpret_cast<const float4*>(x)[i];
    bf16 h[4], l[4];
    split1(v.x, h[0], l[0]); split1(v.y, h[1], l[1]);
    split1(v.z, h[2], l[2]); split1(v.w, h[3], l[3]);
    uint2 ph, pl;
    ph.x = ((uint32_t)*(uint16_t*)&h[1] << 16) | *(uint16_t*)&h[0];
    ph.y = ((uint32_t)*(uint16_t*)&h[3] << 16) | *(uint16_t*)&h[2];
    pl.x = ((uint32_t)*(uint16_t*)&l[1] << 16) | *(uint16_t*)&l[0];
    pl.y = ((uint32_t)*(uint16_t*)&l[3] << 16) | *(uint16_t*)&l[2];
    reinterpret_cast<uint2*>(hi)[i] = ph;
    reinterpret_cast<uint2*>(lo)[i] = pl;
}

// vp [B, N, D] fp32 -> vpT hi/lo [B*H, DK, N] bf16
__global__ void vtrans_split(const float* __restrict__ vp,
                             bf16* __restrict__ hi, bf16* __restrict__ lo)
{
    __shared__ float tile[32][33];
    const int j0 = blockIdx.x * 32;
    const int c0 = blockIdx.y * 32;
    const int b  = blockIdx.z;
    const int tx = threadIdx.x, ty = threadIdx.y;
    for (int rr = ty; rr < 32; rr += 8)
        tile[rr][tx] = vp[((long long)(b * NN_ + j0 + rr)) * DD + c0 + tx];
    __syncthreads();
    for (int rr = ty; rr < 32; rr += 8) {
        int c = c0 + rr;
        int h = c >> 6, dl = c & 63;
        long long idx = ((long long)(b * HH + h) * DK + dl) * NN_ + j0 + tx;
        bf16 hh, ll;
        split1(tile[tx][rr], hh, ll);
        hi[idx] = hh;
        lo[idx] = ll;
    }
}

// ---------------------------------------------------------------------------
// Tensor-core GEMM (NT): C[M,512] = A[M,512] @ W[512,512]^T  via hi/lo split.
// BM=BN=128, BK=32, 2-stage cp.async pipeline. 8 warps (2M x 4N).
// OUTM: 0 = fp32 out; 1 = fp32 out + residual; 2 = bf16 hi/lo out.
// smem rows padded to 80B.
// ---------------------------------------------------------------------------
#define GM_SMEM 81920
#define GM_STG  40960u

template<int OUTM>
__global__ void __launch_bounds__(256)
mma_gemm(const bf16* __restrict__ Ahi, const bf16* __restrict__ Alo,
         const bf16* __restrict__ Bhi, const bf16* __restrict__ Blo,
         float* __restrict__ Cf, bf16* __restrict__ Chi, bf16* __restrict__ Clo,
         const float* __restrict__ R)
{
    extern __shared__ char smem[];
    const int tid = threadIdx.x;
    const int wid = tid >> 5;
    const int lane = tid & 31;
    const uint32_t sb = smem_u32(smem);
    const int n0 = blockIdx.x * 128;
    const int m0 = blockIdx.y * 128;

    const int wm = (wid >> 2) * 64;
    const int wn = (wid & 3) * 32;

    float acc[4][4][4];
#pragma unroll
    for (int i = 0; i < 4; i++)
#pragma unroll
        for (int j = 0; j < 4; j++)
#pragma unroll
            for (int c = 0; c < 4; c++) acc[i][j][c] = 0.0f;

    auto load_stage = [&](int kt, int s) {
        const int k0 = kt * 32;
        const uint32_t st = sb + (uint32_t)s * GM_STG;
        for (int i = tid; i < 2048; i += 256) {
            int t = i >> 9, r = (i & 511) >> 2, c = i & 3;
            const bf16* src;
            if (t == 0)      src = Ahi + (long long)(m0 + r) * DD + k0 + c * 8;
            else if (t == 1) src = Alo + (long long)(m0 + r) * DD + k0 + c * 8;
            else if (t == 2) src = Bhi + (long long)(n0 + r) * DD + k0 + c * 8;
            else             src = Blo + (long long)(n0 + r) * DD + k0 + c * 8;
            CP16(st + (uint32_t)t * 10240u + (uint32_t)(r * 80 + c * 16), (const char*)src);
        }
    };

    load_stage(0, 0); CP_COMMIT();

    for (int kt = 0; kt < 16; kt++) {
        if (kt < 15) { load_stage(kt + 1, (kt + 1) & 1); CP_COMMIT(); }
        if (kt < 15) CP_WAIT1(); else CP_WAIT0();
        __syncthreads();
        const uint32_t st = sb + (uint32_t)(kt & 1) * GM_STG;
#pragma unroll
        for (int prod = 0; prod < 3; prod++) {
            const uint32_t Ab = st + ((prod == 1) ? 10240u : 0u);
            const uint32_t Bb = st + 20480u + ((prod == 2) ? 10240u : 0u);
#pragma unroll
            for (int kc = 0; kc < 2; kc++) {
                const uint32_t colA = (uint32_t)(kc * 32 + ((lane >> 4) & 1) * 16);
                const uint32_t colB = (uint32_t)(kc * 32 + ((lane >> 3) & 1) * 16);
                uint32_t bf[8];
#pragma unroll
                for (int j = 0; j < 2; j++) {
                    int n = wn + j * 16 + ((lane >> 4) & 1) * 8 + (lane & 7);
                    ldsm4(bf[j * 4 + 0], bf[j * 4 + 1], bf[j * 4 + 2], bf[j * 4 + 3],
                          Bb + (uint32_t)(n * 80) + colB);
                }
#pragma unroll
                for (int mi = 0; mi < 4; mi++) {
                    uint32_t a0, a1, a2, a3;
                    int m = wm + mi * 16 + (lane & 15);
                    ldsm4(a0, a1, a2, a3, Ab + (uint32_t)(m * 80) + colA);
#pragma unroll
                    for (int j = 0; j < 2; j++) {
                        mma16816(acc[mi][2 * j],     a0, a1, a2, a3, bf[j * 4 + 0], bf[j * 4 + 1]);
                        mma16816(acc[mi][2 * j + 1], a0, a1, a2, a3, bf[j * 4 + 2], bf[j * 4 + 3]);
                    }
                }
            }
        }
        __syncthreads();
    }

    // epilogue: direct stores from fragments
#pragma unroll
    for (int mi = 0; mi < 4; mi++) {
#pragma unroll
        for (int ni = 0; ni < 4; ni++) {
            int r  = wm + mi * 16 + (lane >> 2);
            int cc = wn + ni * 8 + (lane & 3) * 2;
#pragma unroll
            for (int half = 0; half < 2; half++) {
                int row = m0 + r + half * 8;
                int col = n0 + cc;
                float v0 = acc[mi][ni][half * 2 + 0];
                float v1 = acc[mi][ni][half * 2 + 1];
                if (OUTM == 2) {
                    bf16 h0, l0, h1, l1;
                    split1(v0, h0, l0); split1(v1, h1, l1);
                    uint32_t ph = ((uint32_t)*(uint16_t*)&h1 << 16) | *(uint16_t*)&h0;
                    uint32_t pl = ((uint32_t)*(uint16_t*)&l1 << 16) | *(uint16_t*)&l0;
                    *reinterpret_cast<uint32_t*>(Chi + (long long)row * DD + col) = ph;
                    *reinterpret_cast<uint32_t*>(Clo + (long long)row * DD + col) = pl;
                } else {
                    if (OUTM == 1) {
                        float2 r2 = *reinterpret_cast<const float2*>(R + (long long)row * DD + col);
                        v0 += r2.x; v1 += r2.y;
                    }
                    float2 o; o.x = v0; o.y = v1;
                    *reinterpret_cast<float2*>(Cf + (long long)row * DD + col) = o;
                }
            }
        }
    }
}

// ---------------------------------------------------------------------------
// scores_exp: per (b,h), CTA = 128 K-rows x ALL 4096 Q-cols.
// Writes exp(0.125 * Kp@Qp^T) (unnormalized) into attn region in place, and
// deterministic per-row sums into g_rowsum. A (K tile) resident, B streamed.
// ---------------------------------------------------------------------------
#define SCX_SMEM 110592

__global__ void __launch_bounds__(256)
scores_exp(const bf16* __restrict__ Khi, const bf16* __restrict__ Klo,
           const bf16* __restrict__ Qhi, const bf16* __restrict__ Qlo,
           float* __restrict__ S, float* __restrict__ rowsum)
{
    extern __shared__ char smem[];
    const int tid = threadIdx.x;
    const int wid = tid >> 5;
    const int lane = tid & 31;
    const uint32_t sb = smem_u32(smem);

    const int m0 = blockIdx.x * 128;
    const int bh = blockIdx.y;
    const int b = bh >> 3, h = bh & 7;
    const long long arow = (long long)(b * NN_ + m0);
    const int coff = h * DK;

    // resident A (K rows), 144B pitch: tiles at 0 (hi), 18432 (lo)
    for (int i = tid; i < 2048; i += 256) {
        int t = i >> 10, r = (i & 1023) >> 3, c = i & 7;
        const bf16* src = (t ? Klo : Khi) + (arow + r) * DD + coff + c * 8;
        CP16(sb + (uint32_t)t * 18432u + (uint32_t)(r * 144 + c * 16), (const char*)src);
    }

    auto load_B = [&](int nb, int s) {
        const long long brow = (long long)b * NN_ + (long long)nb * 128;
        const uint32_t st = sb + 36864u + (uint32_t)s * 36864u;
        for (int i = tid; i < 2048; i += 256) {
            int t = i >> 10, r = (i & 1023) >> 3, c = i & 7;
            const bf16* src = (t ? Qlo : Qhi) + (brow + r) * DD + coff + c * 8;
            CP16(st + (uint32_t)t * 18432u + (uint32_t)(r * 144 + c * 16), (const char*)src);
        }
    };

    load_B(0, 0); CP_COMMIT();

    const int wm = (wid >> 2) * 64;
    const int wn = (wid & 3) * 32;
    const long long cbase = (long long)bh * NN_ * NN_;
    float rs[8];
#pragma unroll
    for (int i = 0; i < 8; i++) rs[i] = 0.0f;

    for (int nb = 0; nb < 32; nb++) {
        if (nb < 31) { load_B(nb + 1, (nb + 1) & 1); CP_COMMIT(); }
        if (nb < 31) CP_WAIT1(); else CP_WAIT0();
        __syncthreads();

        float acc[4][4][4];
#pragma unroll
        for (int i = 0; i < 4; i++)
#pragma unroll
            for (int j = 0; j < 4; j++)
#pragma unroll
                for (int c = 0; c < 4; c++) acc[i][j][c] = 0.0f;

        const uint32_t Bst = sb + 36864u + (uint32_t)(nb & 1) * 36864u;
#pragma unroll
        for (int prod = 0; prod < 3; prod++) {
            const uint32_t Ab = sb + ((prod == 1) ? 18432u : 0u);
            const uint32_t Bb = Bst + ((prod == 2) ? 18432u : 0u);
#pragma unroll
            for (int kc = 0; kc < 4; kc++) {
                const uint32_t colA = (uint32_t)(kc * 32 + ((lane >> 4) & 1) * 16);
                const uint32_t colB = (uint32_t)(kc * 32 + ((lane >> 3) & 1) * 16);
                uint32_t bf[8];
#pragma unroll
                for (int j = 0; j < 2; j++) {
                    int n = wn + j * 16 + ((lane >> 4) & 1) * 8 + (lane & 7);
                    ldsm4(bf[j * 4 + 0], bf[j * 4 + 1], bf[j * 4 + 2], bf[j * 4 + 3],
                          Bb + (uint32_t)(n * 144) + colB);
                }
#pragma unroll
                for (int mi = 0; mi < 4; mi++) {
                    uint32_t a0, a1, a2, a3;
                    int m = wm + mi * 16 + (lane & 15);
                    ldsm4(a0, a1, a2, a3, Ab + (uint32_t)(m * 144) + colA);
#pragma unroll
                    for (int j = 0; j < 2; j++) {
                        mma16816(acc[mi][2 * j],     a0, a1, a2, a3, bf[j * 4 + 0], bf[j * 4 + 1]);
                        mma16816(acc[mi][2 * j + 1], a0, a1, a2, a3, bf[j * 4 + 2], bf[j * 4 + 3]);
                    }
                }
            }
        }

        // epilogue: exp + direct stores + rowsum partials
#pragma unroll
        for (int mi = 0; mi < 4; mi++) {
#pragma unroll
            for (int ni = 0; ni < 4; ni++) {
                int r  = wm + mi * 16 + (lane >> 2);
                int cc = wn + ni * 8 + (lane & 3) * 2;
                long long col = (long long)nb * 128 + cc;
#pragma unroll
                for (int half = 0; half < 2; half++) {
                    float e0 = __expf(0.125f * acc[mi][ni][half * 2 + 0]);
                    float e1 = __expf(0.125f * acc[mi][ni][half * 2 + 1]);
                    float2 o; o.x = e0; o.y = e1;
                    *reinterpret_cast<float2*>(
                        S + cbase + (long long)(m0 + r + half * 8) * NN_ + col) = o;
                    rs[mi * 2 + half] += e0 + e1;
                }
            }
        }
        __syncthreads();
    }

    // deterministic rowsum reduction
#pragma unroll
    for (int i = 0; i < 8; i++) {
        rs[i] += __shfl_xor_sync(~0u, rs[i], 1);
        rs[i] += __shfl_xor_sync(~0u, rs[i], 2);
    }
    float* rsm = (float*)(smem + 36864);
    if ((lane & 3) == 0) {
#pragma unroll
        for (int mi = 0; mi < 4; mi++)
#pragma unroll
            for (int half = 0; half < 2; half++) {
                int lr = wm + mi * 16 + half * 8 + (lane >> 2);
                rsm[(wid & 3) * 128 + lr] = rs[mi * 2 + half];
            }
    }
    __syncthreads();
    if (tid < 128) {
        float t = rsm[tid] + rsm[128 + tid] + rsm[256 + tid] + rsm[384 + tid];
        rowsum[(long long)bh * NN_ + m0 + tid] = t;
    }
}

// ---------------------------------------------------------------------------
// av_mma: feat = softmax(S) @ Vp. Reads unnormalized exp S, scales by
// 1/rowsum, writes normalized attn back IN PLACE, splits to bf16 in-register,
// MMA against V^T. BM=128, BN=64, K=4096.
// ---------------------------------------------------------------------------
#define AV_SMEM 61440
#define AV_STAGE 30720u
#define AV_AHI 0u
#define AV_ALO 10240u
#define AV_BHI 20480u
#define AV_BLO 25600u

__global__ void __launch_bounds__(256)
av_mma(float* __restrict__ S, const float* __restrict__ rowsum,
       const bf16* __restrict__ Vhi, const bf16* __restrict__ Vlo,
       float* __restrict__ C)
{
    extern __shared__ char smem[];
    const int tid = threadIdx.x;
    const int wid = tid >> 5;
    const int lane = tid & 31;
    const uint32_t sb = smem_u32(smem);

    const int m0 = blockIdx.y * 128;
    const int bh = blockIdx.z;
    const int b = bh >> 3, h = bh & 7;

    float* Abase = S + (long long)bh * NN_ * NN_ + (long long)m0 * NN_;
    const long long vrow = (long long)bh * DK;

    const int wm = (wid >> 1) * 32;
    const int wn = (wid & 1) * 32;

    float acc[2][4][4];
#pragma unroll
    for (int i = 0; i < 2; i++)
#pragma unroll
        for (int j = 0; j < 4; j++)
#pragma unroll
            for (int c = 0; c < 4; c++) acc[i][j][c] = 0.0f;

    const int ar_r[4]  = { tid >> 3, (tid + 256) >> 3, (tid + 512) >> 3, (tid + 768) >> 3 };
    const int c4 = tid & 7;

    float inv4[4];
#pragma unroll
    for (int q = 0; q < 4; q++)
        inv4[q] = __frcp_rn(rowsum[(long long)bh * NN_ + m0 + ar_r[q]]);

    float4 ar[4];
#pragma unroll
    for (int q = 0; q < 4; q++)
        ar[q] = *reinterpret_cast<const float4*>(Abase + (long long)ar_r[q] * NN_ + c4 * 4);

    for (int chunk = 0; chunk < 128; chunk++) {
        const uint32_t st = sb + (uint32_t)(chunk & 1) * AV_STAGE;
        const int k0 = chunk * 32;

        for (int i = tid; i < 512; i += 256) {
            int op = i >> 8, rr = (i & 255) >> 2, cc = i & 3;
            const bf16* src = (op ? Vlo : Vhi) + (vrow + rr) * NN_ + k0 + cc * 8;
            CP16(st + (op ? AV_BLO : AV_BHI) + (uint32_t)(rr * 80 + cc * 16), (const char*)src);
        }
        CP_COMMIT();

        // normalize, write attn in place, split to hi/lo, STS
#pragma unroll
        for (int q = 0; q < 4; q++) {
            ar[q].x *= inv4[q]; ar[q].y *= inv4[q];
            ar[q].z *= inv4[q]; ar[q].w *= inv4[q];
            *reinterpret_cast<float4*>(Abase + (long long)ar_r[q] * NN_ + k0 + c4 * 4) = ar[q];
            bf16 hh[4], ll[4];
            split1(ar[q].x, hh[0], ll[0]); split1(ar[q].y, hh[1], ll[1]);
            split1(ar[q].z, hh[2], ll[2]); split1(ar[q].w, hh[3], ll[3]);
            uint2 ph, pl;
            ph.x = ((uint32_t)*(uint16_t*)&hh[1] << 16) | *(uint16_t*)&hh[0];
            ph.y = ((uint32_t)*(uint16_t*)&hh[3] << 16) | *(uint16_t*)&hh[2];
            pl.x = ((uint32_t)*(uint16_t*)&ll[1] << 16) | *(uint16_t*)&ll[0];
            pl.y = ((uint32_t)*(uint16_t*)&ll[3] << 16) | *(uint16_t*)&ll[2];
            uint32_t d = (uint32_t)(ar_r[q] * 80 + c4 * 8);
            *reinterpret_cast<uint2*>(smem + (st - sb) + AV_AHI + d) = ph;
            *reinterpret_cast<uint2*>(smem + (st - sb) + AV_ALO + d) = pl;
        }

        if (chunk < 127) {
#pragma unroll
            for (int q = 0; q < 4; q++)
                ar[q] = *reinterpret_cast<const float4*>(
                    Abase + (long long)ar_r[q] * NN_ + k0 + 32 + c4 * 4);
        }

        CP_WAIT0();
        __syncthreads();

#pragma unroll
        for (int prod = 0; prod < 3; prod++) {
            const uint32_t Ab = st + ((prod == 1) ? AV_ALO : AV_AHI);
            const uint32_t Bb = st + ((prod == 2) ? AV_BLO : AV_BHI);
#pragma unroll
            for (int kc = 0; kc < 2; kc++) {
                const uint32_t colA = (uint32_t)(kc * 32 + ((lane >> 4) & 1) * 16);
                const uint32_t colB = (uint32_t)(kc * 32 + ((lane >> 3) & 1) * 16);
                uint32_t bf[8];
#pragma unroll
                for (int j = 0; j < 2; j++) {
                    int n = wn + j * 16 + ((lane >> 4) & 1) * 8 + (lane & 7);
                    ldsm4(bf[j * 4 + 0], bf[j * 4 + 1], bf[j * 4 + 2], bf[j * 4 + 3],
                          Bb + (uint32_t)(n * 80) + colB);
                }
#pragma unroll
                for (int mi = 0; mi < 2; mi++) {
                    uint32_t a0, a1, a2, a3;
                    int m = wm + mi * 16 + (lane & 15);
                    ldsm4(a0, a1, a2, a3, Ab + (uint32_t)(m * 80) + colA);
#pragma unroll
                    for (int j = 0; j < 2; j++) {
                        mma16816(acc[mi][2 * j],     a0, a1, a2, a3, bf[j * 4 + 0], bf[j * 4 + 1]);
                        mma16816(acc[mi][2 * j + 1], a0, a1, a2, a3, bf[j * 4 + 2], bf[j * 4 + 3]);
                    }
                }
            }
        }
        __syncthreads();
    }

    // epilogue via smem staging (stride 68), coalesced stores to feat
    float* stg = (float*)smem;
#pragma unroll
    for (int mi = 0; mi < 2; mi++) {
#pragma unroll
        for (int ni = 0; ni < 4; ni++) {
            int r = wm + mi * 16 + (lane >> 2);
            int cc = wn + ni * 8 + (lane & 3) * 2;
            stg[r * 68 + cc]           = acc[mi][ni][0];
            stg[r * 68 + cc + 1]       = acc[mi][ni][1];
            stg[(r + 8) * 68 + cc]     = acc[mi][ni][2];
            stg[(r + 8) * 68 + cc + 1] = acc[mi][ni][3];
        }
    }
    __syncthreads();
    for (int idx = tid; idx < 2048; idx += 256) {
        int r = idx >> 4, cq = idx & 15;
        float4 v = *reinterpret_cast<float4*>(stg + r * 68 + cq * 4);
        *reinterpret_cast<float4*>(C + (long long)(b * NN_ + m0 + r) * DD + h * DK + cq * 4) = v;
    }
}

// ---------------------------------------------------------------------------
// In-place row LayerNorm
// ---------------------------------------------------------------------------
__global__ void layernorm_rows(float* __restrict__ y,
                               const float* __restrict__ gamma,
                               const float* __restrict__ beta)
{
    const long long base = (long long)blockIdx.x * DD;
    const int t = threadIdx.x;
    const int lane = t & 31, warp = t >> 5;
    __shared__ float red[32];

    float x0 = y[base + t];
    float x1 = y[base + t + 256];

    float s = x0 + x1;
#pragma unroll
    for (int o = 16; o > 0; o >>= 1) s += __shfl_xor_sync(~0u, s, o);
    if (lane == 0) red[warp] = s;
    __syncthreads();
    if (warp == 0) {
        float x = (lane < 8) ? red[lane] : 0.0f;
#pragma unroll
        for (int o = 16; o > 0; o >>= 1) x += __shfl_xor_sync(~0u, x, o);
        if (lane == 0) red[0] = x;
    }
    __syncthreads();
    const float mu = red[0] * (1.0f / DD);
    __syncthreads();

    const float d0 = x0 - mu, d1 = x1 - mu;
    float v = d0 * d0 + d1 * d1;
#pragma unroll
    for (int o = 16; o > 0; o >>= 1) v += __shfl_xor_sync(~0u, v, o);
    if (lane == 0) red[warp] = v;
    __syncthreads();
    if (warp == 0) {
        float x = (lane < 8) ? red[lane] : 0.0f;
#pragma unroll
        for (int o = 16; o > 0; o >>= 1) x += __shfl_xor_sync(~0u, x, o);
        if (lane == 0) red[0] = x;
    }
    __syncthreads();
    const float r = rsqrtf(red[0] * (1.0f / DD) + 1e-5f);

    y[base + t]       = d0 * r * gamma[t]       + beta[t];
    y[base + t + 256] = d1 * r * gamma[t + 256] + beta[t + 256];
}

// ---------------------------------------------------------------------------
extern "C" void kernel_launch(void* const* d_in, const int* in_sizes, int n_in,
                              void* d_out, int out_size)
{
    const float* q    = (const float*)d_in[0];
    const float* k    = (const float*)d_in[1];
    const float* v    = (const float*)d_in[2];
    const float* w_q  = (const float*)d_in[3];
    const float* w_k  = (const float*)d_in[4];
    const float* w_v  = (const float*)d_in[5];
    const float* w_fc = (const float*)d_in[6];
    const float* gam  = (const float*)d_in[7];
    const float* bet  = (const float*)d_in[8];

    float* out  = (float*)d_out;                          // [B,N,D]
    float* attn = out + (long long)BB * NN_ * DD;         // [B,H,N,N]

    float *vp, *feat, *rsum;
    cudaGetSymbolAddress((void**)&vp,   g_vp);
    cudaGetSymbolAddress((void**)&feat, g_feat);
    cudaGetSymbolAddress((void**)&rsum, g_rowsum);
    bf16 *xqh, *xql, *xkh, *xkl, *xvh, *xvl;
    bf16 *wqh, *wql, *wkh, *wkl, *wvh, *wvl, *wfh, *wfl;
    bf16 *qph, *qpl, *kph, *kpl, *vth, *vtl, *fth, *ftl;
    cudaGetSymbolAddress((void**)&xqh, g_xq_hi); cudaGetSymbolAddress((void**)&xql, g_xq_lo);
    cudaGetSymbolAddress((void**)&xkh, g_xk_hi); cudaGetSymbolAddress((void**)&xkl, g_xk_lo);
    cudaGetSymbolAddress((void**)&xvh, g_xv_hi); cudaGetSymbolAddress((void**)&xvl, g_xv_lo);
    cudaGetSymbolAddress((void**)&wqh, g_wq_hi); cudaGetSymbolAddress((void**)&wql, g_wq_lo);
    cudaGetSymbolAddress((void**)&wkh, g_wk_hi); cudaGetSymbolAddress((void**)&wkl, g_wk_lo);
    cudaGetSymbolAddress((void**)&wvh, g_wv_hi); cudaGetSymbolAddress((void**)&wvl, g_wv_lo);
    cudaGetSymbolAddress((void**)&wfh, g_wf_hi); cudaGetSymbolAddress((void**)&wfl, g_wf_lo);
    cudaGetSymbolAddress((void**)&qph, g_qp_hi); cudaGetSymbolAddress((void**)&qpl, g_qp_lo);
    cudaGetSymbolAddress((void**)&kph, g_kp_hi); cudaGetSymbolAddress((void**)&kpl, g_kp_lo);
    cudaGetSymbolAddress((void**)&vth, g_vpt_hi); cudaGetSymbolAddress((void**)&vtl, g_vpt_lo);
    cudaGetSymbolAddress((void**)&fth, g_ft_hi); cudaGetSymbolAddress((void**)&ftl, g_ft_lo);

    cudaFuncSetAttribute(mma_gemm<0>, cudaFuncAttributeMaxDynamicSharedMemorySize, GM_SMEM);
    cudaFuncSetAttribute(mma_gemm<1>, cudaFuncAttributeMaxDynamicSharedMemorySize, GM_SMEM);
    cudaFuncSetAttribute(mma_gemm<2>, cudaFuncAttributeMaxDynamicSharedMemorySize, GM_SMEM);
    cudaFuncSetAttribute(scores_exp, cudaFuncAttributeMaxDynamicSharedMemorySize, SCX_SMEM);
    cudaFuncSetAttribute(av_mma,     cudaFuncAttributeMaxDynamicSharedMemorySize, AV_SMEM);

    const int M = BB * NN_;          // 8192
    const int n4i = M * DD / 4;      // inputs
    const int n4w = DD * DD / 4;     // weights

    // 1) splits of inputs + weights
    split_k<<<(n4i + 255) / 256, 256>>>(q, xqh, xql, n4i);
    split_k<<<(n4i + 255) / 256, 256>>>(k, xkh, xkl, n4i);
    split_k<<<(n4i + 255) / 256, 256>>>(v, xvh, xvl, n4i);
    split_k<<<(n4w + 255) / 256, 256>>>(w_q, wqh, wql, n4w);
    split_k<<<(n4w + 255) / 256, 256>>>(w_k, wkh, wkl, n4w);
    split_k<<<(n4w + 255) / 256, 256>>>(w_v, wvh, wvl, n4w);
    split_k<<<(n4w + 255) / 256, 256>>>(w_fc, wfh, wfl, n4w);

    // 2) projections on tensor cores
    {
        dim3 grid(DD / 128, M / 128);
        mma_gemm<2><<<grid, 256, GM_SMEM>>>(xqh, xql, wqh, wql, nullptr, qph, qpl, nullptr);
        mma_gemm<2><<<grid, 256, GM_SMEM>>>(xkh, xkl, wkh, wkl, nullptr, kph, kpl, nullptr);
        mma_gemm<0><<<grid, 256, GM_SMEM>>>(xvh, xvl, wvh, wvl, vp, nullptr, nullptr, nullptr);
    }
    vtrans_split<<<dim3(NN_ / 32, DD / 32, BB), dim3(32, 8)>>>(vp, vth, vtl);

    // 3) scores + exp + rowsum (unnormalized exp into attn region)
    scores_exp<<<dim3(NN_ / 128, BB * HH), 256, SCX_SMEM>>>(kph, kpl, qph, qpl, attn, rsum);

    // 4) attn@V with in-place normalization of attn
    av_mma<<<dim3(1, NN_ / 128, BB * HH), 256, AV_SMEM>>>(attn, rsum, vth, vtl, feat);

    // 5) fc + residual on tensor cores
    split_k<<<(n4i + 255) / 256, 256>>>(feat, fth, ftl, n4i);
    {
        dim3 grid(DD / 128, M / 128);
        mma_gemm<1><<<grid, 256, GM_SMEM>>>(fth, ftl, wfh, wfl, out, nullptr, nullptr, q);
    }

    // 6) LayerNorm
    layernorm_rows<<<M, 256>>>(out, gam, bet);
}

// round 6
// speedup vs baseline: 2.5099x; 1.0233x over previous
#include <cuda_runtime.h>
#include <cuda_bf16.h>
#include <cuda_fp16.h>
#include <math.h>
#include <stdint.h>

#define BB 2
#define NN_ 4096
#define DD 512
#define HH 8
#define DK 64

typedef __nv_bfloat16 bf16;

// ---------------------------------------------------------------------------
// Scratch (device globals — no allocation allowed)
// ---------------------------------------------------------------------------
__device__ float g_vp[BB * NN_ * DD];
__device__ float g_rowsum[BB * HH * NN_];

__device__ bf16 g_xq_hi[BB * NN_ * DD]; __device__ bf16 g_xq_lo[BB * NN_ * DD];
__device__ bf16 g_xk_hi[BB * NN_ * DD]; __device__ bf16 g_xk_lo[BB * NN_ * DD];
__device__ bf16 g_xv_hi[BB * NN_ * DD]; __device__ bf16 g_xv_lo[BB * NN_ * DD];
__device__ bf16 g_wq_hi[DD * DD]; __device__ bf16 g_wq_lo[DD * DD];
__device__ bf16 g_wk_hi[DD * DD]; __device__ bf16 g_wk_lo[DD * DD];
__device__ bf16 g_wv_hi[DD * DD]; __device__ bf16 g_wv_lo[DD * DD];
__device__ bf16 g_wf_hi[DD * DD]; __device__ bf16 g_wf_lo[DD * DD];
__device__ bf16 g_qp_hi[BB * NN_ * DD]; __device__ bf16 g_qp_lo[BB * NN_ * DD];
__device__ bf16 g_kp_hi[BB * NN_ * DD]; __device__ bf16 g_kp_lo[BB * NN_ * DD];
__device__ __half g_vpt_h[BB * HH * DK * NN_];           // [bh, d, token] fp16
__device__ bf16 g_ft_hi[BB * NN_ * DD]; __device__ bf16 g_ft_lo[BB * NN_ * DD];

// ---------------------------------------------------------------------------
// PTX helpers (arch-portable: cp.async / ldmatrix / mma.sync only)
// ---------------------------------------------------------------------------
__device__ __forceinline__ uint32_t smem_u32(const void* p) {
    uint32_t a;
    asm("{ .reg .u64 t; cvta.to.shared.u64 t, %1; cvt.u32.u64 %0, t; }"
        : "=r"(a) : "l"(p));
    return a;
}

#define CP16(dst, src) \
    asm volatile("cp.async.cg.shared.global [%0], [%1], 16;" :: "r"(dst), "l"(src))
#define CP_COMMIT() asm volatile("cp.async.commit_group;" ::: "memory")
#define CP_WAIT0()  asm volatile("cp.async.wait_group 0;" ::: "memory")
#define CP_WAIT1()  asm volatile("cp.async.wait_group 1;" ::: "memory")
#define CP_WAIT2()  asm volatile("cp.async.wait_group 2;" ::: "memory")

__device__ __forceinline__ void ldsm4(uint32_t& r0, uint32_t& r1, uint32_t& r2, uint32_t& r3,
                                      uint32_t addr) {
    asm volatile("ldmatrix.sync.aligned.m8n8.x4.shared.b16 {%0,%1,%2,%3}, [%4];"
                 : "=r"(r0), "=r"(r1), "=r"(r2), "=r"(r3) : "r"(addr));
}

__device__ __forceinline__ void mma16816(float* c,
                                         uint32_t a0, uint32_t a1, uint32_t a2, uint32_t a3,
                                         uint32_t b0, uint32_t b1) {
    asm volatile(
        "mma.sync.aligned.m16n8k16.row.col.f32.bf16.bf16.f32 "
        "{%0,%1,%2,%3}, {%4,%5,%6,%7}, {%8,%9}, {%0,%1,%2,%3};"
        : "+f"(c[0]), "+f"(c[1]), "+f"(c[2]), "+f"(c[3])
        : "r"(a0), "r"(a1), "r"(a2), "r"(a3), "r"(b0), "r"(b1));
}

__device__ __forceinline__ void mma16816h(float* c,
                                          uint32_t a0, uint32_t a1, uint32_t a2, uint32_t a3,
                                          uint32_t b0, uint32_t b1) {
    asm volatile(
        "mma.sync.aligned.m16n8k16.row.col.f32.f16.f16.f32 "
        "{%0,%1,%2,%3}, {%4,%5,%6,%7}, {%8,%9}, {%0,%1,%2,%3};"
        : "+f"(c[0]), "+f"(c[1]), "+f"(c[2]), "+f"(c[3])
        : "r"(a0), "r"(a1), "r"(a2), "r"(a3), "r"(b0), "r"(b1));
}

__device__ __forceinline__ void split1(float x, bf16& h, bf16& l) {
    h = __float2bfloat16(x);
    l = __float2bfloat16(x - __bfloat162float(h));
}

// ---------------------------------------------------------------------------
// fp32 -> bf16 hi/lo split (elementwise)
// ---------------------------------------------------------------------------
__global__ void split_k(const float* __restrict__ x,
                        bf16* __restrict__ hi, bf16* __restrict__ lo, int n4)
{
    int i = blockIdx.x * blockDim.x + threadIdx.x;
    if (i >= n4) return;
    float4 v = reinterpret_cast<const float4*>(x)[i];
    bf16 h[4], l[4];
    split1(v.x, h[0], l[0]); split1(v.y, h[1], l[1]);
    split1(v.z, h[2], l[2]); split1(v.w, h[3], l[3]);
    uint2 ph, pl;
    ph.x = ((uint32_t)*(uint16_t*)&h[1] << 16) | *(uint16_t*)&h[0];
    ph.y = ((uint32_t)*(uint16_t*)&h[3] << 16) | *(uint16_t*)&h[2];
    pl.x = ((uint32_t)*(uint16_t*)&l[1] << 16) | *(uint16_t*)&l[0];
    pl.y = ((uint32_t)*(uint16_t*)&l[3] << 16) | *(uint16_t*)&l[2];
    reinterpret_cast<uint2*>(hi)[i] = ph;
    reinterpret_cast<uint2*>(lo)[i] = pl;
}

// vp [B, N, D] fp32 -> vpT fp16 [B*H, DK, N]
__global__ void vtrans_f16(const float* __restrict__ vp, __half* __restrict__ vt)
{
    __shared__ float tile[32][33];
    const int j0 = blockIdx.x * 32;
    const int c0 = blockIdx.y * 32;
    const int b  = blockIdx.z;
    const int tx = threadIdx.x, ty = threadIdx.y;
    for (int rr = ty; rr < 32; rr += 8)
        tile[rr][tx] = vp[((long long)(b * NN_ + j0 + rr)) * DD + c0 + tx];
    __syncthreads();
    for (int rr = ty; rr < 32; rr += 8) {
        int c = c0 + rr;
        int h = c >> 6, dl = c & 63;
        long long idx = ((long long)(b * HH + h) * DK + dl) * NN_ + j0 + tx;
        vt[idx] = __float2half_rn(tile[tx][rr]);
    }
}

// ---------------------------------------------------------------------------
// Tensor-core GEMM (NT): C[M,512] = A[M,512] @ W[512,512]^T  via hi/lo split.
// BM=BN=128, BK=32, 3-stage cp.async pipeline. 8 warps (2M x 4N).
// OUTM: 0 = fp32 out; 1 = fp32 out + residual; 2 = bf16 hi/lo out.
// ---------------------------------------------------------------------------
#define GM_SMEM 122880
#define GM_STG  40960u

template<int OUTM>
__global__ void __launch_bounds__(256)
mma_gemm(const bf16* __restrict__ Ahi, const bf16* __restrict__ Alo,
         const bf16* __restrict__ Bhi, const bf16* __restrict__ Blo,
         float* __restrict__ Cf, bf16* __restrict__ Chi, bf16* __restrict__ Clo,
         const float* __restrict__ R)
{
    extern __shared__ char smem[];
    const int tid = threadIdx.x;
    const int wid = tid >> 5;
    const int lane = tid & 31;
    const uint32_t sb = smem_u32(smem);
    const int n0 = blockIdx.x * 128;
    const int m0 = blockIdx.y * 128;

    const int wm = (wid >> 2) * 64;
    const int wn = (wid & 3) * 32;

    float acc[4][4][4];
#pragma unroll
    for (int i = 0; i < 4; i++)
#pragma unroll
        for (int j = 0; j < 4; j++)
#pragma unroll
            for (int c = 0; c < 4; c++) acc[i][j][c] = 0.0f;

    auto load_stage = [&](int kt, int s) {
        const int k0 = kt * 32;
        const uint32_t st = sb + (uint32_t)s * GM_STG;
        for (int i = tid; i < 2048; i += 256) {
            int t = i >> 9, r = (i & 511) >> 2, c = i & 3;
            const bf16* src;
            if (t == 0)      src = Ahi + (long long)(m0 + r) * DD + k0 + c * 8;
            else if (t == 1) src = Alo + (long long)(m0 + r) * DD + k0 + c * 8;
            else if (t == 2) src = Bhi + (long long)(n0 + r) * DD + k0 + c * 8;
            else             src = Blo + (long long)(n0 + r) * DD + k0 + c * 8;
            CP16(st + (uint32_t)t * 10240u + (uint32_t)(r * 80 + c * 16), (const char*)src);
        }
    };

    load_stage(0, 0); CP_COMMIT();
    load_stage(1, 1); CP_COMMIT();

    for (int kt = 0; kt < 16; kt++) {
        if (kt + 2 < 16) { load_stage(kt + 2, (kt + 2) % 3); CP_COMMIT(); CP_WAIT2(); }
        else if (kt + 1 < 16) { CP_WAIT1(); }
        else { CP_WAIT0(); }
        __syncthreads();
        const uint32_t st = sb + (uint32_t)(kt % 3) * GM_STG;
#pragma unroll
        for (int prod = 0; prod < 3; prod++) {
            const uint32_t Ab = st + ((prod == 1) ? 10240u : 0u);
            const uint32_t Bb = st + 20480u + ((prod == 2) ? 10240u : 0u);
#pragma unroll
            for (int kc = 0; kc < 2; kc++) {
                const uint32_t colA = (uint32_t)(kc * 32 + ((lane >> 4) & 1) * 16);
                const uint32_t colB = (uint32_t)(kc * 32 + ((lane >> 3) & 1) * 16);
                uint32_t bf[8];
#pragma unroll
                for (int j = 0; j < 2; j++) {
                    int n = wn + j * 16 + ((lane >> 4) & 1) * 8 + (lane & 7);
                    ldsm4(bf[j * 4 + 0], bf[j * 4 + 1], bf[j * 4 + 2], bf[j * 4 + 3],
                          Bb + (uint32_t)(n * 80) + colB);
                }
#pragma unroll
                for (int mi = 0; mi < 4; mi++) {
                    uint32_t a0, a1, a2, a3;
                    int m = wm + mi * 16 + (lane & 15);
                    ldsm4(a0, a1, a2, a3, Ab + (uint32_t)(m * 80) + colA);
#pragma unroll
                    for (int j = 0; j < 2; j++) {
                        mma16816(acc[mi][2 * j],     a0, a1, a2, a3, bf[j * 4 + 0], bf[j * 4 + 1]);
                        mma16816(acc[mi][2 * j + 1], a0, a1, a2, a3, bf[j * 4 + 2], bf[j * 4 + 3]);
                    }
                }
            }
        }
        __syncthreads();
    }

    // epilogue: direct stores from fragments
#pragma unroll
    for (int mi = 0; mi < 4; mi++) {
#pragma unroll
        for (int ni = 0; ni < 4; ni++) {
            int r  = wm + mi * 16 + (lane >> 2);
            int cc = wn + ni * 8 + (lane & 3) * 2;
#pragma unroll
            for (int half = 0; half < 2; half++) {
                int row = m0 + r + half * 8;
                int col = n0 + cc;
                float v0 = acc[mi][ni][half * 2 + 0];
                float v1 = acc[mi][ni][half * 2 + 1];
                if (OUTM == 2) {
                    bf16 h0, l0, h1, l1;
                    split1(v0, h0, l0); split1(v1, h1, l1);
                    uint32_t ph = ((uint32_t)*(uint16_t*)&h1 << 16) | *(uint16_t*)&h0;
                    uint32_t pl = ((uint32_t)*(uint16_t*)&l1 << 16) | *(uint16_t*)&l0;
                    *reinterpret_cast<uint32_t*>(Chi + (long long)row * DD + col) = ph;
                    *reinterpret_cast<uint32_t*>(Clo + (long long)row * DD + col) = pl;
                } else {
                    if (OUTM == 1) {
                        float2 r2 = *reinterpret_cast<const float2*>(R + (long long)row * DD + col);
                        v0 += r2.x; v1 += r2.y;
                    }
                    float2 o; o.x = v0; o.y = v1;
                    *reinterpret_cast<float2*>(Cf + (long long)row * DD + col) = o;
                }
            }
        }
    }
}

// ---------------------------------------------------------------------------
// scores_exp: per (b,h), CTA = 128 K-rows x ALL 4096 Q-cols.
// Writes exp(0.125 * Kp@Qp^T) (unnormalized) into attn region, and
// deterministic per-row sums into g_rowsum. A resident, B streamed (2-stage).
// ---------------------------------------------------------------------------
#define SCX_SMEM 110592

__global__ void __launch_bounds__(256)
scores_exp(const bf16* __restrict__ Khi, const bf16* __restrict__ Klo,
           const bf16* __restrict__ Qhi, const bf16* __restrict__ Qlo,
           float* __restrict__ S, float* __restrict__ rowsum)
{
    extern __shared__ char smem[];
    const int tid = threadIdx.x;
    const int wid = tid >> 5;
    const int lane = tid & 31;
    const uint32_t sb = smem_u32(smem);

    const int m0 = blockIdx.x * 128;
    const int bh = blockIdx.y;
    const int b = bh >> 3, h = bh & 7;
    const long long arow = (long long)(b * NN_ + m0);
    const int coff = h * DK;

    for (int i = tid; i < 2048; i += 256) {
        int t = i >> 10, r = (i & 1023) >> 3, c = i & 7;
        const bf16* src = (t ? Klo : Khi) + (arow + r) * DD + coff + c * 8;
        CP16(sb + (uint32_t)t * 18432u + (uint32_t)(r * 144 + c * 16), (const char*)src);
    }

    auto load_B = [&](int nb, int s) {
        const long long brow = (long long)b * NN_ + (long long)nb * 128;
        const uint32_t st = sb + 36864u + (uint32_t)s * 36864u;
        for (int i = tid; i < 2048; i += 256) {
            int t = i >> 10, r = (i & 1023) >> 3, c = i & 7;
            const bf16* src = (t ? Qlo : Qhi) + (brow + r) * DD + coff + c * 8;
            CP16(st + (uint32_t)t * 18432u + (uint32_t)(r * 144 + c * 16), (const char*)src);
        }
    };

    load_B(0, 0); CP_COMMIT();

    const int wm = (wid >> 2) * 64;
    const int wn = (wid & 3) * 32;
    const long long cbase = (long long)bh * NN_ * NN_;
    float rs[8];
#pragma unroll
    for (int i = 0; i < 8; i++) rs[i] = 0.0f;

    for (int nb = 0; nb < 32; nb++) {
        if (nb < 31) { load_B(nb + 1, (nb + 1) & 1); CP_COMMIT(); }
        if (nb < 31) CP_WAIT1(); else CP_WAIT0();
        __syncthreads();

        float acc[4][4][4];
#pragma unroll
        for (int i = 0; i < 4; i++)
#pragma unroll
            for (int j = 0; j < 4; j++)
#pragma unroll
                for (int c = 0; c < 4; c++) acc[i][j][c] = 0.0f;

        const uint32_t Bst = sb + 36864u + (uint32_t)(nb & 1) * 36864u;
#pragma unroll
        for (int prod = 0; prod < 3; prod++) {
            const uint32_t Ab = sb + ((prod == 1) ? 18432u : 0u);
            const uint32_t Bb = Bst + ((prod == 2) ? 18432u : 0u);
#pragma unroll
            for (int kc = 0; kc < 4; kc++) {
                const uint32_t colA = (uint32_t)(kc * 32 + ((lane >> 4) & 1) * 16);
                const uint32_t colB = (uint32_t)(kc * 32 + ((lane >> 3) & 1) * 16);
                uint32_t bf[8];
#pragma unroll
                for (int j = 0; j < 2; j++) {
                    int n = wn + j * 16 + ((lane >> 4) & 1) * 8 + (lane & 7);
                    ldsm4(bf[j * 4 + 0], bf[j * 4 + 1], bf[j * 4 + 2], bf[j * 4 + 3],
                          Bb + (uint32_t)(n * 144) + colB);
                }
#pragma unroll
                for (int mi = 0; mi < 4; mi++) {
                    uint32_t a0, a1, a2, a3;
                    int m = wm + mi * 16 + (lane & 15);
                    ldsm4(a0, a1, a2, a3, Ab + (uint32_t)(m * 144) + colA);
#pragma unroll
                    for (int j = 0; j < 2; j++) {
                        mma16816(acc[mi][2 * j],     a0, a1, a2, a3, bf[j * 4 + 0], bf[j * 4 + 1]);
                        mma16816(acc[mi][2 * j + 1], a0, a1, a2, a3, bf[j * 4 + 2], bf[j * 4 + 3]);
                    }
                }
            }
        }

#pragma unroll
        for (int mi = 0; mi < 4; mi++) {
#pragma unroll
            for (int ni = 0; ni < 4; ni++) {
                int r  = wm + mi * 16 + (lane >> 2);
                int cc = wn + ni * 8 + (lane & 3) * 2;
                long long col = (long long)nb * 128 + cc;
#pragma unroll
                for (int half = 0; half < 2; half++) {
                    float e0 = __expf(0.125f * acc[mi][ni][half * 2 + 0]);
                    float e1 = __expf(0.125f * acc[mi][ni][half * 2 + 1]);
                    float2 o; o.x = e0; o.y = e1;
                    *reinterpret_cast<float2*>(
                        S + cbase + (long long)(m0 + r + half * 8) * NN_ + col) = o;
                    rs[mi * 2 + half] += e0 + e1;
                }
            }
        }
        __syncthreads();
    }

    // deterministic rowsum reduction
#pragma unroll
    for (int i = 0; i < 8; i++) {
        rs[i] += __shfl_xor_sync(~0u, rs[i], 1);
        rs[i] += __shfl_xor_sync(~0u, rs[i], 2);
    }
    float* rsm = (float*)(smem + 36864);
    if ((lane & 3) == 0) {
#pragma unroll
        for (int mi = 0; mi < 4; mi++)
#pragma unroll
            for (int half = 0; half < 2; half++) {
                int lr = wm + mi * 16 + half * 8 + (lane >> 2);
                rsm[(wid & 3) * 128 + lr] = rs[mi * 2 + half];
            }
    }
    __syncthreads();
    if (tid < 128) {
        float t = rsm[tid] + rsm[128 + tid] + rsm[256 + tid] + rsm[384 + tid];
        rowsum[(long long)bh * NN_ + m0 + tid] = t;
    }
}

// ---------------------------------------------------------------------------
// av_mma: feat = softmax(S) @ Vp via SINGLE fp16 product.
// Reads unnormalized exp S, scales by 1/rowsum, writes normalized attn back
// IN PLACE, converts to fp16, MMA against fp16 V^T. Emits feat as bf16 hi/lo.
// BM=128, BN=64, K=4096 (chunks of 32), double-buffered.
// ---------------------------------------------------------------------------
#define AV_SMEM 30720
#define AV_STAGE 15360u
#define AV_VOFF 10240u

__global__ void __launch_bounds__(256)
av_mma(float* __restrict__ S, const float* __restrict__ rowsum,
       const __half* __restrict__ Vh,
       bf16* __restrict__ Fhi, bf16* __restrict__ Flo)
{
    extern __shared__ char smem[];
    const int tid = threadIdx.x;
    const int wid = tid >> 5;
    const int lane = tid & 31;
    const uint32_t sb = smem_u32(smem);

    const int m0 = blockIdx.y * 128;
    const int bh = blockIdx.z;
    const int b = bh >> 3, h = bh & 7;

    float* Abase = S + (long long)bh * NN_ * NN_ + (long long)m0 * NN_;
    const long long vrow = (long long)bh * DK;

    const int wm = (wid >> 1) * 32;
    const int wn = (wid & 1) * 32;

    float acc[2][4][4];
#pragma unroll
    for (int i = 0; i < 2; i++)
#pragma unroll
        for (int j = 0; j < 4; j++)
#pragma unroll
            for (int c = 0; c < 4; c++) acc[i][j][c] = 0.0f;

    const int ar_r[4]  = { tid >> 3, (tid + 256) >> 3, (tid + 512) >> 3, (tid + 768) >> 3 };
    const int c4 = tid & 7;

    float inv4[4];
#pragma unroll
    for (int q = 0; q < 4; q++)
        inv4[q] = __frcp_rn(rowsum[(long long)bh * NN_ + m0 + ar_r[q]]);

    float4 ar[4];
#pragma unroll
    for (int q = 0; q < 4; q++)
        ar[q] = *reinterpret_cast<const float4*>(Abase + (long long)ar_r[q] * NN_ + c4 * 4);

    for (int chunk = 0; chunk < 128; chunk++) {
        const uint32_t stoff = (uint32_t)(chunk & 1) * AV_STAGE;
        const uint32_t st = sb + stoff;
        const int k0 = chunk * 32;

        // V chunk fp16: 64 rows x 64B = 256 CP16
        {
            int rr = tid >> 2, cc = tid & 3;
            CP16(st + AV_VOFF + (uint32_t)(rr * 80 + cc * 16),
                 (const char*)(Vh + (vrow + rr) * NN_ + k0 + cc * 8));
        }
        CP_COMMIT();

        // normalize, write attn in place, convert to fp16, STS
#pragma unroll
        for (int q = 0; q < 4; q++) {
            ar[q].x *= inv4[q]; ar[q].y *= inv4[q];
            ar[q].z *= inv4[q]; ar[q].w *= inv4[q];
            *reinterpret_cast<float4*>(Abase + (long long)ar_r[q] * NN_ + k0 + c4 * 4) = ar[q];
            __half2 h01 = __floats2half2_rn(ar[q].x, ar[q].y);
            __half2 h23 = __floats2half2_rn(ar[q].z, ar[q].w);
            uint2 pk;
            pk.x = *reinterpret_cast<uint32_t*>(&h01);
            pk.y = *reinterpret_cast<uint32_t*>(&h23);
            *reinterpret_cast<uint2*>(smem + stoff + (uint32_t)(ar_r[q] * 80 + c4 * 8)) = pk;
        }

        if (chunk < 127) {
#pragma unroll
            for (int q = 0; q < 4; q++)
                ar[q] = *reinterpret_cast<const float4*>(
                    Abase + (long long)ar_r[q] * NN_ + k0 + 32 + c4 * 4);
        }

        CP_WAIT0();
        __syncthreads();

#pragma unroll
        for (int kc = 0; kc < 2; kc++) {
            const uint32_t colA = (uint32_t)(kc * 32 + ((lane >> 4) & 1) * 16);
            const uint32_t colB = (uint32_t)(kc * 32 + ((lane >> 3) & 1) * 16);
            uint32_t bf[8];
#pragma unroll
            for (int j = 0; j < 2; j++) {
                int n = wn + j * 16 + ((lane >> 4) & 1) * 8 + (lane & 7);
                ldsm4(bf[j * 4 + 0], bf[j * 4 + 1], bf[j * 4 + 2], bf[j * 4 + 3],
                      st + AV_VOFF + (uint32_t)(n * 80) + colB);
            }
#pragma unroll
            for (int mi = 0; mi < 2; mi++) {
                uint32_t a0, a1, a2, a3;
                int m = wm + mi * 16 + (lane & 15);
                ldsm4(a0, a1, a2, a3, st + (uint32_t)(m * 80) + colA);
#pragma unroll
                for (int j = 0; j < 2; j++) {
                    mma16816h(acc[mi][2 * j],     a0, a1, a2, a3, bf[j * 4 + 0], bf[j * 4 + 1]);
                    mma16816h(acc[mi][2 * j + 1], a0, a1, a2, a3, bf[j * 4 + 2], bf[j * 4 + 3]);
                }
            }
        }
        __syncthreads();
    }

    // epilogue: emit feat as bf16 hi/lo directly
#pragma unroll
    for (int mi = 0; mi < 2; mi++) {
#pragma unroll
        for (int ni = 0; ni < 4; ni++) {
            int r  = wm + mi * 16 + (lane >> 2);
            int cc = wn + ni * 8 + (lane & 3) * 2;
#pragma unroll
            for (int half = 0; half < 2; half++) {
                long long row = (long long)(b * NN_ + m0 + r + half * 8);
                int col = h * DK + cc;
                float v0 = acc[mi][ni][half * 2 + 0];
                float v1 = acc[mi][ni][half * 2 + 1];
                bf16 h0, l0, h1, l1;
                split1(v0, h0, l0); split1(v1, h1, l1);
                uint32_t ph = ((uint32_t)*(uint16_t*)&h1 << 16) | *(uint16_t*)&h0;
                uint32_t pl = ((uint32_t)*(uint16_t*)&l1 << 16) | *(uint16_t*)&l0;
                *reinterpret_cast<uint32_t*>(Fhi + row * DD + col) = ph;
                *reinterpret_cast<uint32_t*>(Flo + row * DD + col) = pl;
            }
        }
    }
}

// ---------------------------------------------------------------------------
// In-place row LayerNorm
// ---------------------------------------------------------------------------
__global__ void layernorm_rows(float* __restrict__ y,
                               const float* __restrict__ gamma,
                               const float* __restrict__ beta)
{
    const long long base = (long long)blockIdx.x * DD;
    const int t = threadIdx.x;
    const int lane = t & 31, warp = t >> 5;
    __shared__ float red[32];

    float x0 = y[base + t];
    float x1 = y[base + t + 256];

    float s = x0 + x1;
#pragma unroll
    for (int o = 16; o > 0; o >>= 1) s += __shfl_xor_sync(~0u, s, o);
    if (lane == 0) red[warp] = s;
    __syncthreads();
    if (warp == 0) {
        float x = (lane < 8) ? red[lane] : 0.0f;
#pragma unroll
        for (int o = 16; o > 0; o >>= 1) x += __shfl_xor_sync(~0u, x, o);
        if (lane == 0) red[0] = x;
    }
    __syncthreads();
    const float mu = red[0] * (1.0f / DD);
    __syncthreads();

    const float d0 = x0 - mu, d1 = x1 - mu;
    float v = d0 * d0 + d1 * d1;
#pragma unroll
    for (int o = 16; o > 0; o >>= 1) v += __shfl_xor_sync(~0u, v, o);
    if (lane == 0) red[warp] = v;
    __syncthreads();
    if (warp == 0) {
        float x = (lane < 8) ? red[lane] : 0.0f;
#pragma unroll
        for (int o = 16; o > 0; o >>= 1) x += __shfl_xor_sync(~0u, x, o);
        if (lane == 0) red[0] = x;
    }
    __syncthreads();
    const float r = rsqrtf(red[0] * (1.0f / DD) + 1e-5f);

    y[base + t]       = d0 * r * gamma[t]       + beta[t];
    y[base + t + 256] = d1 * r * gamma[t + 256] + beta[t + 256];
}

// ---------------------------------------------------------------------------
extern "C" void kernel_launch(void* const* d_in, const int* in_sizes, int n_in,
                              void* d_out, int out_size)
{
    const float* q    = (const float*)d_in[0];
    const float* k    = (const float*)d_in[1];
    const float* v    = (const float*)d_in[2];
    const float* w_q  = (const float*)d_in[3];
    const float* w_k  = (const float*)d_in[4];
    const float* w_v  = (const float*)d_in[5];
    const float* w_fc = (const float*)d_in[6];
    const float* gam  = (const float*)d_in[7];
    const float* bet  = (const float*)d_in[8];

    float* out  = (float*)d_out;                          // [B,N,D]
    float* attn = out + (long long)BB * NN_ * DD;         // [B,H,N,N]

    float *vp, *rsum;
    cudaGetSymbolAddress((void**)&vp,   g_vp);
    cudaGetSymbolAddress((void**)&rsum, g_rowsum);
    bf16 *xqh, *xql, *xkh, *xkl, *xvh, *xvl;
    bf16 *wqh, *wql, *wkh, *wkl, *wvh, *wvl, *wfh, *wfl;
    bf16 *qph, *qpl, *kph, *kpl, *fth, *ftl;
    __half* vth;
    cudaGetSymbolAddress((void**)&xqh, g_xq_hi); cudaGetSymbolAddress((void**)&xql, g_xq_lo);
    cudaGetSymbolAddress((void**)&xkh, g_xk_hi); cudaGetSymbolAddress((void**)&xkl, g_xk_lo);
    cudaGetSymbolAddress((void**)&xvh, g_xv_hi); cudaGetSymbolAddress((void**)&xvl, g_xv_lo);
    cudaGetSymbolAddress((void**)&wqh, g_wq_hi); cudaGetSymbolAddress((void**)&wql, g_wq_lo);
    cudaGetSymbolAddress((void**)&wkh, g_wk_hi); cudaGetSymbolAddress((void**)&wkl, g_wk_lo);
    cudaGetSymbolAddress((void**)&wvh, g_wv_hi); cudaGetSymbolAddress((void**)&wvl, g_wv_lo);
    cudaGetSymbolAddress((void**)&wfh, g_wf_hi); cudaGetSymbolAddress((void**)&wfl, g_wf_lo);
    cudaGetSymbolAddress((void**)&qph, g_qp_hi); cudaGetSymbolAddress((void**)&qpl, g_qp_lo);
    cudaGetSymbolAddress((void**)&kph, g_kp_hi); cudaGetSymbolAddress((void**)&kpl, g_kp_lo);
    cudaGetSymbolAddress((void**)&vth, g_vpt_h);
    cudaGetSymbolAddress((void**)&fth, g_ft_hi); cudaGetSymbolAddress((void**)&ftl, g_ft_lo);

    cudaFuncSetAttribute(mma_gemm<0>, cudaFuncAttributeMaxDynamicSharedMemorySize, GM_SMEM);
    cudaFuncSetAttribute(mma_gemm<1>, cudaFuncAttributeMaxDynamicSharedMemorySize, GM_SMEM);
    cudaFuncSetAttribute(mma_gemm<2>, cudaFuncAttributeMaxDynamicSharedMemorySize, GM_SMEM);
    cudaFuncSetAttribute(scores_exp, cudaFuncAttributeMaxDynamicSharedMemorySize, SCX_SMEM);
    cudaFuncSetAttribute(av_mma,     cudaFuncAttributeMaxDynamicSharedMemorySize, AV_SMEM);

    const int M = BB * NN_;          // 8192
    const int n4i = M * DD / 4;
    const int n4w = DD * DD / 4;

    // 1) splits of inputs + weights
    split_k<<<(n4i + 255) / 256, 256>>>(q, xqh, xql, n4i);
    split_k<<<(n4i + 255) / 256, 256>>>(k, xkh, xkl, n4i);
    split_k<<<(n4i + 255) / 256, 256>>>(v, xvh, xvl, n4i);
    split_k<<<(n4w + 255) / 256, 256>>>(w_q, wqh, wql, n4w);
    split_k<<<(n4w + 255) / 256, 256>>>(w_k, wkh, wkl, n4w);
    split_k<<<(n4w + 255) / 256, 256>>>(w_v, wvh, wvl, n4w);
    split_k<<<(n4w + 255) / 256, 256>>>(w_fc, wfh, wfl, n4w);

    // 2) projections on tensor cores
    {
        dim3 grid(DD / 128, M / 128);
        mma_gemm<2><<<grid, 256, GM_SMEM>>>(xqh, xql, wqh, wql, nullptr, qph, qpl, nullptr);
        mma_gemm<2><<<grid, 256, GM_SMEM>>>(xkh, xkl, wkh, wkl, nullptr, kph, kpl, nullptr);
        mma_gemm<0><<<grid, 256, GM_SMEM>>>(xvh, xvl, wvh, wvl, vp, nullptr, nullptr, nullptr);
    }
    vtrans_f16<<<dim3(NN_ / 32, DD / 32, BB), dim3(32, 8)>>>(vp, vth);

    // 3) scores + exp + rowsum (unnormalized exp into attn region)
    scores_exp<<<dim3(NN_ / 128, BB * HH), 256, SCX_SMEM>>>(kph, kpl, qph, qpl, attn, rsum);

    // 4) attn@V (fp16) with in-place normalization of attn; emits feat hi/lo
    av_mma<<<dim3(1, NN_ / 128, BB * HH), 256, AV_SMEM>>>(attn, rsum, vth, fth, ftl);

    // 5) fc + residual on tensor cores
    {
        dim3 grid(DD / 128, M / 128);
        mma_gemm<1><<<grid, 256, GM_SMEM>>>(fth, ftl, wfh, wfl, out, nullptr, nullptr, q);
    }

    // 6) LayerNorm
    layernorm_rows<<<M, 256>>>(out, gam, bet);
}

// round 7
// speedup vs baseline: 2.5947x; 1.0338x over previous
#include <cuda_runtime.h>
#include <cuda_bf16.h>
#include <cuda_fp16.h>
#include <math.h>
#include <stdint.h>

#define BB 2
#define NN_ 4096
#define DD 512
#define HH 8
#define DK 64

typedef __nv_bfloat16 bf16;

// ---------------------------------------------------------------------------
// Scratch (device globals — no allocation allowed)
// ---------------------------------------------------------------------------
__device__ float g_vp[BB * NN_ * DD];

__device__ bf16 g_xq_hi[BB * NN_ * DD]; __device__ bf16 g_xq_lo[BB * NN_ * DD];
__device__ bf16 g_xk_hi[BB * NN_ * DD]; __device__ bf16 g_xk_lo[BB * NN_ * DD];
__device__ bf16 g_xv_hi[BB * NN_ * DD]; __device__ bf16 g_xv_lo[BB * NN_ * DD];
__device__ bf16 g_wq_hi[DD * DD]; __device__ bf16 g_wq_lo[DD * DD];
__device__ bf16 g_wk_hi[DD * DD]; __device__ bf16 g_wk_lo[DD * DD];
__device__ bf16 g_wv_hi[DD * DD]; __device__ bf16 g_wv_lo[DD * DD];
__device__ bf16 g_wf_hi[DD * DD]; __device__ bf16 g_wf_lo[DD * DD];
__device__ bf16 g_qp_hi[BB * NN_ * DD]; __device__ bf16 g_qp_lo[BB * NN_ * DD];
__device__ bf16 g_kp_hi[BB * NN_ * DD]; __device__ bf16 g_kp_lo[BB * NN_ * DD];
__device__ __half g_vpt_h[BB * HH * DK * NN_];           // [bh, d, token] fp16
__device__ bf16 g_ft_hi[BB * NN_ * DD]; __device__ bf16 g_ft_lo[BB * NN_ * DD];

// ---------------------------------------------------------------------------
// PTX helpers (arch-portable: cp.async / ldmatrix / mma.sync only)
// ---------------------------------------------------------------------------
__device__ __forceinline__ uint32_t smem_u32(const void* p) {
    uint32_t a;
    asm("{ .reg .u64 t; cvta.to.shared.u64 t, %1; cvt.u32.u64 %0, t; }"
        : "=r"(a) : "l"(p));
    return a;
}

#define CP16(dst, src) \
    asm volatile("cp.async.cg.shared.global [%0], [%1], 16;" :: "r"(dst), "l"(src))
#define CP_COMMIT() asm volatile("cp.async.commit_group;" ::: "memory")
#define CP_WAIT0()  asm volatile("cp.async.wait_group 0;" ::: "memory")
#define CP_WAIT1()  asm volatile("cp.async.wait_group 1;" ::: "memory")
#define CP_WAIT2()  asm volatile("cp.async.wait_group 2;" ::: "memory")

__device__ __forceinline__ void ldsm4(uint32_t& r0, uint32_t& r1, uint32_t& r2, uint32_t& r3,
                                      uint32_t addr) {
    asm volatile("ldmatrix.sync.aligned.m8n8.x4.shared.b16 {%0,%1,%2,%3}, [%4];"
                 : "=r"(r0), "=r"(r1), "=r"(r2), "=r"(r3) : "r"(addr));
}

__device__ __forceinline__ void mma16816(float* c,
                                         uint32_t a0, uint32_t a1, uint32_t a2, uint32_t a3,
                                         uint32_t b0, uint32_t b1) {
    asm volatile(
        "mma.sync.aligned.m16n8k16.row.col.f32.bf16.bf16.f32 "
        "{%0,%1,%2,%3}, {%4,%5,%6,%7}, {%8,%9}, {%0,%1,%2,%3};"
        : "+f"(c[0]), "+f"(c[1]), "+f"(c[2]), "+f"(c[3])
        : "r"(a0), "r"(a1), "r"(a2), "r"(a3), "r"(b0), "r"(b1));
}

__device__ __forceinline__ void mma16816h(float* c,
                                          uint32_t a0, uint32_t a1, uint32_t a2, uint32_t a3,
                                          uint32_t b0, uint32_t b1) {
    asm volatile(
        "mma.sync.aligned.m16n8k16.row.col.f32.f16.f16.f32 "
        "{%0,%1,%2,%3}, {%4,%5,%6,%7}, {%8,%9}, {%0,%1,%2,%3};"
        : "+f"(c[0]), "+f"(c[1]), "+f"(c[2]), "+f"(c[3])
        : "r"(a0), "r"(a1), "r"(a2), "r"(a3), "r"(b0), "r"(b1));
}

__device__ __forceinline__ void split1(float x, bf16& h, bf16& l) {
    h = __float2bfloat16(x);
    l = __float2bfloat16(x - __bfloat162float(h));
}

// ---------------------------------------------------------------------------
// fp32 -> bf16 hi/lo split (elementwise)
// ---------------------------------------------------------------------------
__global__ void split_k(const float* __restrict__ x,
                        bf16* __restrict__ hi, bf16* __restrict__ lo, int n4)
{
    int i = blockIdx.x * blockDim.x + threadIdx.x;
    if (i >= n4) return;
    float4 v = reinterpret_cast<const float4*>(x)[i];
    bf16 h[4], l[4];
    split1(v.x, h[0], l[0]); split1(v.y, h[1], l[1]);
    split1(v.z, h[2], l[2]); split1(v.w, h[3], l[3]);
    uint2 ph, pl;
    ph.x = ((uint32_t)*(uint16_t*)&h[1] << 16) | *(uint16_t*)&h[0];
    ph.y = ((uint32_t)*(uint16_t*)&h[3] << 16) | *(uint16_t*)&h[2];
    pl.x = ((uint32_t)*(uint16_t*)&l[1] << 16) | *(uint16_t*)&l[0];
    pl.y = ((uint32_t)*(uint16_t*)&l[3] << 16) | *(uint16_t*)&l[2];
    reinterpret_cast<uint2*>(hi)[i] = ph;
    reinterpret_cast<uint2*>(lo)[i] = pl;
}

// vp [B, N, D] fp32 -> vpT fp16 [B*H, DK, N]
__global__ void vtrans_f16(const float* __restrict__ vp, __half* __restrict__ vt)
{
    __shared__ float tile[32][33];
    const int j0 = blockIdx.x * 32;
    const int c0 = blockIdx.y * 32;
    const int b  = blockIdx.z;
    const int tx = threadIdx.x, ty = threadIdx.y;
    for (int rr = ty; rr < 32; rr += 8)
        tile[rr][tx] = vp[((long long)(b * NN_ + j0 + rr)) * DD + c0 + tx];
    __syncthreads();
    for (int rr = ty; rr < 32; rr += 8) {
        int c = c0 + rr;
        int h = c >> 6, dl = c & 63;
        long long idx = ((long long)(b * HH + h) * DK + dl) * NN_ + j0 + tx;
        vt[idx] = __float2half_rn(tile[tx][rr]);
    }
}

// ---------------------------------------------------------------------------
// Tensor-core GEMM (NT): C[M,512] = A[M,512] @ W[512,512]^T  via hi/lo split.
// BM=BN=128, BK=32, 3-stage cp.async pipeline. 8 warps (2M x 4N).
// OUTM: 0 = fp32 out; 1 = fp32 out + residual; 2 = bf16 hi/lo out.
// ---------------------------------------------------------------------------
#define GM_SMEM 122880
#define GM_STG  40960u

template<int OUTM>
__global__ void __launch_bounds__(256)
mma_gemm(const bf16* __restrict__ Ahi, const bf16* __restrict__ Alo,
         const bf16* __restrict__ Bhi, const bf16* __restrict__ Blo,
         float* __restrict__ Cf, bf16* __restrict__ Chi, bf16* __restrict__ Clo,
         const float* __restrict__ R)
{
    extern __shared__ char smem[];
    const int tid = threadIdx.x;
    const int wid = tid >> 5;
    const int lane = tid & 31;
    const uint32_t sb = smem_u32(smem);
    const int n0 = blockIdx.x * 128;
    const int m0 = blockIdx.y * 128;

    const int wm = (wid >> 2) * 64;
    const int wn = (wid & 3) * 32;

    float acc[4][4][4];
#pragma unroll
    for (int i = 0; i < 4; i++)
#pragma unroll
        for (int j = 0; j < 4; j++)
#pragma unroll
            for (int c = 0; c < 4; c++) acc[i][j][c] = 0.0f;

    auto load_stage = [&](int kt, int s) {
        const int k0 = kt * 32;
        const uint32_t st = sb + (uint32_t)s * GM_STG;
        for (int i = tid; i < 2048; i += 256) {
            int t = i >> 9, r = (i & 511) >> 2, c = i & 3;
            const bf16* src;
            if (t == 0)      src = Ahi + (long long)(m0 + r) * DD + k0 + c * 8;
            else if (t == 1) src = Alo + (long long)(m0 + r) * DD + k0 + c * 8;
            else if (t == 2) src = Bhi + (long long)(n0 + r) * DD + k0 + c * 8;
            else             src = Blo + (long long)(n0 + r) * DD + k0 + c * 8;
            CP16(st + (uint32_t)t * 10240u + (uint32_t)(r * 80 + c * 16), (const char*)src);
        }
    };

    load_stage(0, 0); CP_COMMIT();
    load_stage(1, 1); CP_COMMIT();

    for (int kt = 0; kt < 16; kt++) {
        if (kt + 2 < 16) { load_stage(kt + 2, (kt + 2) % 3); CP_COMMIT(); CP_WAIT2(); }
        else if (kt + 1 < 16) { CP_WAIT1(); }
        else { CP_WAIT0(); }
        __syncthreads();
        const uint32_t st = sb + (uint32_t)(kt % 3) * GM_STG;
#pragma unroll
        for (int prod = 0; prod < 3; prod++) {
            const uint32_t Ab = st + ((prod == 1) ? 10240u : 0u);
            const uint32_t Bb = st + 20480u + ((prod == 2) ? 10240u : 0u);
#pragma unroll
            for (int kc = 0; kc < 2; kc++) {
                const uint32_t colA = (uint32_t)(kc * 32 + ((lane >> 4) & 1) * 16);
                const uint32_t colB = (uint32_t)(kc * 32 + ((lane >> 3) & 1) * 16);
                uint32_t bf[8];
#pragma unroll
                for (int j = 0; j < 2; j++) {
                    int n = wn + j * 16 + ((lane >> 4) & 1) * 8 + (lane & 7);
                    ldsm4(bf[j * 4 + 0], bf[j * 4 + 1], bf[j * 4 + 2], bf[j * 4 + 3],
                          Bb + (uint32_t)(n * 80) + colB);
                }
#pragma unroll
                for (int mi = 0; mi < 4; mi++) {
                    uint32_t a0, a1, a2, a3;
                    int m = wm + mi * 16 + (lane & 15);
                    ldsm4(a0, a1, a2, a3, Ab + (uint32_t)(m * 80) + colA);
#pragma unroll
                    for (int j = 0; j < 2; j++) {
                        mma16816(acc[mi][2 * j],     a0, a1, a2, a3, bf[j * 4 + 0], bf[j * 4 + 1]);
                        mma16816(acc[mi][2 * j + 1], a0, a1, a2, a3, bf[j * 4 + 2], bf[j * 4 + 3]);
                    }
                }
            }
        }
        __syncthreads();
    }

#pragma unroll
    for (int mi = 0; mi < 4; mi++) {
#pragma unroll
        for (int ni = 0; ni < 4; ni++) {
            int r  = wm + mi * 16 + (lane >> 2);
            int cc = wn + ni * 8 + (lane & 3) * 2;
#pragma unroll
            for (int half = 0; half < 2; half++) {
                int row = m0 + r + half * 8;
                int col = n0 + cc;
                float v0 = acc[mi][ni][half * 2 + 0];
                float v1 = acc[mi][ni][half * 2 + 1];
                if (OUTM == 2) {
                    bf16 h0, l0, h1, l1;
                    split1(v0, h0, l0); split1(v1, h1, l1);
                    uint32_t ph = ((uint32_t)*(uint16_t*)&h1 << 16) | *(uint16_t*)&h0;
                    uint32_t pl = ((uint32_t)*(uint16_t*)&l1 << 16) | *(uint16_t*)&l0;
                    *reinterpret_cast<uint32_t*>(Chi + (long long)row * DD + col) = ph;
                    *reinterpret_cast<uint32_t*>(Clo + (long long)row * DD + col) = pl;
                } else {
                    if (OUTM == 1) {
                        float2 r2 = *reinterpret_cast<const float2*>(R + (long long)row * DD + col);
                        v0 += r2.x; v1 += r2.y;
                    }
                    float2 o; o.x = v0; o.y = v1;
                    *reinterpret_cast<float2*>(Cf + (long long)row * DD + col) = o;
                }
            }
        }
    }
}

// ---------------------------------------------------------------------------
// Fused attention: per CTA = 128-row attn stripe of one (b,h).
// Pass 1: S = K@Q^T (3-prod bf16), exp, in-register rowsum (no stores).
// Pass 2: recompute S (bitwise identical), normalize, store attn (fp32,
// normalized, ONCE), convert P fragments -> fp16 A operands, feat += P@V
// (fp16), emit feat as bf16 hi/lo.
// 8 warps, each owns m16 x all-4096-n. Q (and V in pass 2) double-buffered.
// ---------------------------------------------------------------------------
#define FU_SMEM 145408
#define FU_KHI 0u
#define FU_KLO 18432u
#define FU_Q0  36864u
#define FU_QST 36864u
#define FU_V0  110592u
#define FU_VST 17408u

__global__ void __launch_bounds__(256)
fused_attn(const bf16* __restrict__ Khi, const bf16* __restrict__ Klo,
           const bf16* __restrict__ Qhi, const bf16* __restrict__ Qlo,
           const __half* __restrict__ Vh,
           float* __restrict__ S, bf16* __restrict__ Fhi, bf16* __restrict__ Flo)
{
    extern __shared__ char smem[];
    const int tid = threadIdx.x;
    const int wid = tid >> 5;
    const int lane = tid & 31;
    const uint32_t sb = smem_u32(smem);

    const int m0 = blockIdx.x * 128;
    const int bh = blockIdx.y;
    const int b = bh >> 3, h = bh & 7;
    const long long arow = (long long)(b * NN_ + m0);
    const int coff = h * DK;
    const long long vrow = (long long)bh * DK;

    // resident K tile (hi/lo), 144B pitch
    for (int i = tid; i < 2048; i += 256) {
        int t = i >> 10, r = (i & 1023) >> 3, c = i & 7;
        const bf16* src = (t ? Klo : Khi) + (arow + r) * DD + coff + c * 8;
        CP16(sb + (uint32_t)t * 18432u + (uint32_t)(r * 144 + c * 16), (const char*)src);
    }

    auto load_Q = [&](int nb, int s) {
        const long long brow = (long long)b * NN_ + (long long)nb * 128;
        const uint32_t st = sb + FU_Q0 + (uint32_t)s * FU_QST;
        for (int i = tid; i < 2048; i += 256) {
            int t = i >> 10, r = (i & 1023) >> 3, c = i & 7;
            const bf16* src = (t ? Qlo : Qhi) + (brow + r) * DD + coff + c * 8;
            CP16(st + (uint32_t)t * 18432u + (uint32_t)(r * 144 + c * 16), (const char*)src);
        }
    };
    auto load_V = [&](int nb, int s) {
        const uint32_t st = sb + FU_V0 + (uint32_t)s * FU_VST;
        for (int i = tid; i < 1024; i += 256) {
            int r = i >> 4, c = i & 15;
            CP16(st + (uint32_t)(r * 272 + c * 16),
                 (const char*)(Vh + (vrow + r) * NN_ + nb * 128 + c * 8));
        }
    };

    const int gid = lane >> 2, tig = lane & 3;
    const long long cbase = (long long)bh * NN_ * NN_;
    const int mrow = m0 + wid * 16 + gid;

    float rs0 = 0.0f, rs1 = 0.0f, inv0 = 0.0f, inv1 = 0.0f;
    float facc[8][4];
#pragma unroll
    for (int i = 0; i < 8; i++)
#pragma unroll
        for (int c = 0; c < 4; c++) facc[i][c] = 0.0f;

#pragma unroll
    for (int pass = 0; pass < 2; pass++) {
        load_Q(0, 0);
        if (pass) load_V(0, 0);
        CP_COMMIT();

        for (int nb = 0; nb < 32; nb++) {
            if (nb < 31) {
                load_Q(nb + 1, (nb + 1) & 1);
                if (pass) load_V(nb + 1, (nb + 1) & 1);
                CP_COMMIT(); CP_WAIT1();
            } else { CP_WAIT0(); }
            __syncthreads();

            const uint32_t Qst = sb + FU_Q0 + (uint32_t)(nb & 1) * FU_QST;
            const uint32_t Vst = sb + FU_V0 + (uint32_t)(nb & 1) * FU_VST;

#pragma unroll
            for (int half = 0; half < 2; half++) {
                float sacc[8][4];
#pragma unroll
                for (int i = 0; i < 8; i++)
#pragma unroll
                    for (int c = 0; c < 4; c++) sacc[i][c] = 0.0f;

#pragma unroll
                for (int prod = 0; prod < 3; prod++) {
                    const uint32_t Ab = sb + ((prod == 1) ? FU_KLO : FU_KHI);
                    const uint32_t Qb = Qst + ((prod == 2) ? 18432u : 0u);
#pragma unroll
                    for (int kc = 0; kc < 4; kc++) {
                        const uint32_t colA = (uint32_t)(kc * 32 + ((lane >> 4) & 1) * 16);
                        const uint32_t colB = (uint32_t)(kc * 32 + ((lane >> 3) & 1) * 16);
                        uint32_t a0, a1, a2, a3;
                        ldsm4(a0, a1, a2, a3,
                              Ab + (uint32_t)((wid * 16 + (lane & 15)) * 144) + colA);
#pragma unroll
                        for (int j = 0; j < 4; j++) {
                            int n = half * 64 + j * 16 + ((lane >> 4) & 1) * 8 + (lane & 7);
                            uint32_t q0, q1, q2, q3;
                            ldsm4(q0, q1, q2, q3, Qb + (uint32_t)(n * 144) + colB);
                            mma16816(sacc[2 * j],     a0, a1, a2, a3, q0, q1);
                            mma16816(sacc[2 * j + 1], a0, a1, a2, a3, q2, q3);
                        }
                    }
                }

                if (pass == 0) {
#pragma unroll
                    for (int j = 0; j < 8; j++) {
                        rs0 += __expf(0.125f * sacc[j][0]) + __expf(0.125f * sacc[j][1]);
                        rs1 += __expf(0.125f * sacc[j][2]) + __expf(0.125f * sacc[j][3]);
                    }
                } else {
#pragma unroll
                    for (int kch = 0; kch < 4; kch++) {
                        uint32_t a0, a1, a2, a3;
#pragma unroll
                        for (int jj = 0; jj < 2; jj++) {
                            int j = 2 * kch + jj;
                            float p0 = __expf(0.125f * sacc[j][0]) * inv0;
                            float p1 = __expf(0.125f * sacc[j][1]) * inv0;
                            float p2 = __expf(0.125f * sacc[j][2]) * inv1;
                            float p3 = __expf(0.125f * sacc[j][3]) * inv1;
                            long long colg = (long long)nb * 128 + half * 64 + j * 8 + tig * 2;
                            float2 o0; o0.x = p0; o0.y = p1;
                            float2 o1; o1.x = p2; o1.y = p3;
                            *reinterpret_cast<float2*>(S + cbase + (long long)mrow * NN_ + colg) = o0;
                            *reinterpret_cast<float2*>(S + cbase + (long long)(mrow + 8) * NN_ + colg) = o1;
                            __half2 h01 = __floats2half2_rn(p0, p1);
                            __half2 h23 = __floats2half2_rn(p2, p3);
                            if (jj == 0) { a0 = *reinterpret_cast<uint32_t*>(&h01);
                                           a1 = *reinterpret_cast<uint32_t*>(&h23); }
                            else         { a2 = *reinterpret_cast<uint32_t*>(&h01);
                                           a3 = *reinterpret_cast<uint32_t*>(&h23); }
                        }
                        const uint32_t colV = (uint32_t)(half * 128 + kch * 32 + ((lane >> 3) & 1) * 16);
#pragma unroll
                        for (int vj = 0; vj < 4; vj++) {
                            int n = vj * 16 + ((lane >> 4) & 1) * 8 + (lane & 7);
                            uint32_t v0, v1, v2, v3;
                            ldsm4(v0, v1, v2, v3, Vst + (uint32_t)(n * 272) + colV);
                            mma16816h(facc[2 * vj],     a0, a1, a2, a3, v0, v1);
                            mma16816h(facc[2 * vj + 1], a0, a1, a2, a3, v2, v3);
                        }
                    }
                }
            }
            __syncthreads();
        }

        if (pass == 0) {
            rs0 += __shfl_xor_sync(~0u, rs0, 1);
            rs0 += __shfl_xor_sync(~0u, rs0, 2);
            rs1 += __shfl_xor_sync(~0u, rs1, 1);
            rs1 += __shfl_xor_sync(~0u, rs1, 2);
            inv0 = __frcp_rn(rs0);
            inv1 = __frcp_rn(rs1);
        }
    }

    // feat epilogue: bf16 hi/lo
#pragma unroll
    for (int n8 = 0; n8 < 8; n8++) {
        int col = h * DK + n8 * 8 + tig * 2;
#pragma unroll
        for (int half = 0; half < 2; half++) {
            long long row = (long long)(b * NN_ + mrow + half * 8);
            float v0 = facc[n8][half * 2 + 0];
            float v1 = facc[n8][half * 2 + 1];
            bf16 h0, l0, h1, l1;
            split1(v0, h0, l0); split1(v1, h1, l1);
            uint32_t ph = ((uint32_t)*(uint16_t*)&h1 << 16) | *(uint16_t*)&h0;
            uint32_t pl = ((uint32_t)*(uint16_t*)&l1 << 16) | *(uint16_t*)&l0;
            *reinterpret_cast<uint32_t*>(Fhi + row * DD + col) = ph;
            *reinterpret_cast<uint32_t*>(Flo + row * DD + col) = pl;
        }
    }
}

// ---------------------------------------------------------------------------
// In-place row LayerNorm
// ---------------------------------------------------------------------------
__global__ void layernorm_rows(float* __restrict__ y,
                               const float* __restrict__ gamma,
                               const float* __restrict__ beta)
{
    const long long base = (long long)blockIdx.x * DD;
    const int t = threadIdx.x;
    const int lane = t & 31, warp = t >> 5;
    __shared__ float red[32];

    float x0 = y[base + t];
    float x1 = y[base + t + 256];

    float s = x0 + x1;
#pragma unroll
    for (int o = 16; o > 0; o >>= 1) s += __shfl_xor_sync(~0u, s, o);
    if (lane == 0) red[warp] = s;
    __syncthreads();
    if (warp == 0) {
        float x = (lane < 8) ? red[lane] : 0.0f;
#pragma unroll
        for (int o = 16; o > 0; o >>= 1) x += __shfl_xor_sync(~0u, x, o);
        if (lane == 0) red[0] = x;
    }
    __syncthreads();
    const float mu = red[0] * (1.0f / DD);
    __syncthreads();

    const float d0 = x0 - mu, d1 = x1 - mu;
    float v = d0 * d0 + d1 * d1;
#pragma unroll
    for (int o = 16; o > 0; o >>= 1) v += __shfl_xor_sync(~0u, v, o);
    if (lane == 0) red[warp] = v;
    __syncthreads();
    if (warp == 0) {
        float x = (lane < 8) ? red[lane] : 0.0f;
#pragma unroll
        for (int o = 16; o > 0; o >>= 1) x += __shfl_xor_sync(~0u, x, o);
        if (lane == 0) red[0] = x;
    }
    __syncthreads();
    const float r = rsqrtf(red[0] * (1.0f / DD) + 1e-5f);

    y[base + t]       = d0 * r * gamma[t]       + beta[t];
    y[base + t + 256] = d1 * r * gamma[t + 256] + beta[t + 256];
}

// ---------------------------------------------------------------------------
extern "C" void kernel_launch(void* const* d_in, const int* in_sizes, int n_in,
                              void* d_out, int out_size)
{
    const float* q    = (const float*)d_in[0];
    const float* k    = (const float*)d_in[1];
    const float* v    = (const float*)d_in[2];
    const float* w_q  = (const float*)d_in[3];
    const float* w_k  = (const float*)d_in[4];
    const float* w_v  = (const float*)d_in[5];
    const float* w_fc = (const float*)d_in[6];
    const float* gam  = (const float*)d_in[7];
    const float* bet  = (const float*)d_in[8];

    float* out  = (float*)d_out;                          // [B,N,D]
    float* attn = out + (long long)BB * NN_ * DD;         // [B,H,N,N]

    float* vp;
    cudaGetSymbolAddress((void**)&vp, g_vp);
    bf16 *xqh, *xql, *xkh, *xkl, *xvh, *xvl;
    bf16 *wqh, *wql, *wkh, *wkl, *wvh, *wvl, *wfh, *wfl;
    bf16 *qph, *qpl, *kph, *kpl, *fth, *ftl;
    __half* vth;
    cudaGetSymbolAddress((void**)&xqh, g_xq_hi); cudaGetSymbolAddress((void**)&xql, g_xq_lo);
    cudaGetSymbolAddress((void**)&xkh, g_xk_hi); cudaGetSymbolAddress((void**)&xkl, g_xk_lo);
    cudaGetSymbolAddress((void**)&xvh, g_xv_hi); cudaGetSymbolAddress((void**)&xvl, g_xv_lo);
    cudaGetSymbolAddress((void**)&wqh, g_wq_hi); cudaGetSymbolAddress((void**)&wql, g_wq_lo);
    cudaGetSymbolAddress((void**)&wkh, g_wk_hi); cudaGetSymbolAddress((void**)&wkl, g_wk_lo);
    cudaGetSymbolAddress((void**)&wvh, g_wv_hi); cudaGetSymbolAddress((void**)&wvl, g_wv_lo);
    cudaGetSymbolAddress((void**)&wfh, g_wf_hi); cudaGetSymbolAddress((void**)&wfl, g_wf_lo);
    cudaGetSymbolAddress((void**)&qph, g_qp_hi); cudaGetSymbolAddress((void**)&qpl, g_qp_lo);
    cudaGetSymbolAddress((void**)&kph, g_kp_hi); cudaGetSymbolAddress((void**)&kpl, g_kp_lo);
    cudaGetSymbolAddress((void**)&vth, g_vpt_h);
    cudaGetSymbolAddress((void**)&fth, g_ft_hi); cudaGetSymbolAddress((void**)&ftl, g_ft_lo);

    cudaFuncSetAttribute(mma_gemm<0>, cudaFuncAttributeMaxDynamicSharedMemorySize, GM_SMEM);
    cudaFuncSetAttribute(mma_gemm<1>, cudaFuncAttributeMaxDynamicSharedMemorySize, GM_SMEM);
    cudaFuncSetAttribute(mma_gemm<2>, cudaFuncAttributeMaxDynamicSharedMemorySize, GM_SMEM);
    cudaFuncSetAttribute(fused_attn, cudaFuncAttributeMaxDynamicSharedMemorySize, FU_SMEM);

    const int M = BB * NN_;          // 8192
    const int n4i = M * DD / 4;
    const int n4w = DD * DD / 4;

    // 1) splits of inputs + weights
    split_k<<<(n4i + 255) / 256, 256>>>(q, xqh, xql, n4i);
    split_k<<<(n4i + 255) / 256, 256>>>(k, xkh, xkl, n4i);
    split_k<<<(n4i + 255) / 256, 256>>>(v, xvh, xvl, n4i);
    split_k<<<(n4w + 255) / 256, 256>>>(w_q, wqh, wql, n4w);
    split_k<<<(n4w + 255) / 256, 256>>>(w_k, wkh, wkl, n4w);
    split_k<<<(n4w + 255) / 256, 256>>>(w_v, wvh, wvl, n4w);
    split_k<<<(n4w + 255) / 256, 256>>>(w_fc, wfh, wfl, n4w);

    // 2) projections on tensor cores
    {
        dim3 grid(DD / 128, M / 128);
        mma_gemm<2><<<grid, 256, GM_SMEM>>>(xqh, xql, wqh, wql, nullptr, qph, qpl, nullptr);
        mma_gemm<2><<<grid, 256, GM_SMEM>>>(xkh, xkl, wkh, wkl, nullptr, kph, kpl, nullptr);
        mma_gemm<0><<<grid, 256, GM_SMEM>>>(xvh, xvl, wvh, wvl, vp, nullptr, nullptr, nullptr);
    }
    vtrans_f16<<<dim3(NN_ / 32, DD / 32, BB), dim3(32, 8)>>>(vp, vth);

    // 3) fused attention: normalized attn (single write) + feat hi/lo
    fused_attn<<<dim3(NN_ / 128, BB * HH), 256, FU_SMEM>>>(
        kph, kpl, qph, qpl, vth, attn, fth, ftl);

    // 4) fc + residual on tensor cores
    {
        dim3 grid(DD / 128, M / 128);
        mma_gemm<1><<<grid, 256, GM_SMEM>>>(fth, ftl, wfh, wfl, out, nullptr, nullptr, q);
    }

    // 5) LayerNorm
    layernorm_rows<<<M, 256>>>(out, gam, bet);
}

// round 8
// speedup vs baseline: 2.9156x; 1.1237x over previous
#include <cuda_runtime.h>
#include <cuda_bf16.h>
#include <cuda_fp16.h>
#include <math.h>
#include <stdint.h>

#define BB 2
#define NN_ 4096
#define DD 512
#define HH 8
#define DK 64

typedef __nv_bfloat16 bf16;

// ---------------------------------------------------------------------------
// Scratch (device globals — no allocation allowed)
// ---------------------------------------------------------------------------
__device__ float g_vp[BB * NN_ * DD];
__device__ float g_rowsum[BB * HH * NN_];
__device__ __half g_e[(size_t)BB * HH * NN_ * NN_];      // unnormalized exp, fp16

__device__ bf16 g_xq_hi[BB * NN_ * DD]; __device__ bf16 g_xq_lo[BB * NN_ * DD];
__device__ bf16 g_xk_hi[BB * NN_ * DD]; __device__ bf16 g_xk_lo[BB * NN_ * DD];
__device__ bf16 g_xv_hi[BB * NN_ * DD]; __device__ bf16 g_xv_lo[BB * NN_ * DD];
__device__ bf16 g_wq_hi[DD * DD]; __device__ bf16 g_wq_lo[DD * DD];
__device__ bf16 g_wk_hi[DD * DD]; __device__ bf16 g_wk_lo[DD * DD];
__device__ bf16 g_wv_hi[DD * DD]; __device__ bf16 g_wv_lo[DD * DD];
__device__ bf16 g_wf_hi[DD * DD]; __device__ bf16 g_wf_lo[DD * DD];
__device__ bf16 g_qp_hi[BB * NN_ * DD]; __device__ bf16 g_qp_lo[BB * NN_ * DD];
__device__ bf16 g_kp_hi[BB * NN_ * DD]; __device__ bf16 g_kp_lo[BB * NN_ * DD];
__device__ __half g_vpt_h[BB * HH * DK * NN_];           // [bh, d, token] fp16
__device__ bf16 g_ft_hi[BB * NN_ * DD]; __device__ bf16 g_ft_lo[BB * NN_ * DD];

// ---------------------------------------------------------------------------
// PTX helpers (arch-portable: cp.async / ldmatrix / mma.sync only)
// ---------------------------------------------------------------------------
__device__ __forceinline__ uint32_t smem_u32(const void* p) {
    uint32_t a;
    asm("{ .reg .u64 t; cvta.to.shared.u64 t, %1; cvt.u32.u64 %0, t; }"
        : "=r"(a) : "l"(p));
    return a;
}

#define CP16(dst, src) \
    asm volatile("cp.async.cg.shared.global [%0], [%1], 16;" :: "r"(dst), "l"(src))
#define CP_COMMIT() asm volatile("cp.async.commit_group;" ::: "memory")
#define CP_WAIT0()  asm volatile("cp.async.wait_group 0;" ::: "memory")
#define CP_WAIT1()  asm volatile("cp.async.wait_group 1;" ::: "memory")
#define CP_WAIT2()  asm volatile("cp.async.wait_group 2;" ::: "memory")

__device__ __forceinline__ void ldsm4(uint32_t& r0, uint32_t& r1, uint32_t& r2, uint32_t& r3,
                                      uint32_t addr) {
    asm volatile("ldmatrix.sync.aligned.m8n8.x4.shared.b16 {%0,%1,%2,%3}, [%4];"
                 : "=r"(r0), "=r"(r1), "=r"(r2), "=r"(r3) : "r"(addr));
}

__device__ __forceinline__ void mma16816(float* c,
                                         uint32_t a0, uint32_t a1, uint32_t a2, uint32_t a3,
                                         uint32_t b0, uint32_t b1) {
    asm volatile(
        "mma.sync.aligned.m16n8k16.row.col.f32.bf16.bf16.f32 "
        "{%0,%1,%2,%3}, {%4,%5,%6,%7}, {%8,%9}, {%0,%1,%2,%3};"
        : "+f"(c[0]), "+f"(c[1]), "+f"(c[2]), "+f"(c[3])
        : "r"(a0), "r"(a1), "r"(a2), "r"(a3), "r"(b0), "r"(b1));
}

__device__ __forceinline__ void mma16816h(float* c,
                                          uint32_t a0, uint32_t a1, uint32_t a2, uint32_t a3,
                                          uint32_t b0, uint32_t b1) {
    asm volatile(
        "mma.sync.aligned.m16n8k16.row.col.f32.f16.f16.f32 "
        "{%0,%1,%2,%3}, {%4,%5,%6,%7}, {%8,%9}, {%0,%1,%2,%3};"
        : "+f"(c[0]), "+f"(c[1]), "+f"(c[2]), "+f"(c[3])
        : "r"(a0), "r"(a1), "r"(a2), "r"(a3), "r"(b0), "r"(b1));
}

__device__ __forceinline__ void split1(float x, bf16& h, bf16& l) {
    h = __float2bfloat16(x);
    l = __float2bfloat16(x - __bfloat162float(h));
}

__device__ __forceinline__ void split_body(const float* __restrict__ x,
                                           bf16* __restrict__ hi,
                                           bf16* __restrict__ lo, int i) {
    float4 v = reinterpret_cast<const float4*>(x)[i];
    bf16 h[4], l[4];
    split1(v.x, h[0], l[0]); split1(v.y, h[1], l[1]);
    split1(v.z, h[2], l[2]); split1(v.w, h[3], l[3]);
    uint2 ph, pl;
    ph.x = ((uint32_t)*(uint16_t*)&h[1] << 16) | *(uint16_t*)&h[0];
    ph.y = ((uint32_t)*(uint16_t*)&h[3] << 16) | *(uint16_t*)&h[2];
    pl.x = ((uint32_t)*(uint16_t*)&l[1] << 16) | *(uint16_t*)&l[0];
    pl.y = ((uint32_t)*(uint16_t*)&l[3] << 16) | *(uint16_t*)&l[2];
    reinterpret_cast<uint2*>(hi)[i] = ph;
    reinterpret_cast<uint2*>(lo)[i] = pl;
}

// merged splits: 3 input tensors / 4 weight tensors in one launch each
__global__ void split3(const float* x0, const float* x1, const float* x2,
                       bf16* h0, bf16* h1, bf16* h2,
                       bf16* l0, bf16* l1, bf16* l2, int n4)
{
    int i = blockIdx.x * blockDim.x + threadIdx.x;
    if (i >= n4) return;
    int w = blockIdx.y;
    const float* x = (w == 0) ? x0 : (w == 1) ? x1 : x2;
    bf16* hi = (w == 0) ? h0 : (w == 1) ? h1 : h2;
    bf16* lo = (w == 0) ? l0 : (w == 1) ? l1 : l2;
    split_body(x, hi, lo, i);
}

__global__ void split4(const float* x0, const float* x1, const float* x2, const float* x3,
                       bf16* h0, bf16* h1, bf16* h2, bf16* h3,
                       bf16* l0, bf16* l1, bf16* l2, bf16* l3, int n4)
{
    int i = blockIdx.x * blockDim.x + threadIdx.x;
    if (i >= n4) return;
    int w = blockIdx.y;
    const float* x = (w == 0) ? x0 : (w == 1) ? x1 : (w == 2) ? x2 : x3;
    bf16* hi = (w == 0) ? h0 : (w == 1) ? h1 : (w == 2) ? h2 : h3;
    bf16* lo = (w == 0) ? l0 : (w == 1) ? l1 : (w == 2) ? l2 : l3;
    split_body(x, hi, lo, i);
}

// vp [B, N, D] fp32 -> vpT fp16 [B*H, DK, N]
__global__ void vtrans_f16(const float* __restrict__ vp, __half* __restrict__ vt)
{
    __shared__ float tile[32][33];
    const int j0 = blockIdx.x * 32;
    const int c0 = blockIdx.y * 32;
    const int b  = blockIdx.z;
    const int tx = threadIdx.x, ty = threadIdx.y;
    for (int rr = ty; rr < 32; rr += 8)
        tile[rr][tx] = vp[((long long)(b * NN_ + j0 + rr)) * DD + c0 + tx];
    __syncthreads();
    for (int rr = ty; rr < 32; rr += 8) {
        int c = c0 + rr;
        int h = c >> 6, dl = c & 63;
        long long idx = ((long long)(b * HH + h) * DK + dl) * NN_ + j0 + tx;
        vt[idx] = __float2half_rn(tile[tx][rr]);
    }
}

// ---------------------------------------------------------------------------
// Tensor-core GEMM (NT): C[M,512] = A[M,512] @ W[512,512]^T  via hi/lo split.
// BM=BN=128, BK=32, 3-stage cp.async pipeline. 8 warps (2M x 4N).
// OUTM: 0 = fp32 out; 1 = fp32 out + residual; 2 = bf16 hi/lo out.
// ---------------------------------------------------------------------------
#define GM_SMEM 122880
#define GM_STG  40960u

template<int OUTM>
__global__ void __launch_bounds__(256)
mma_gemm(const bf16* __restrict__ Ahi, const bf16* __restrict__ Alo,
         const bf16* __restrict__ Bhi, const bf16* __restrict__ Blo,
         float* __restrict__ Cf, bf16* __restrict__ Chi, bf16* __restrict__ Clo,
         const float* __restrict__ R)
{
    extern __shared__ char smem[];
    const int tid = threadIdx.x;
    const int wid = tid >> 5;
    const int lane = tid & 31;
    const uint32_t sb = smem_u32(smem);
    const int n0 = blockIdx.x * 128;
    const int m0 = blockIdx.y * 128;

    const int wm = (wid >> 2) * 64;
    const int wn = (wid & 3) * 32;

    float acc[4][4][4];
#pragma unroll
    for (int i = 0; i < 4; i++)
#pragma unroll
        for (int j = 0; j < 4; j++)
#pragma unroll
            for (int c = 0; c < 4; c++) acc[i][j][c] = 0.0f;

    auto load_stage = [&](int kt, int s) {
        const int k0 = kt * 32;
        const uint32_t st = sb + (uint32_t)s * GM_STG;
        for (int i = tid; i < 2048; i += 256) {
            int t = i >> 9, r = (i & 511) >> 2, c = i & 3;
            const bf16* src;
            if (t == 0)      src = Ahi + (long long)(m0 + r) * DD + k0 + c * 8;
            else if (t == 1) src = Alo + (long long)(m0 + r) * DD + k0 + c * 8;
            else if (t == 2) src = Bhi + (long long)(n0 + r) * DD + k0 + c * 8;
            else             src = Blo + (long long)(n0 + r) * DD + k0 + c * 8;
            CP16(st + (uint32_t)t * 10240u + (uint32_t)(r * 80 + c * 16), (const char*)src);
        }
    };

    load_stage(0, 0); CP_COMMIT();
    load_stage(1, 1); CP_COMMIT();

    for (int kt = 0; kt < 16; kt++) {
        if (kt + 2 < 16) { load_stage(kt + 2, (kt + 2) % 3); CP_COMMIT(); CP_WAIT2(); }
        else if (kt + 1 < 16) { CP_WAIT1(); }
        else { CP_WAIT0(); }
        __syncthreads();
        const uint32_t st = sb + (uint32_t)(kt % 3) * GM_STG;
#pragma unroll
        for (int prod = 0; prod < 3; prod++) {
            const uint32_t Ab = st + ((prod == 1) ? 10240u : 0u);
            const uint32_t Bb = st + 20480u + ((prod == 2) ? 10240u : 0u);
#pragma unroll
            for (int kc = 0; kc < 2; kc++) {
                const uint32_t colA = (uint32_t)(kc * 32 + ((lane >> 4) & 1) * 16);
                const uint32_t colB = (uint32_t)(kc * 32 + ((lane >> 3) & 1) * 16);
                uint32_t bf[8];
#pragma unroll
                for (int j = 0; j < 2; j++) {
                    int n = wn + j * 16 + ((lane >> 4) & 1) * 8 + (lane & 7);
                    ldsm4(bf[j * 4 + 0], bf[j * 4 + 1], bf[j * 4 + 2], bf[j * 4 + 3],
                          Bb + (uint32_t)(n * 80) + colB);
                }
#pragma unroll
                for (int mi = 0; mi < 4; mi++) {
                    uint32_t a0, a1, a2, a3;
                    int m = wm + mi * 16 + (lane & 15);
                    ldsm4(a0, a1, a2, a3, Ab + (uint32_t)(m * 80) + colA);
#pragma unroll
                    for (int j = 0; j < 2; j++) {
                        mma16816(acc[mi][2 * j],     a0, a1, a2, a3, bf[j * 4 + 0], bf[j * 4 + 1]);
                        mma16816(acc[mi][2 * j + 1], a0, a1, a2, a3, bf[j * 4 + 2], bf[j * 4 + 3]);
                    }
                }
            }
        }
        __syncthreads();
    }

#pragma unroll
    for (int mi = 0; mi < 4; mi++) {
#pragma unroll
        for (int ni = 0; ni < 4; ni++) {
            int r  = wm + mi * 16 + (lane >> 2);
            int cc = wn + ni * 8 + (lane & 3) * 2;
#pragma unroll
            for (int half = 0; half < 2; half++) {
                int row = m0 + r + half * 8;
                int col = n0 + cc;
                float v0 = acc[mi][ni][half * 2 + 0];
                float v1 = acc[mi][ni][half * 2 + 1];
                if (OUTM == 2) {
                    bf16 h0, l0, h1, l1;
                    split1(v0, h0, l0); split1(v1, h1, l1);
                    uint32_t ph = ((uint32_t)*(uint16_t*)&h1 << 16) | *(uint16_t*)&h0;
                    uint32_t pl = ((uint32_t)*(uint16_t*)&l1 << 16) | *(uint16_t*)&l0;
                    *reinterpret_cast<uint32_t*>(Chi + (long long)row * DD + col) = ph;
                    *reinterpret_cast<uint32_t*>(Clo + (long long)row * DD + col) = pl;
                } else {
                    if (OUTM == 1) {
                        float2 r2 = *reinterpret_cast<const float2*>(R + (long long)row * DD + col);
                        v0 += r2.x; v1 += r2.y;
                    }
                    float2 o; o.x = v0; o.y = v1;
                    *reinterpret_cast<float2*>(Cf + (long long)row * DD + col) = o;
                }
            }
        }
    }
}

// ---------------------------------------------------------------------------
// Fused attention, SINGLE pass: per CTA = 128-row attn stripe of one (b,h).
// S = K@Q^T (3-prod bf16); e = exp(0.125 S) -> fp16, stored to scratch E
// (unnormalized) AND used as A operand for feat += e@V (fp16 MMA).
// Rowsums accumulate in registers; feat scaled by 1/rowsum in epilogue.
// ---------------------------------------------------------------------------
#define FU_SMEM 145408
#define FU_KHI 0u
#define FU_KLO 18432u
#define FU_Q0  36864u
#define FU_QST 36864u
#define FU_V0  110592u
#define FU_VST 17408u

__global__ void __launch_bounds__(256)
fused_attn(const bf16* __restrict__ Khi, const bf16* __restrict__ Klo,
           const bf16* __restrict__ Qhi, const bf16* __restrict__ Qlo,
           const __half* __restrict__ Vh,
           __half* __restrict__ E, float* __restrict__ rowsum,
           bf16* __restrict__ Fhi, bf16* __restrict__ Flo)
{
    extern __shared__ char smem[];
    const int tid = threadIdx.x;
    const int wid = tid >> 5;
    const int lane = tid & 31;
    const uint32_t sb = smem_u32(smem);

    const int m0 = blockIdx.x * 128;
    const int bh = blockIdx.y;
    const int b = bh >> 3, h = bh & 7;
    const long long arow = (long long)(b * NN_ + m0);
    const int coff = h * DK;
    const long long vrow = (long long)bh * DK;

    // resident K tile (hi/lo), 144B pitch
    for (int i = tid; i < 2048; i += 256) {
        int t = i >> 10, r = (i & 1023) >> 3, c = i & 7;
        const bf16* src = (t ? Klo : Khi) + (arow + r) * DD + coff + c * 8;
        CP16(sb + (uint32_t)t * 18432u + (uint32_t)(r * 144 + c * 16), (const char*)src);
    }

    auto load_Q = [&](int nb, int s) {
        const long long brow = (long long)b * NN_ + (long long)nb * 128;
        const uint32_t st = sb + FU_Q0 + (uint32_t)s * FU_QST;
        for (int i = tid; i < 2048; i += 256) {
            int t = i >> 10, r = (i & 1023) >> 3, c = i & 7;
            const bf16* src = (t ? Qlo : Qhi) + (brow + r) * DD + coff + c * 8;
            CP16(st + (uint32_t)t * 18432u + (uint32_t)(r * 144 + c * 16), (const char*)src);
        }
    };
    auto load_V = [&](int nb, int s) {
        const uint32_t st = sb + FU_V0 + (uint32_t)s * FU_VST;
        for (int i = tid; i < 1024; i += 256) {
            int r = i >> 4, c = i & 15;
            CP16(st + (uint32_t)(r * 272 + c * 16),
                 (const char*)(Vh + (vrow + r) * NN_ + nb * 128 + c * 8));
        }
    };

    const int gid = lane >> 2, tig = lane & 3;
    const long long ebase = (long long)bh * NN_ * NN_;
    const int mrow = m0 + wid * 16 + gid;

    float rs0 = 0.0f, rs1 = 0.0f;
    float facc[8][4];
#pragma unroll
    for (int i = 0; i < 8; i++)
#pragma unroll
        for (int c = 0; c < 4; c++) facc[i][c] = 0.0f;

    load_Q(0, 0); load_V(0, 0); CP_COMMIT();

    for (int nb = 0; nb < 32; nb++) {
        if (nb < 31) {
            load_Q(nb + 1, (nb + 1) & 1);
            load_V(nb + 1, (nb + 1) & 1);
            CP_COMMIT(); CP_WAIT1();
        } else { CP_WAIT0(); }
        __syncthreads();

        const uint32_t Qst = sb + FU_Q0 + (uint32_t)(nb & 1) * FU_QST;
        const uint32_t Vst = sb + FU_V0 + (uint32_t)(nb & 1) * FU_VST;

#pragma unroll
        for (int half = 0; half < 2; half++) {
            float sacc[8][4];
#pragma unroll
            for (int i = 0; i < 8; i++)
#pragma unroll
                for (int c = 0; c < 4; c++) sacc[i][c] = 0.0f;

#pragma unroll
            for (int prod = 0; prod < 3; prod++) {
                const uint32_t Ab = sb + ((prod == 1) ? FU_KLO : FU_KHI);
                const uint32_t Qb = Qst + ((prod == 2) ? 18432u : 0u);
#pragma unroll
                for (int kc = 0; kc < 4; kc++) {
                    const uint32_t colA = (uint32_t)(kc * 32 + ((lane >> 4) & 1) * 16);
                    const uint32_t colB = (uint32_t)(kc * 32 + ((lane >> 3) & 1) * 16);
                    uint32_t a0, a1, a2, a3;
                    ldsm4(a0, a1, a2, a3,
                          Ab + (uint32_t)((wid * 16 + (lane & 15)) * 144) + colA);
#pragma unroll
                    for (int j = 0; j < 4; j++) {
                        int n = half * 64 + j * 16 + ((lane >> 4) & 1) * 8 + (lane & 7);
                        uint32_t q0, q1, q2, q3;
                        ldsm4(q0, q1, q2, q3, Qb + (uint32_t)(n * 144) + colB);
                        mma16816(sacc[2 * j],     a0, a1, a2, a3, q0, q1);
                        mma16816(sacc[2 * j + 1], a0, a1, a2, a3, q2, q3);
                    }
                }
            }

            // exp -> fp16 (store to E AND feed P@V), rowsum in registers
#pragma unroll
            for (int kch = 0; kch < 4; kch++) {
                uint32_t a0, a1, a2, a3;
#pragma unroll
                for (int jj = 0; jj < 2; jj++) {
                    int j = 2 * kch + jj;
                    float e0 = __expf(0.125f * sacc[j][0]);
                    float e1 = __expf(0.125f * sacc[j][1]);
                    float e2 = __expf(0.125f * sacc[j][2]);
                    float e3 = __expf(0.125f * sacc[j][3]);
                    rs0 += e0 + e1;
                    rs1 += e2 + e3;
                    __half2 h01 = __floats2half2_rn(e0, e1);
                    __half2 h23 = __floats2half2_rn(e2, e3);
                    long long colg = (long long)nb * 128 + half * 64 + j * 8 + tig * 2;
                    *reinterpret_cast<uint32_t*>(E + ebase + (long long)mrow * NN_ + colg) =
                        *reinterpret_cast<uint32_t*>(&h01);
                    *reinterpret_cast<uint32_t*>(E + ebase + (long long)(mrow + 8) * NN_ + colg) =
                        *reinterpret_cast<uint32_t*>(&h23);
                    if (jj == 0) { a0 = *reinterpret_cast<uint32_t*>(&h01);
                                   a1 = *reinterpret_cast<uint32_t*>(&h23); }
                    else         { a2 = *reinterpret_cast<uint32_t*>(&h01);
                                   a3 = *reinterpret_cast<uint32_t*>(&h23); }
                }
                const uint32_t colV = (uint32_t)(half * 128 + kch * 32 + ((lane >> 3) & 1) * 16);
#pragma unroll
                for (int vj = 0; vj < 4; vj++) {
                    int n = vj * 16 + ((lane >> 4) & 1) * 8 + (lane & 7);
                    uint32_t v0, v1, v2, v3;
                    ldsm4(v0, v1, v2, v3, Vst + (uint32_t)(n * 272) + colV);
                    mma16816h(facc[2 * vj],     a0, a1, a2, a3, v0, v1);
                    mma16816h(facc[2 * vj + 1], a0, a1, a2, a3, v2, v3);
                }
            }
        }
        __syncthreads();
    }

    // rowsum reduce across quad, write to gmem, scale feat
    rs0 += __shfl_xor_sync(~0u, rs0, 1);
    rs0 += __shfl_xor_sync(~0u, rs0, 2);
    rs1 += __shfl_xor_sync(~0u, rs1, 1);
    rs1 += __shfl_xor_sync(~0u, rs1, 2);
    const float inv0 = __frcp_rn(rs0);
    const float inv1 = __frcp_rn(rs1);
    if (tig == 0) {
        rowsum[(long long)bh * NN_ + mrow]     = rs0;
        rowsum[(long long)bh * NN_ + mrow + 8] = rs1;
    }

#pragma unroll
    for (int n8 = 0; n8 < 8; n8++) {
        int col = h * DK + n8 * 8 + tig * 2;
#pragma unroll
        for (int half = 0; half < 2; half++) {
            long long row = (long long)(b * NN_ + mrow + half * 8);
            float inv = half ? inv1 : inv0;
            float v0 = facc[n8][half * 2 + 0] * inv;
            float v1 = facc[n8][half * 2 + 1] * inv;
            bf16 h0, l0, h1, l1;
            split1(v0, h0, l0); split1(v1, h1, l1);
            uint32_t ph = ((uint32_t)*(uint16_t*)&h1 << 16) | *(uint16_t*)&h0;
            uint32_t pl = ((uint32_t)*(uint16_t*)&l1 << 16) | *(uint16_t*)&l0;
            *reinterpret_cast<uint32_t*>(Fhi + row * DD + col) = ph;
            *reinterpret_cast<uint32_t*>(Flo + row * DD + col) = pl;
        }
    }
}

// ---------------------------------------------------------------------------
// attn_norm: attn[row, :] = float(E[row, :]) * rcp(rowsum[row])
// ---------------------------------------------------------------------------
__global__ void __launch_bounds__(256)
attn_norm(const __half* __restrict__ E, const float* __restrict__ rowsum,
          float* __restrict__ A)
{
    const long long row = blockIdx.x;
    const float inv = __frcp_rn(rowsum[row]);
    const uint2* pe = reinterpret_cast<const uint2*>(E + row * (long long)NN_);
    float4* pa = reinterpret_cast<float4*>(A + row * (long long)NN_);
    const int t = threadIdx.x;
#pragma unroll
    for (int i = 0; i < 4; i++) {
        uint2 u = pe[t + i * 256];
        __half2 a = *reinterpret_cast<__half2*>(&u.x);
        __half2 bq = *reinterpret_cast<__half2*>(&u.y);
        float2 fa = __half22float2(a);
        float2 fb = __half22float2(bq);
        float4 o;
        o.x = fa.x * inv; o.y = fa.y * inv;
        o.z = fb.x * inv; o.w = fb.y * inv;
        pa[t + i * 256] = o;
    }
}

// ---------------------------------------------------------------------------
// In-place row LayerNorm
// ---------------------------------------------------------------------------
__global__ void layernorm_rows(float* __restrict__ y,
                               const float* __restrict__ gamma,
                               const float* __restrict__ beta)
{
    const long long base = (long long)blockIdx.x * DD;
    const int t = threadIdx.x;
    const int lane = t & 31, warp = t >> 5;
    __shared__ float red[32];

    float x0 = y[base + t];
    float x1 = y[base + t + 256];

    float s = x0 + x1;
#pragma unroll
    for (int o = 16; o > 0; o >>= 1) s += __shfl_xor_sync(~0u, s, o);
    if (lane == 0) red[warp] = s;
    __syncthreads();
    if (warp == 0) {
        float x = (lane < 8) ? red[lane] : 0.0f;
#pragma unroll
        for (int o = 16; o > 0; o >>= 1) x += __shfl_xor_sync(~0u, x, o);
        if (lane == 0) red[0] = x;
    }
    __syncthreads();
    const float mu = red[0] * (1.0f / DD);
    __syncthreads();

    const float d0 = x0 - mu, d1 = x1 - mu;
    float v = d0 * d0 + d1 * d1;
#pragma unroll
    for (int o = 16; o > 0; o >>= 1) v += __shfl_xor_sync(~0u, v, o);
    if (lane == 0) red[warp] = v;
    __syncthreads();
    if (warp == 0) {
        float x = (lane < 8) ? red[lane] : 0.0f;
#pragma unroll
        for (int o = 16; o > 0; o >>= 1) x += __shfl_xor_sync(~0u, x, o);
        if (lane == 0) red[0] = x;
    }
    __syncthreads();
    const float r = rsqrtf(red[0] * (1.0f / DD) + 1e-5f);

    y[base + t]       = d0 * r * gamma[t]       + beta[t];
    y[base + t + 256] = d1 * r * gamma[t + 256] + beta[t + 256];
}

// ---------------------------------------------------------------------------
extern "C" void kernel_launch(void* const* d_in, const int* in_sizes, int n_in,
                              void* d_out, int out_size)
{
    const float* q    = (const float*)d_in[0];
    const float* k    = (const float*)d_in[1];
    const float* v    = (const float*)d_in[2];
    const float* w_q  = (const float*)d_in[3];
    const float* w_k  = (const float*)d_in[4];
    const float* w_v  = (const float*)d_in[5];
    const float* w_fc = (const float*)d_in[6];
    const float* gam  = (const float*)d_in[7];
    const float* bet  = (const float*)d_in[8];

    float* out  = (float*)d_out;                          // [B,N,D]
    float* attn = out + (long long)BB * NN_ * DD;         // [B,H,N,N]

    float *vp, *rsum;
    __half* eptr;
    cudaGetSymbolAddress((void**)&vp,   g_vp);
    cudaGetSymbolAddress((void**)&rsum, g_rowsum);
    cudaGetSymbolAddress((void**)&eptr, g_e);
    bf16 *xqh, *xql, *xkh, *xkl, *xvh, *xvl;
    bf16 *wqh, *wql, *wkh, *wkl, *wvh, *wvl, *wfh, *wfl;
    bf16 *qph, *qpl, *kph, *kpl, *fth, *ftl;
    __half* vth;
    cudaGetSymbolAddress((void**)&xqh, g_xq_hi); cudaGetSymbolAddress((void**)&xql, g_xq_lo);
    cudaGetSymbolAddress((void**)&xkh, g_xk_hi); cudaGetSymbolAddress((void**)&xkl, g_xk_lo);
    cudaGetSymbolAddress((void**)&xvh, g_xv_hi); cudaGetSymbolAddress((void**)&xvl, g_xv_lo);
    cudaGetSymbolAddress((void**)&wqh, g_wq_hi); cudaGetSymbolAddress((void**)&wql, g_wq_lo);
    cudaGetSymbolAddress((void**)&wkh, g_wk_hi); cudaGetSymbolAddress((void**)&wkl, g_wk_lo);
    cudaGetSymbolAddress((void**)&wvh, g_wv_hi); cudaGetSymbolAddress((void**)&wvl, g_wv_lo);
    cudaGetSymbolAddress((void**)&wfh, g_wf_hi); cudaGetSymbolAddress((void**)&wfl, g_wf_lo);
    cudaGetSymbolAddress((void**)&qph, g_qp_hi); cudaGetSymbolAddress((void**)&qpl, g_qp_lo);
    cudaGetSymbolAddress((void**)&kph, g_kp_hi); cudaGetSymbolAddress((void**)&kpl, g_kp_lo);
    cudaGetSymbolAddress((void**)&vth, g_vpt_h);
    cudaGetSymbolAddress((void**)&fth, g_ft_hi); cudaGetSymbolAddress((void**)&ftl, g_ft_lo);

    cudaFuncSetAttribute(mma_gemm<0>, cudaFuncAttributeMaxDynamicSharedMemorySize, GM_SMEM);
    cudaFuncSetAttribute(mma_gemm<1>, cudaFuncAttributeMaxDynamicSharedMemorySize, GM_SMEM);
    cudaFuncSetAttribute(mma_gemm<2>, cudaFuncAttributeMaxDynamicSharedMemorySize, GM_SMEM);
    cudaFuncSetAttribute(fused_attn, cudaFuncAttributeMaxDynamicSharedMemorySize, FU_SMEM);

    const int M = BB * NN_;          // 8192
    const int n4i = M * DD / 4;
    const int n4w = DD * DD / 4;

    // 1) splits (merged: 1 launch for inputs, 1 for weights)
    split3<<<dim3((n4i + 255) / 256, 3), 256>>>(q, k, v, xqh, xkh, xvh, xql, xkl, xvl, n4i);
    split4<<<dim3((n4w + 255) / 256, 4), 256>>>(w_q, w_k, w_v, w_fc,
                                                wqh, wkh, wvh, wfh,
                                                wql, wkl, wvl, wfl, n4w);

    // 2) projections on tensor cores
    {
        dim3 grid(DD / 128, M / 128);
        mma_gemm<2><<<grid, 256, GM_SMEM>>>(xqh, xql, wqh, wql, nullptr, qph, qpl, nullptr);
        mma_gemm<2><<<grid, 256, GM_SMEM>>>(xkh, xkl, wkh, wkl, nullptr, kph, kpl, nullptr);
        mma_gemm<0><<<grid, 256, GM_SMEM>>>(xvh, xvl, wvh, wvl, vp, nullptr, nullptr, nullptr);
    }
    vtrans_f16<<<dim3(NN_ / 32, DD / 32, BB), dim3(32, 8)>>>(vp, vth);

    // 3) fused single-pass attention: E (unnorm fp16) + rowsum + feat hi/lo
    fused_attn<<<dim3(NN_ / 128, BB * HH), 256, FU_SMEM>>>(
        kph, kpl, qph, qpl, vth, eptr, rsum, fth, ftl);

    // 4) normalize attn into output region
    attn_norm<<<BB * HH * NN_, 256>>>(eptr, rsum, attn);

    // 5) fc + residual on tensor cores
    {
        dim3 grid(DD / 128, M / 128);
        mma_gemm<1><<<grid, 256, GM_SMEM>>>(fth, ftl, wfh, wfl, out, nullptr, nullptr, q);
    }

    // 6) LayerNorm
    layernorm_rows<<<M, 256>>>(out, gam, bet);
}

// round 9
// speedup vs baseline: 2.9878x; 1.0248x over previous
#include <cuda_runtime.h>
#include <cuda_bf16.h>
#include <cuda_fp16.h>
#include <math.h>
#include <stdint.h>

#define BB 2
#define NN_ 4096
#define DD 512
#define HH 8
#define DK 64

typedef __nv_bfloat16 bf16;

// ---------------------------------------------------------------------------
// Scratch (device globals — no allocation allowed)
// ---------------------------------------------------------------------------
__device__ float g_vp[BB * NN_ * DD];
__device__ float g_rowsum[BB * HH * NN_];
__device__ __half g_e[(size_t)BB * HH * NN_ * NN_];      // unnormalized exp, fp16

__device__ bf16 g_xq_hi[BB * NN_ * DD]; __device__ bf16 g_xq_lo[BB * NN_ * DD];
__device__ bf16 g_xk_hi[BB * NN_ * DD]; __device__ bf16 g_xk_lo[BB * NN_ * DD];
__device__ bf16 g_xv_hi[BB * NN_ * DD]; __device__ bf16 g_xv_lo[BB * NN_ * DD];
__device__ bf16 g_wq_hi[DD * DD]; __device__ bf16 g_wq_lo[DD * DD];
__device__ bf16 g_wk_hi[DD * DD]; __device__ bf16 g_wk_lo[DD * DD];
__device__ bf16 g_wv_hi[DD * DD]; __device__ bf16 g_wv_lo[DD * DD];
__device__ bf16 g_wf_hi[DD * DD]; __device__ bf16 g_wf_lo[DD * DD];
__device__ bf16 g_qp_hi[BB * NN_ * DD]; __device__ bf16 g_qp_lo[BB * NN_ * DD];
__device__ bf16 g_kp_hi[BB * NN_ * DD]; __device__ bf16 g_kp_lo[BB * NN_ * DD];
__device__ __half g_vpt_h[BB * HH * DK * NN_];           // [bh, d, token] fp16
__device__ bf16 g_ft_hi[BB * NN_ * DD]; __device__ bf16 g_ft_lo[BB * NN_ * DD];

// ---------------------------------------------------------------------------
// PTX helpers
// ---------------------------------------------------------------------------
__device__ __forceinline__ uint32_t smem_u32(const void* p) {
    uint32_t a;
    asm("{ .reg .u64 t; cvta.to.shared.u64 t, %1; cvt.u32.u64 %0, t; }"
        : "=r"(a) : "l"(p));
    return a;
}

#define CP16(dst, src) \
    asm volatile("cp.async.cg.shared.global [%0], [%1], 16;" :: "r"(dst), "l"(src))
#define CP_COMMIT() asm volatile("cp.async.commit_group;" ::: "memory")
#define CP_WAIT0()  asm volatile("cp.async.wait_group 0;" ::: "memory")
#define CP_WAIT1()  asm volatile("cp.async.wait_group 1;" ::: "memory")

__device__ __forceinline__ void ldsm4(uint32_t& r0, uint32_t& r1, uint32_t& r2, uint32_t& r3,
                                      uint32_t addr) {
    asm volatile("ldmatrix.sync.aligned.m8n8.x4.shared.b16 {%0,%1,%2,%3}, [%4];"
                 : "=r"(r0), "=r"(r1), "=r"(r2), "=r"(r3) : "r"(addr));
}

__device__ __forceinline__ void mma16816(float* c,
                                         uint32_t a0, uint32_t a1, uint32_t a2, uint32_t a3,
                                         uint32_t b0, uint32_t b1) {
    asm volatile(
        "mma.sync.aligned.m16n8k16.row.col.f32.bf16.bf16.f32 "
        "{%0,%1,%2,%3}, {%4,%5,%6,%7}, {%8,%9}, {%0,%1,%2,%3};"
        : "+f"(c[0]), "+f"(c[1]), "+f"(c[2]), "+f"(c[3])
        : "r"(a0), "r"(a1), "r"(a2), "r"(a3), "r"(b0), "r"(b1));
}

__device__ __forceinline__ void mma16816h(float* c,
                                          uint32_t a0, uint32_t a1, uint32_t a2, uint32_t a3,
                                          uint32_t b0, uint32_t b1) {
    asm volatile(
        "mma.sync.aligned.m16n8k16.row.col.f32.f16.f16.f32 "
        "{%0,%1,%2,%3}, {%4,%5,%6,%7}, {%8,%9}, {%0,%1,%2,%3};"
        : "+f"(c[0]), "+f"(c[1]), "+f"(c[2]), "+f"(c[3])
        : "r"(a0), "r"(a1), "r"(a2), "r"(a3), "r"(b0), "r"(b1));
}

__device__ __forceinline__ void split1(float x, bf16& h, bf16& l) {
    h = __float2bfloat16(x);
    l = __float2bfloat16(x - __bfloat162float(h));
}

__device__ __forceinline__ void split_body(const float* __restrict__ x,
                                           bf16* __restrict__ hi,
                                           bf16* __restrict__ lo, int i) {
    float4 v = reinterpret_cast<const float4*>(x)[i];
    bf16 h[4], l[4];
    split1(v.x, h[0], l[0]); split1(v.y, h[1], l[1]);
    split1(v.z, h[2], l[2]); split1(v.w, h[3], l[3]);
    uint2 ph, pl;
    ph.x = ((uint32_t)*(uint16_t*)&h[1] << 16) | *(uint16_t*)&h[0];
    ph.y = ((uint32_t)*(uint16_t*)&h[3] << 16) | *(uint16_t*)&h[2];
    pl.x = ((uint32_t)*(uint16_t*)&l[1] << 16) | *(uint16_t*)&l[0];
    pl.y = ((uint32_t)*(uint16_t*)&l[3] << 16) | *(uint16_t*)&l[2];
    reinterpret_cast<uint2*>(hi)[i] = ph;
    reinterpret_cast<uint2*>(lo)[i] = pl;
}

__global__ void split3(const float* x0, const float* x1, const float* x2,
                       bf16* h0, bf16* h1, bf16* h2,
                       bf16* l0, bf16* l1, bf16* l2, int n4)
{
    int i = blockIdx.x * blockDim.x + threadIdx.x;
    if (i >= n4) return;
    int w = blockIdx.y;
    const float* x = (w == 0) ? x0 : (w == 1) ? x1 : x2;
    bf16* hi = (w == 0) ? h0 : (w == 1) ? h1 : h2;
    bf16* lo = (w == 0) ? l0 : (w == 1) ? l1 : l2;
    split_body(x, hi, lo, i);
}

__global__ void split4(const float* x0, const float* x1, const float* x2, const float* x3,
                       bf16* h0, bf16* h1, bf16* h2, bf16* h3,
                       bf16* l0, bf16* l1, bf16* l2, bf16* l3, int n4)
{
    int i = blockIdx.x * blockDim.x + threadIdx.x;
    if (i >= n4) return;
    int w = blockIdx.y;
    const float* x = (w == 0) ? x0 : (w == 1) ? x1 : (w == 2) ? x2 : x3;
    bf16* hi = (w == 0) ? h0 : (w == 1) ? h1 : (w == 2) ? h2 : h3;
    bf16* lo = (w == 0) ? l0 : (w == 1) ? l1 : (w == 2) ? l2 : l3;
    split_body(x, hi, lo, i);
}

// vp [B, N, D] fp32 -> vpT fp16 [B*H, DK, N]
__global__ void vtrans_f16(const float* __restrict__ vp, __half* __restrict__ vt)
{
    __shared__ float tile[32][33];
    const int j0 = blockIdx.x * 32;
    const int c0 = blockIdx.y * 32;
    const int b  = blockIdx.z;
    const int tx = threadIdx.x, ty = threadIdx.y;
    for (int rr = ty; rr < 32; rr += 8)
        tile[rr][tx] = vp[((long long)(b * NN_ + j0 + rr)) * DD + c0 + tx];
    __syncthreads();
    for (int rr = ty; rr < 32; rr += 8) {
        int c = c0 + rr;
        int h = c >> 6, dl = c & 63;
        long long idx = ((long long)(b * HH + h) * DK + dl) * NN_ + j0 + tx;
        vt[idx] = __float2half_rn(tile[tx][rr]);
    }
}

// ---------------------------------------------------------------------------
// Tensor-core GEMM (NT): 2-stage pipeline, 80KB smem -> 2 CTAs/SM.
// ---------------------------------------------------------------------------
#define GM_SMEM 81920
#define GM_STG  40960u

template<int OUTM>
__global__ void __launch_bounds__(256)
mma_gemm(const bf16* __restrict__ Ahi, const bf16* __restrict__ Alo,
         const bf16* __restrict__ Bhi, const bf16* __restrict__ Blo,
         float* __restrict__ Cf, bf16* __restrict__ Chi, bf16* __restrict__ Clo,
         const float* __restrict__ R)
{
    extern __shared__ char smem[];
    const int tid = threadIdx.x;
    const int wid = tid >> 5;
    const int lane = tid & 31;
    const uint32_t sb = smem_u32(smem);
    const int n0 = blockIdx.x * 128;
    const int m0 = blockIdx.y * 128;

    const int wm = (wid >> 2) * 64;
    const int wn = (wid & 3) * 32;

    float acc[4][4][4];
#pragma unroll
    for (int i = 0; i < 4; i++)
#pragma unroll
        for (int j = 0; j < 4; j++)
#pragma unroll
            for (int c = 0; c < 4; c++) acc[i][j][c] = 0.0f;

    auto load_stage = [&](int kt, int s) {
        const int k0 = kt * 32;
        const uint32_t st = sb + (uint32_t)s * GM_STG;
        for (int i = tid; i < 2048; i += 256) {
            int t = i >> 9, r = (i & 511) >> 2, c = i & 3;
            const bf16* src;
            if (t == 0)      src = Ahi + (long long)(m0 + r) * DD + k0 + c * 8;
            else if (t == 1) src = Alo + (long long)(m0 + r) * DD + k0 + c * 8;
            else if (t == 2) src = Bhi + (long long)(n0 + r) * DD + k0 + c * 8;
            else             src = Blo + (long long)(n0 + r) * DD + k0 + c * 8;
            CP16(st + (uint32_t)t * 10240u + (uint32_t)(r * 80 + c * 16), (const char*)src);
        }
    };

    load_stage(0, 0); CP_COMMIT();

    for (int kt = 0; kt < 16; kt++) {
        if (kt < 15) { load_stage(kt + 1, (kt + 1) & 1); CP_COMMIT(); CP_WAIT1(); }
        else { CP_WAIT0(); }
        __syncthreads();
        const uint32_t st = sb + (uint32_t)(kt & 1) * GM_STG;
#pragma unroll
        for (int prod = 0; prod < 3; prod++) {
            const uint32_t Ab = st + ((prod == 1) ? 10240u : 0u);
            const uint32_t Bb = st + 20480u + ((prod == 2) ? 10240u : 0u);
#pragma unroll
            for (int kc = 0; kc < 2; kc++) {
                const uint32_t colA = (uint32_t)(kc * 32 + ((lane >> 4) & 1) * 16);
                const uint32_t colB = (uint32_t)(kc * 32 + ((lane >> 3) & 1) * 16);
                uint32_t bf[8];
#pragma unroll
                for (int j = 0; j < 2; j++) {
                    int n = wn + j * 16 + ((lane >> 4) & 1) * 8 + (lane & 7);
                    ldsm4(bf[j * 4 + 0], bf[j * 4 + 1], bf[j * 4 + 2], bf[j * 4 + 3],
                          Bb + (uint32_t)(n * 80) + colB);
                }
#pragma unroll
                for (int mi = 0; mi < 4; mi++) {
                    uint32_t a0, a1, a2, a3;
                    int m = wm + mi * 16 + (lane & 15);
                    ldsm4(a0, a1, a2, a3, Ab + (uint32_t)(m * 80) + colA);
#pragma unroll
                    for (int j = 0; j < 2; j++) {
                        mma16816(acc[mi][2 * j],     a0, a1, a2, a3, bf[j * 4 + 0], bf[j * 4 + 1]);
                        mma16816(acc[mi][2 * j + 1], a0, a1, a2, a3, bf[j * 4 + 2], bf[j * 4 + 3]);
                    }
                }
            }
        }
        __syncthreads();
    }

#pragma unroll
    for (int mi = 0; mi < 4; mi++) {
#pragma unroll
        for (int ni = 0; ni < 4; ni++) {
            int r  = wm + mi * 16 + (lane >> 2);
            int cc = wn + ni * 8 + (lane & 3) * 2;
#pragma unroll
            for (int half = 0; half < 2; half++) {
                int row = m0 + r + half * 8;
                int col = n0 + cc;
                float v0 = acc[mi][ni][half * 2 + 0];
                float v1 = acc[mi][ni][half * 2 + 1];
                if (OUTM == 2) {
                    bf16 h0, l0, h1, l1;
                    split1(v0, h0, l0); split1(v1, h1, l1);
                    uint32_t ph = ((uint32_t)*(uint16_t*)&h1 << 16) | *(uint16_t*)&h0;
                    uint32_t pl = ((uint32_t)*(uint16_t*)&l1 << 16) | *(uint16_t*)&l0;
                    *reinterpret_cast<uint32_t*>(Chi + (long long)row * DD + col) = ph;
                    *reinterpret_cast<uint32_t*>(Clo + (long long)row * DD + col) = pl;
                } else {
                    if (OUTM == 1) {
                        float2 r2 = *reinterpret_cast<const float2*>(R + (long long)row * DD + col);
                        v0 += r2.x; v1 += r2.y;
                    }
                    float2 o; o.x = v0; o.y = v1;
                    *reinterpret_cast<float2*>(Cf + (long long)row * DD + col) = o;
                }
            }
        }
    }
}

// ---------------------------------------------------------------------------
// Fused attention, single pass, nb = 64 Q-rows per step.
// smem: K 36KB resident + Q 2x18KB + V 2x9KB = 90KB -> 2 CTAs/SM.
// S = K@Q^T (3-prod bf16); e = exp(0.125 S) -> fp16 -> E scratch + P@V (fp16).
// ---------------------------------------------------------------------------
#define FU_SMEM 92160
#define FU_KHI 0u
#define FU_KLO 18432u
#define FU_Q0  36864u
#define FU_QST 18432u
#define FU_V0  73728u
#define FU_VST 9216u

__global__ void __launch_bounds__(256)
fused_attn(const bf16* __restrict__ Khi, const bf16* __restrict__ Klo,
           const bf16* __restrict__ Qhi, const bf16* __restrict__ Qlo,
           const __half* __restrict__ Vh,
           __half* __restrict__ E, float* __restrict__ rowsum,
           bf16* __restrict__ Fhi, bf16* __restrict__ Flo)
{
    extern __shared__ char smem[];
    const int tid = threadIdx.x;
    const int wid = tid >> 5;
    const int lane = tid & 31;
    const uint32_t sb = smem_u32(smem);

    const int m0 = blockIdx.x * 128;
    const int bh = blockIdx.y;
    const int b = bh >> 3, h = bh & 7;
    const long long arow = (long long)(b * NN_ + m0);
    const int coff = h * DK;
    const long long vrow = (long long)bh * DK;

    // resident K tile (hi/lo), 144B pitch, 128 rows
    for (int i = tid; i < 2048; i += 256) {
        int t = i >> 10, r = (i & 1023) >> 3, c = i & 7;
        const bf16* src = (t ? Klo : Khi) + (arow + r) * DD + coff + c * 8;
        CP16(sb + (uint32_t)t * 18432u + (uint32_t)(r * 144 + c * 16), (const char*)src);
    }

    auto load_Q = [&](int nb, int s) {
        const long long brow = (long long)b * NN_ + (long long)nb * 64;
        const uint32_t st = sb + FU_Q0 + (uint32_t)s * FU_QST;
        for (int i = tid; i < 1024; i += 256) {
            int t = i >> 9, r = (i & 511) >> 3, c = i & 7;
            const bf16* src = (t ? Qlo : Qhi) + (brow + r) * DD + coff + c * 8;
            CP16(st + (uint32_t)t * 9216u + (uint32_t)(r * 144 + c * 16), (const char*)src);
        }
    };
    auto load_V = [&](int nb, int s) {
        const uint32_t st = sb + FU_V0 + (uint32_t)s * FU_VST;
        for (int i = tid; i < 512; i += 256) {
            int r = i >> 3, c = i & 7;
            CP16(st + (uint32_t)(r * 144 + c * 16),
                 (const char*)(Vh + (vrow + r) * NN_ + nb * 64 + c * 8));
        }
    };

    const int gid = lane >> 2, tig = lane & 3;
    const long long ebase = (long long)bh * NN_ * NN_;
    const int mrow = m0 + wid * 16 + gid;

    float rs0 = 0.0f, rs1 = 0.0f;
    float facc[8][4];
#pragma unroll
    for (int i = 0; i < 8; i++)
#pragma unroll
        for (int c = 0; c < 4; c++) facc[i][c] = 0.0f;

    load_Q(0, 0); load_V(0, 0); CP_COMMIT();

    for (int nb = 0; nb < 64; nb++) {
        if (nb < 63) {
            load_Q(nb + 1, (nb + 1) & 1);
            load_V(nb + 1, (nb + 1) & 1);
            CP_COMMIT(); CP_WAIT1();
        } else { CP_WAIT0(); }
        __syncthreads();

        const uint32_t Qst = sb + FU_Q0 + (uint32_t)(nb & 1) * FU_QST;
        const uint32_t Vst = sb + FU_V0 + (uint32_t)(nb & 1) * FU_VST;

        float sacc[8][4];
#pragma unroll
        for (int i = 0; i < 8; i++)
#pragma unroll
            for (int c = 0; c < 4; c++) sacc[i][c] = 0.0f;

        // scores: S[m16, n64] over dk=64 (3 products)
#pragma unroll
        for (int prod = 0; prod < 3; prod++) {
            const uint32_t Ab = sb + ((prod == 1) ? FU_KLO : FU_KHI);
            const uint32_t Qb = Qst + ((prod == 2) ? 9216u : 0u);
#pragma unroll
            for (int kc = 0; kc < 4; kc++) {
                const uint32_t colA = (uint32_t)(kc * 32 + ((lane >> 4) & 1) * 16);
                const uint32_t colB = (uint32_t)(kc * 32 + ((lane >> 3) & 1) * 16);
                uint32_t a0, a1, a2, a3;
                ldsm4(a0, a1, a2, a3,
                      Ab + (uint32_t)((wid * 16 + (lane & 15)) * 144) + colA);
#pragma unroll
                for (int j = 0; j < 4; j++) {
                    int n = j * 16 + ((lane >> 4) & 1) * 8 + (lane & 7);
                    uint32_t q0, q1, q2, q3;
                    ldsm4(q0, q1, q2, q3, Qb + (uint32_t)(n * 144) + colB);
                    mma16816(sacc[2 * j],     a0, a1, a2, a3, q0, q1);
                    mma16816(sacc[2 * j + 1], a0, a1, a2, a3, q2, q3);
                }
            }
        }

        // exp -> fp16 (store to E AND feed P@V), rowsum in registers
#pragma unroll
        for (int kch = 0; kch < 4; kch++) {
            uint32_t a0, a1, a2, a3;
#pragma unroll
            for (int jj = 0; jj < 2; jj++) {
                int j = 2 * kch + jj;
                float e0 = __expf(0.125f * sacc[j][0]);
                float e1 = __expf(0.125f * sacc[j][1]);
                float e2 = __expf(0.125f * sacc[j][2]);
                float e3 = __expf(0.125f * sacc[j][3]);
                rs0 += e0 + e1;
                rs1 += e2 + e3;
                __half2 h01 = __floats2half2_rn(e0, e1);
                __half2 h23 = __floats2half2_rn(e2, e3);
                long long colg = (long long)nb * 64 + j * 8 + tig * 2;
                *reinterpret_cast<uint32_t*>(E + ebase + (long long)mrow * NN_ + colg) =
                    *reinterpret_cast<uint32_t*>(&h01);
                *reinterpret_cast<uint32_t*>(E + ebase + (long long)(mrow + 8) * NN_ + colg) =
                    *reinterpret_cast<uint32_t*>(&h23);
                if (jj == 0) { a0 = *reinterpret_cast<uint32_t*>(&h01);
                               a1 = *reinterpret_cast<uint32_t*>(&h23); }
                else         { a2 = *reinterpret_cast<uint32_t*>(&h01);
                               a3 = *reinterpret_cast<uint32_t*>(&h23); }
            }
            const uint32_t colV = (uint32_t)(kch * 32 + ((lane >> 3) & 1) * 16);
#pragma unroll
            for (int vj = 0; vj < 4; vj++) {
                int n = vj * 16 + ((lane >> 4) & 1) * 8 + (lane & 7);
                uint32_t v0, v1, v2, v3;
                ldsm4(v0, v1, v2, v3, Vst + (uint32_t)(n * 144) + colV);
                mma16816h(facc[2 * vj],     a0, a1, a2, a3, v0, v1);
                mma16816h(facc[2 * vj + 1], a0, a1, a2, a3, v2, v3);
            }
        }
        __syncthreads();
    }

    // rowsum reduce across quad, write to gmem, scale feat
    rs0 += __shfl_xor_sync(~0u, rs0, 1);
    rs0 += __shfl_xor_sync(~0u, rs0, 2);
    rs1 += __shfl_xor_sync(~0u, rs1, 1);
    rs1 += __shfl_xor_sync(~0u, rs1, 2);
    const float inv0 = __frcp_rn(rs0);
    const float inv1 = __frcp_rn(rs1);
    if (tig == 0) {
        rowsum[(long long)bh * NN_ + mrow]     = rs0;
        rowsum[(long long)bh * NN_ + mrow + 8] = rs1;
    }

#pragma unroll
    for (int n8 = 0; n8 < 8; n8++) {
        int col = h * DK + n8 * 8 + tig * 2;
#pragma unroll
        for (int half = 0; half < 2; half++) {
            long long row = (long long)(b * NN_ + mrow + half * 8);
            float inv = half ? inv1 : inv0;
            float v0 = facc[n8][half * 2 + 0] * inv;
            float v1 = facc[n8][half * 2 + 1] * inv;
            bf16 h0, l0, h1, l1;
            split1(v0, h0, l0); split1(v1, h1, l1);
            uint32_t ph = ((uint32_t)*(uint16_t*)&h1 << 16) | *(uint16_t*)&h0;
            uint32_t pl = ((uint32_t)*(uint16_t*)&l1 << 16) | *(uint16_t*)&l0;
            *reinterpret_cast<uint32_t*>(Fhi + row * DD + col) = ph;
            *reinterpret_cast<uint32_t*>(Flo + row * DD + col) = pl;
        }
    }
}

// ---------------------------------------------------------------------------
// attn_norm: attn[row, :] = float(E[row, :]) * rcp(rowsum[row])
// ---------------------------------------------------------------------------
__global__ void __launch_bounds__(256)
attn_norm(const __half* __restrict__ E, const float* __restrict__ rowsum,
          float* __restrict__ A)
{
    const long long row = blockIdx.x;
    const float inv = __frcp_rn(rowsum[row]);
    const uint2* pe = reinterpret_cast<const uint2*>(E + row * (long long)NN_);
    float4* pa = reinterpret_cast<float4*>(A + row * (long long)NN_);
    const int t = threadIdx.x;
#pragma unroll
    for (int i = 0; i < 4; i++) {
        uint2 u = pe[t + i * 256];
        __half2 a = *reinterpret_cast<__half2*>(&u.x);
        __half2 bq = *reinterpret_cast<__half2*>(&u.y);
        float2 fa = __half22float2(a);
        float2 fb = __half22float2(bq);
        float4 o;
        o.x = fa.x * inv; o.y = fa.y * inv;
        o.z = fb.x * inv; o.w = fb.y * inv;
        pa[t + i * 256] = o;
    }
}

// ---------------------------------------------------------------------------
// In-place row LayerNorm
// ---------------------------------------------------------------------------
__global__ void layernorm_rows(float* __restrict__ y,
                               const float* __restrict__ gamma,
                               const float* __restrict__ beta)
{
    const long long base = (long long)blockIdx.x * DD;
    const int t = threadIdx.x;
    const int lane = t & 31, warp = t >> 5;
    __shared__ float red[32];

    float x0 = y[base + t];
    float x1 = y[base + t + 256];

    float s = x0 + x1;
#pragma unroll
    for (int o = 16; o > 0; o >>= 1) s += __shfl_xor_sync(~0u, s, o);
    if (lane == 0) red[warp] = s;
    __syncthreads();
    if (warp == 0) {
        float x = (lane < 8) ? red[lane] : 0.0f;
#pragma unroll
        for (int o = 16; o > 0; o >>= 1) x += __shfl_xor_sync(~0u, x, o);
        if (lane == 0) red[0] = x;
    }
    __syncthreads();
    const float mu = red[0] * (1.0f / DD);
    __syncthreads();

    const float d0 = x0 - mu, d1 = x1 - mu;
    float v = d0 * d0 + d1 * d1;
#pragma unroll
    for (int o = 16; o > 0; o >>= 1) v += __shfl_xor_sync(~0u, v, o);
    if (lane == 0) red[warp] = v;
    __syncthreads();
    if (warp == 0) {
        float x = (lane < 8) ? red[lane] : 0.0f;
#pragma unroll
        for (int o = 16; o > 0; o >>= 1) x += __shfl_xor_sync(~0u, x, o);
        if (lane == 0) red[0] = x;
    }
    __syncthreads();
    const float r = rsqrtf(red[0] * (1.0f / DD) + 1e-5f);

    y[base + t]       = d0 * r * gamma[t]       + beta[t];
    y[base + t + 256] = d1 * r * gamma[t + 256] + beta[t + 256];
}

// ---------------------------------------------------------------------------
extern "C" void kernel_launch(void* const* d_in, const int* in_sizes, int n_in,
                              void* d_out, int out_size)
{
    const float* q    = (const float*)d_in[0];
    const float* k    = (const float*)d_in[1];
    const float* v    = (const float*)d_in[2];
    const float* w_q  = (const float*)d_in[3];
    const float* w_k  = (const float*)d_in[4];
    const float* w_v  = (const float*)d_in[5];
    const float* w_fc = (const float*)d_in[6];
    const float* gam  = (const float*)d_in[7];
    const float* bet  = (const float*)d_in[8];

    float* out  = (float*)d_out;                          // [B,N,D]
    float* attn = out + (long long)BB * NN_ * DD;         // [B,H,N,N]

    float *vp, *rsum;
    __half* eptr;
    cudaGetSymbolAddress((void**)&vp,   g_vp);
    cudaGetSymbolAddress((void**)&rsum, g_rowsum);
    cudaGetSymbolAddress((void**)&eptr, g_e);
    bf16 *xqh, *xql, *xkh, *xkl, *xvh, *xvl;
    bf16 *wqh, *wql, *wkh, *wkl, *wvh, *wvl, *wfh, *wfl;
    bf16 *qph, *qpl, *kph, *kpl, *fth, *ftl;
    __half* vth;
    cudaGetSymbolAddress((void**)&xqh, g_xq_hi); cudaGetSymbolAddress((void**)&xql, g_xq_lo);
    cudaGetSymbolAddress((void**)&xkh, g_xk_hi); cudaGetSymbolAddress((void**)&xkl, g_xk_lo);
    cudaGetSymbolAddress((void**)&xvh, g_xv_hi); cudaGetSymbolAddress((void**)&xvl, g_xv_lo);
    cudaGetSymbolAddress((void**)&wqh, g_wq_hi); cudaGetSymbolAddress((void**)&wql, g_wq_lo);
    cudaGetSymbolAddress((void**)&wkh, g_wk_hi); cudaGetSymbolAddress((void**)&wkl, g_wk_lo);
    cudaGetSymbolAddress((void**)&wvh, g_wv_hi); cudaGetSymbolAddress((void**)&wvl, g_wv_lo);
    cudaGetSymbolAddress((void**)&wfh, g_wf_hi); cudaGetSymbolAddress((void**)&wfl, g_wf_lo);
    cudaGetSymbolAddress((void**)&qph, g_qp_hi); cudaGetSymbolAddress((void**)&qpl, g_qp_lo);
    cudaGetSymbolAddress((void**)&kph, g_kp_hi); cudaGetSymbolAddress((void**)&kpl, g_kp_lo);
    cudaGetSymbolAddress((void**)&vth, g_vpt_h);
    cudaGetSymbolAddress((void**)&fth, g_ft_hi); cudaGetSymbolAddress((void**)&ftl, g_ft_lo);

    cudaFuncSetAttribute(mma_gemm<0>, cudaFuncAttributeMaxDynamicSharedMemorySize, GM_SMEM);
    cudaFuncSetAttribute(mma_gemm<1>, cudaFuncAttributeMaxDynamicSharedMemorySize, GM_SMEM);
    cudaFuncSetAttribute(mma_gemm<2>, cudaFuncAttributeMaxDynamicSharedMemorySize, GM_SMEM);
    cudaFuncSetAttribute(fused_attn, cudaFuncAttributeMaxDynamicSharedMemorySize, FU_SMEM);

    const int M = BB * NN_;          // 8192
    const int n4i = M * DD / 4;
    const int n4w = DD * DD / 4;

    // 1) splits (merged)
    split3<<<dim3((n4i + 255) / 256, 3), 256>>>(q, k, v, xqh, xkh, xvh, xql, xkl, xvl, n4i);
    split4<<<dim3((n4w + 255) / 256, 4), 256>>>(w_q, w_k, w_v, w_fc,
                                                wqh, wkh, wvh, wfh,
                                                wql, wkl, wvl, wfl, n4w);

    // 2) projections on tensor cores
    {
        dim3 grid(DD / 128, M / 128);
        mma_gemm<2><<<grid, 256, GM_SMEM>>>(xqh, xql, wqh, wql, nullptr, qph, qpl, nullptr);
        mma_gemm<2><<<grid, 256, GM_SMEM>>>(xkh, xkl, wkh, wkl, nullptr, kph, kpl, nullptr);
        mma_gemm<0><<<grid, 256, GM_SMEM>>>(xvh, xvl, wvh, wvl, vp, nullptr, nullptr, nullptr);
    }
    vtrans_f16<<<dim3(NN_ / 32, DD / 32, BB), dim3(32, 8)>>>(vp, vth);

    // 3) fused single-pass attention (2 CTAs/SM): E + rowsum + feat hi/lo
    fused_attn<<<dim3(NN_ / 128, BB * HH), 256, FU_SMEM>>>(
        kph, kpl, qph, qpl, vth, eptr, rsum, fth, ftl);

    // 4) normalize attn into output region
    attn_norm<<<BB * HH * NN_, 256>>>(eptr, rsum, attn);

    // 5) fc + residual on tensor cores
    {
        dim3 grid(DD / 128, M / 128);
        mma_gemm<1><<<grid, 256, GM_SMEM>>>(fth, ftl, wfh, wfl, out, nullptr, nullptr, q);
    }

    // 6) LayerNorm
    layernorm_rows<<<M, 256>>>(out, gam, bet);
}

// round 10
// speedup vs baseline: 3.0801x; 1.0309x over previous
#include <cuda_runtime.h>
#include <cuda_bf16.h>
#include <cuda_fp16.h>
#include <math.h>
#include <stdint.h>

#define BB 2
#define NN_ 4096
#define DD 512
#define HH 8
#define DK 64

typedef __nv_bfloat16 bf16;

// ---------------------------------------------------------------------------
// Scratch (device globals — no allocation allowed)
// ---------------------------------------------------------------------------
__device__ float g_vp[BB * NN_ * DD];
__device__ float g_rowsum[BB * HH * NN_];
__device__ __half g_e[(size_t)BB * HH * NN_ * NN_];      // unnormalized exp, fp16

__device__ bf16 g_xq_hi[BB * NN_ * DD]; __device__ bf16 g_xq_lo[BB * NN_ * DD];
__device__ bf16 g_xk_hi[BB * NN_ * DD]; __device__ bf16 g_xk_lo[BB * NN_ * DD];
__device__ bf16 g_xv_hi[BB * NN_ * DD]; __device__ bf16 g_xv_lo[BB * NN_ * DD];
__device__ bf16 g_wq_hi[DD * DD]; __device__ bf16 g_wq_lo[DD * DD];
__device__ bf16 g_wk_hi[DD * DD]; __device__ bf16 g_wk_lo[DD * DD];
__device__ bf16 g_wv_hi[DD * DD]; __device__ bf16 g_wv_lo[DD * DD];
__device__ bf16 g_wf_hi[DD * DD]; __device__ bf16 g_wf_lo[DD * DD];
__device__ bf16 g_qp_hi[BB * NN_ * DD]; __device__ bf16 g_qp_lo[BB * NN_ * DD];
__device__ bf16 g_kp_hi[BB * NN_ * DD]; __device__ bf16 g_kp_lo[BB * NN_ * DD];
__device__ __half g_vpt_h[BB * HH * DK * NN_];           // [bh, d, token] fp16
__device__ bf16 g_ft_hi[BB * NN_ * DD]; __device__ bf16 g_ft_lo[BB * NN_ * DD];

// ---------------------------------------------------------------------------
// PTX helpers
// ---------------------------------------------------------------------------
__device__ __forceinline__ uint32_t smem_u32(const void* p) {
    uint32_t a;
    asm("{ .reg .u64 t; cvta.to.shared.u64 t, %1; cvt.u32.u64 %0, t; }"
        : "=r"(a) : "l"(p));
    return a;
}

#define CP16(dst, src) \
    asm volatile("cp.async.cg.shared.global [%0], [%1], 16;" :: "r"(dst), "l"(src))
#define CP_COMMIT() asm volatile("cp.async.commit_group;" ::: "memory")
#define CP_WAIT0()  asm volatile("cp.async.wait_group 0;" ::: "memory")
#define CP_WAIT1()  asm volatile("cp.async.wait_group 1;" ::: "memory")

__device__ __forceinline__ void ldsm4(uint32_t& r0, uint32_t& r1, uint32_t& r2, uint32_t& r3,
                                      uint32_t addr) {
    asm volatile("ldmatrix.sync.aligned.m8n8.x4.shared.b16 {%0,%1,%2,%3}, [%4];"
                 : "=r"(r0), "=r"(r1), "=r"(r2), "=r"(r3) : "r"(addr));
}

__device__ __forceinline__ void mma16816(float* c,
                                         uint32_t a0, uint32_t a1, uint32_t a2, uint32_t a3,
                                         uint32_t b0, uint32_t b1) {
    asm volatile(
        "mma.sync.aligned.m16n8k16.row.col.f32.bf16.bf16.f32 "
        "{%0,%1,%2,%3}, {%4,%5,%6,%7}, {%8,%9}, {%0,%1,%2,%3};"
        : "+f"(c[0]), "+f"(c[1]), "+f"(c[2]), "+f"(c[3])
        : "r"(a0), "r"(a1), "r"(a2), "r"(a3), "r"(b0), "r"(b1));
}

__device__ __forceinline__ void mma16816h(float* c,
                                          uint32_t a0, uint32_t a1, uint32_t a2, uint32_t a3,
                                          uint32_t b0, uint32_t b1) {
    asm volatile(
        "mma.sync.aligned.m16n8k16.row.col.f32.f16.f16.f32 "
        "{%0,%1,%2,%3}, {%4,%5,%6,%7}, {%8,%9}, {%0,%1,%2,%3};"
        : "+f"(c[0]), "+f"(c[1]), "+f"(c[2]), "+f"(c[3])
        : "r"(a0), "r"(a1), "r"(a2), "r"(a3), "r"(b0), "r"(b1));
}

__device__ __forceinline__ void split1(float x, bf16& h, bf16& l) {
    h = __float2bfloat16(x);
    l = __float2bfloat16(x - __bfloat162float(h));
}

__device__ __forceinline__ void split_body(const float* __restrict__ x,
                                           bf16* __restrict__ hi,
                                           bf16* __restrict__ lo, int i) {
    float4 v = reinterpret_cast<const float4*>(x)[i];
    bf16 h[4], l[4];
    split1(v.x, h[0], l[0]); split1(v.y, h[1], l[1]);
    split1(v.z, h[2], l[2]); split1(v.w, h[3], l[3]);
    uint2 ph, pl;
    ph.x = ((uint32_t)*(uint16_t*)&h[1] << 16) | *(uint16_t*)&h[0];
    ph.y = ((uint32_t)*(uint16_t*)&h[3] << 16) | *(uint16_t*)&h[2];
    pl.x = ((uint32_t)*(uint16_t*)&l[1] << 16) | *(uint16_t*)&l[0];
    pl.y = ((uint32_t)*(uint16_t*)&l[3] << 16) | *(uint16_t*)&l[2];
    reinterpret_cast<uint2*>(hi)[i] = ph;
    reinterpret_cast<uint2*>(lo)[i] = pl;
}

__global__ void split3(const float* x0, const float* x1, const float* x2,
                       bf16* h0, bf16* h1, bf16* h2,
                       bf16* l0, bf16* l1, bf16* l2, int n4)
{
    int i = blockIdx.x * blockDim.x + threadIdx.x;
    if (i >= n4) return;
    int w = blockIdx.y;
    const float* x = (w == 0) ? x0 : (w == 1) ? x1 : x2;
    bf16* hi = (w == 0) ? h0 : (w == 1) ? h1 : h2;
    bf16* lo = (w == 0) ? l0 : (w == 1) ? l1 : l2;
    split_body(x, hi, lo, i);
}

__global__ void split4(const float* x0, const float* x1, const float* x2, const float* x3,
                       bf16* h0, bf16* h1, bf16* h2, bf16* h3,
                       bf16* l0, bf16* l1, bf16* l2, bf16* l3, int n4)
{
    int i = blockIdx.x * blockDim.x + threadIdx.x;
    if (i >= n4) return;
    int w = blockIdx.y;
    const float* x = (w == 0) ? x0 : (w == 1) ? x1 : (w == 2) ? x2 : x3;
    bf16* hi = (w == 0) ? h0 : (w == 1) ? h1 : (w == 2) ? h2 : h3;
    bf16* lo = (w == 0) ? l0 : (w == 1) ? l1 : (w == 2) ? l2 : l3;
    split_body(x, hi, lo, i);
}

// vp [B, N, D] fp32 -> vpT fp16 [B*H, DK, N]
__global__ void vtrans_f16(const float* __restrict__ vp, __half* __restrict__ vt)
{
    __shared__ float tile[32][33];
    const int j0 = blockIdx.x * 32;
    const int c0 = blockIdx.y * 32;
    const int b  = blockIdx.z;
    const int tx = threadIdx.x, ty = threadIdx.y;
    for (int rr = ty; rr < 32; rr += 8)
        tile[rr][tx] = vp[((long long)(b * NN_ + j0 + rr)) * DD + c0 + tx];
    __syncthreads();
    for (int rr = ty; rr < 32; rr += 8) {
        int c = c0 + rr;
        int h = c >> 6, dl = c & 63;
        long long idx = ((long long)(b * HH + h) * DK + dl) * NN_ + j0 + tx;
        vt[idx] = __float2half_rn(tile[tx][rr]);
    }
}

// ---------------------------------------------------------------------------
// Tensor-core GEMM (NT): BM=64, BN=128, BK=32, warp tile 32x32.
// 2-stage pipeline, 60KB smem, ~100 regs -> 2 CTAs/SM (reg-capped via
// launch_bounds). Grid (4, 128) = 512 CTAs.
// ---------------------------------------------------------------------------
#define GM_SMEM 61440
#define GM_STG  30720u

template<int OUTM>
__global__ void __launch_bounds__(256, 2)
mma_gemm(const bf16* __restrict__ Ahi, const bf16* __restrict__ Alo,
         const bf16* __restrict__ Bhi, const bf16* __restrict__ Blo,
         float* __restrict__ Cf, bf16* __restrict__ Chi, bf16* __restrict__ Clo,
         const float* __restrict__ R)
{
    extern __shared__ char smem[];
    const int tid = threadIdx.x;
    const int wid = tid >> 5;
    const int lane = tid & 31;
    const uint32_t sb = smem_u32(smem);
    const int n0 = blockIdx.x * 128;
    const int m0 = blockIdx.y * 64;

    const int wm = (wid >> 2) * 32;
    const int wn = (wid & 3) * 32;

    float acc[2][4][4];
#pragma unroll
    for (int i = 0; i < 2; i++)
#pragma unroll
        for (int j = 0; j < 4; j++)
#pragma unroll
            for (int c = 0; c < 4; c++) acc[i][j][c] = 0.0f;

    auto load_stage = [&](int kt, int s) {
        const int k0 = kt * 32;
        const uint32_t st = sb + (uint32_t)s * GM_STG;
        // A: 64 rows x 4 c16 x 2(hi/lo) = 512; B: 128 x 4 x 2 = 1024
        for (int i = tid; i < 1536; i += 256) {
            if (i < 512) {
                int t = (i >> 8) & 1, r = (i & 255) >> 2, c = i & 3;
                const bf16* src = (t ? Alo : Ahi) + (long long)(m0 + r) * DD + k0 + c * 8;
                CP16(st + (uint32_t)t * 5120u + (uint32_t)(r * 80 + c * 16), (const char*)src);
            } else {
                int j = i - 512;
                int t = j >> 9, r = (j & 511) >> 2, c = j & 3;
                const bf16* src = (t ? Blo : Bhi) + (long long)(n0 + r) * DD + k0 + c * 8;
                CP16(st + 10240u + (uint32_t)t * 10240u + (uint32_t)(r * 80 + c * 16),
                     (const char*)src);
            }
        }
    };

    load_stage(0, 0); CP_COMMIT();

    for (int kt = 0; kt < 16; kt++) {
        if (kt < 15) { load_stage(kt + 1, (kt + 1) & 1); CP_COMMIT(); CP_WAIT1(); }
        else { CP_WAIT0(); }
        __syncthreads();
        const uint32_t st = sb + (uint32_t)(kt & 1) * GM_STG;
#pragma unroll
        for (int prod = 0; prod < 3; prod++) {
            const uint32_t Ab = st + ((prod == 1) ? 5120u : 0u);
            const uint32_t Bb = st + 10240u + ((prod == 2) ? 10240u : 0u);
#pragma unroll
            for (int kc = 0; kc < 2; kc++) {
                const uint32_t colA = (uint32_t)(kc * 32 + ((lane >> 4) & 1) * 16);
                const uint32_t colB = (uint32_t)(kc * 32 + ((lane >> 3) & 1) * 16);
                uint32_t bf[8];
#pragma unroll
                for (int j = 0; j < 2; j++) {
                    int n = wn + j * 16 + ((lane >> 4) & 1) * 8 + (lane & 7);
                    ldsm4(bf[j * 4 + 0], bf[j * 4 + 1], bf[j * 4 + 2], bf[j * 4 + 3],
                          Bb + (uint32_t)(n * 80) + colB);
                }
#pragma unroll
                for (int mi = 0; mi < 2; mi++) {
                    uint32_t a0, a1, a2, a3;
                    int m = wm + mi * 16 + (lane & 15);
                    ldsm4(a0, a1, a2, a3, Ab + (uint32_t)(m * 80) + colA);
#pragma unroll
                    for (int j = 0; j < 2; j++) {
                        mma16816(acc[mi][2 * j],     a0, a1, a2, a3, bf[j * 4 + 0], bf[j * 4 + 1]);
                        mma16816(acc[mi][2 * j + 1], a0, a1, a2, a3, bf[j * 4 + 2], bf[j * 4 + 3]);
                    }
                }
            }
        }
        __syncthreads();
    }

#pragma unroll
    for (int mi = 0; mi < 2; mi++) {
#pragma unroll
        for (int ni = 0; ni < 4; ni++) {
            int r  = wm + mi * 16 + (lane >> 2);
            int cc = wn + ni * 8 + (lane & 3) * 2;
#pragma unroll
            for (int half = 0; half < 2; half++) {
                int row = m0 + r + half * 8;
                int col = n0 + cc;
                float v0 = acc[mi][ni][half * 2 + 0];
                float v1 = acc[mi][ni][half * 2 + 1];
                if (OUTM == 2) {
                    bf16 h0, l0, h1, l1;
                    split1(v0, h0, l0); split1(v1, h1, l1);
                    uint32_t ph = ((uint32_t)*(uint16_t*)&h1 << 16) | *(uint16_t*)&h0;
                    uint32_t pl = ((uint32_t)*(uint16_t*)&l1 << 16) | *(uint16_t*)&l0;
                    *reinterpret_cast<uint32_t*>(Chi + (long long)row * DD + col) = ph;
                    *reinterpret_cast<uint32_t*>(Clo + (long long)row * DD + col) = pl;
                } else {
                    if (OUTM == 1) {
                        float2 r2 = *reinterpret_cast<const float2*>(R + (long long)row * DD + col);
                        v0 += r2.x; v1 += r2.y;
                    }
                    float2 o; o.x = v0; o.y = v1;
                    *reinterpret_cast<float2*>(Cf + (long long)row * DD + col) = o;
                }
            }
        }
    }
}

// ---------------------------------------------------------------------------
// Fused attention, single pass, nb = 64 Q-rows per step, 2 CTAs/SM target.
// smem: K 36KB resident + Q 2x18KB + V 2x9KB = 90KB.
// ---------------------------------------------------------------------------
#define FU_SMEM 92160
#define FU_KHI 0u
#define FU_KLO 18432u
#define FU_Q0  36864u
#define FU_QST 18432u
#define FU_V0  73728u
#define FU_VST 9216u

__global__ void __launch_bounds__(256, 2)
fused_attn(const bf16* __restrict__ Khi, const bf16* __restrict__ Klo,
           const bf16* __restrict__ Qhi, const bf16* __restrict__ Qlo,
           const __half* __restrict__ Vh,
           __half* __restrict__ E, float* __restrict__ rowsum,
           bf16* __restrict__ Fhi, bf16* __restrict__ Flo)
{
    extern __shared__ char smem[];
    const int tid = threadIdx.x;
    const int wid = tid >> 5;
    const int lane = tid & 31;
    const uint32_t sb = smem_u32(smem);

    const int m0 = blockIdx.x * 128;
    const int bh = blockIdx.y;
    const int b = bh >> 3, h = bh & 7;
    const long long arow = (long long)(b * NN_ + m0);
    const int coff = h * DK;
    const long long vrow = (long long)bh * DK;

    // resident K tile (hi/lo), 144B pitch, 128 rows
    for (int i = tid; i < 2048; i += 256) {
        int t = i >> 10, r = (i & 1023) >> 3, c = i & 7;
        const bf16* src = (t ? Klo : Khi) + (arow + r) * DD + coff + c * 8;
        CP16(sb + (uint32_t)t * 18432u + (uint32_t)(r * 144 + c * 16), (const char*)src);
    }

    auto load_Q = [&](int nb, int s) {
        const long long brow = (long long)b * NN_ + (long long)nb * 64;
        const uint32_t st = sb + FU_Q0 + (uint32_t)s * FU_QST;
        for (int i = tid; i < 1024; i += 256) {
            int t = i >> 9, r = (i & 511) >> 3, c = i & 7;
            const bf16* src = (t ? Qlo : Qhi) + (brow + r) * DD + coff + c * 8;
            CP16(st + (uint32_t)t * 9216u + (uint32_t)(r * 144 + c * 16), (const char*)src);
        }
    };
    auto load_V = [&](int nb, int s) {
        const uint32_t st = sb + FU_V0 + (uint32_t)s * FU_VST;
        for (int i = tid; i < 512; i += 256) {
            int r = i >> 3, c = i & 7;
            CP16(st + (uint32_t)(r * 144 + c * 16),
                 (const char*)(Vh + (vrow + r) * NN_ + nb * 64 + c * 8));
        }
    };

    const int gid = lane >> 2, tig = lane & 3;
    const long long ebase = (long long)bh * NN_ * NN_;
    const int mrow = m0 + wid * 16 + gid;

    float rs0 = 0.0f, rs1 = 0.0f;
    float facc[8][4];
#pragma unroll
    for (int i = 0; i < 8; i++)
#pragma unroll
        for (int c = 0; c < 4; c++) facc[i][c] = 0.0f;

    load_Q(0, 0); load_V(0, 0); CP_COMMIT();

    for (int nb = 0; nb < 64; nb++) {
        if (nb < 63) {
            load_Q(nb + 1, (nb + 1) & 1);
            load_V(nb + 1, (nb + 1) & 1);
            CP_COMMIT(); CP_WAIT1();
        } else { CP_WAIT0(); }
        __syncthreads();

        const uint32_t Qst = sb + FU_Q0 + (uint32_t)(nb & 1) * FU_QST;
        const uint32_t Vst = sb + FU_V0 + (uint32_t)(nb & 1) * FU_VST;

        float sacc[8][4];
#pragma unroll
        for (int i = 0; i < 8; i++)
#pragma unroll
            for (int c = 0; c < 4; c++) sacc[i][c] = 0.0f;

        // scores: S[m16, n64] over dk=64 (3 products)
#pragma unroll
        for (int prod = 0; prod < 3; prod++) {
            const uint32_t Ab = sb + ((prod == 1) ? FU_KLO : FU_KHI);
            const uint32_t Qb = Qst + ((prod == 2) ? 9216u : 0u);
#pragma unroll
            for (int kc = 0; kc < 4; kc++) {
                const uint32_t colA = (uint32_t)(kc * 32 + ((lane >> 4) & 1) * 16);
                const uint32_t colB = (uint32_t)(kc * 32 + ((lane >> 3) & 1) * 16);
                uint32_t a0, a1, a2, a3;
                ldsm4(a0, a1, a2, a3,
                      Ab + (uint32_t)((wid * 16 + (lane & 15)) * 144) + colA);
#pragma unroll
                for (int j = 0; j < 4; j++) {
                    int n = j * 16 + ((lane >> 4) & 1) * 8 + (lane & 7);
                    uint32_t q0, q1, q2, q3;
                    ldsm4(q0, q1, q2, q3, Qb + (uint32_t)(n * 144) + colB);
                    mma16816(sacc[2 * j],     a0, a1, a2, a3, q0, q1);
                    mma16816(sacc[2 * j + 1], a0, a1, a2, a3, q2, q3);
                }
            }
        }

        // exp -> fp16 (store to E AND feed P@V), rowsum in registers
#pragma unroll
        for (int kch = 0; kch < 4; kch++) {
            uint32_t a0, a1, a2, a3;
#pragma unroll
            for (int jj = 0; jj < 2; jj++) {
                int j = 2 * kch + jj;
                float e0 = __expf(0.125f * sacc[j][0]);
                float e1 = __expf(0.125f * sacc[j][1]);
                float e2 = __expf(0.125f * sacc[j][2]);
                float e3 = __expf(0.125f * sacc[j][3]);
                rs0 += e0 + e1;
                rs1 += e2 + e3;
                __half2 h01 = __floats2half2_rn(e0, e1);
                __half2 h23 = __floats2half2_rn(e2, e3);
                long long colg = (long long)nb * 64 + j * 8 + tig * 2;
                *reinterpret_cast<uint32_t*>(E + ebase + (long long)mrow * NN_ + colg) =
                    *reinterpret_cast<uint32_t*>(&h01);
                *reinterpret_cast<uint32_t*>(E + ebase + (long long)(mrow + 8) * NN_ + colg) =
                    *reinterpret_cast<uint32_t*>(&h23);
                if (jj == 0) { a0 = *reinterpret_cast<uint32_t*>(&h01);
                               a1 = *reinterpret_cast<uint32_t*>(&h23); }
                else         { a2 = *reinterpret_cast<uint32_t*>(&h01);
                               a3 = *reinterpret_cast<uint32_t*>(&h23); }
            }
            const uint32_t colV = (uint32_t)(kch * 32 + ((lane >> 3) & 1) * 16);
#pragma unroll
            for (int vj = 0; vj < 4; vj++) {
                int n = vj * 16 + ((lane >> 4) & 1) * 8 + (lane & 7);
                uint32_t v0, v1, v2, v3;
                ldsm4(v0, v1, v2, v3, Vst + (uint32_t)(n * 144) + colV);
                mma16816h(facc[2 * vj],     a0, a1, a2, a3, v0, v1);
                mma16816h(facc[2 * vj + 1], a0, a1, a2, a3, v2, v3);
            }
        }
        __syncthreads();
    }

    // rowsum reduce across quad, write to gmem, scale feat
    rs0 += __shfl_xor_sync(~0u, rs0, 1);
    rs0 += __shfl_xor_sync(~0u, rs0, 2);
    rs1 += __shfl_xor_sync(~0u, rs1, 1);
    rs1 += __shfl_xor_sync(~0u, rs1, 2);
    const float inv0 = __frcp_rn(rs0);
    const float inv1 = __frcp_rn(rs1);
    if (tig == 0) {
        rowsum[(long long)bh * NN_ + mrow]     = rs0;
        rowsum[(long long)bh * NN_ + mrow + 8] = rs1;
    }

#pragma unroll
    for (int n8 = 0; n8 < 8; n8++) {
        int col = h * DK + n8 * 8 + tig * 2;
#pragma unroll
        for (int half = 0; half < 2; half++) {
            long long row = (long long)(b * NN_ + mrow + half * 8);
            float inv = half ? inv1 : inv0;
            float v0 = facc[n8][half * 2 + 0] * inv;
            float v1 = facc[n8][half * 2 + 1] * inv;
            bf16 h0, l0, h1, l1;
            split1(v0, h0, l0); split1(v1, h1, l1);
            uint32_t ph = ((uint32_t)*(uint16_t*)&h1 << 16) | *(uint16_t*)&h0;
            uint32_t pl = ((uint32_t)*(uint16_t*)&l1 << 16) | *(uint16_t*)&l0;
            *reinterpret_cast<uint32_t*>(Fhi + row * DD + col) = ph;
            *reinterpret_cast<uint32_t*>(Flo + row * DD + col) = pl;
        }
    }
}

// ---------------------------------------------------------------------------
// attn_norm: attn[row, :] = float(E[row, :]) * rcp(rowsum[row])
// ---------------------------------------------------------------------------
__global__ void __launch_bounds__(256)
attn_norm(const __half* __restrict__ E, const float* __restrict__ rowsum,
          float* __restrict__ A)
{
    const long long row = blockIdx.x;
    const float inv = __frcp_rn(rowsum[row]);
    const uint2* pe = reinterpret_cast<const uint2*>(E + row * (long long)NN_);
    float4* pa = reinterpret_cast<float4*>(A + row * (long long)NN_);
    const int t = threadIdx.x;
#pragma unroll
    for (int i = 0; i < 4; i++) {
        uint2 u = pe[t + i * 256];
        __half2 a = *reinterpret_cast<__half2*>(&u.x);
        __half2 bq = *reinterpret_cast<__half2*>(&u.y);
        float2 fa = __half22float2(a);
        float2 fb = __half22float2(bq);
        float4 o;
        o.x = fa.x * inv; o.y = fa.y * inv;
        o.z = fb.x * inv; o.w = fb.y * inv;
        pa[t + i * 256] = o;
    }
}

// ---------------------------------------------------------------------------
// In-place row LayerNorm
// ---------------------------------------------------------------------------
__global__ void layernorm_rows(float* __restrict__ y,
                               const float* __restrict__ gamma,
                               const float* __restrict__ beta)
{
    const long long base = (long long)blockIdx.x * DD;
    const int t = threadIdx.x;
    const int lane = t & 31, warp = t >> 5;
    __shared__ float red[32];

    float x0 = y[base + t];
    float x1 = y[base + t + 256];

    float s = x0 + x1;
#pragma unroll
    for (int o = 16; o > 0; o >>= 1) s += __shfl_xor_sync(~0u, s, o);
    if (lane == 0) red[warp] = s;
    __syncthreads();
    if (warp == 0) {
        float x = (lane < 8) ? red[lane] : 0.0f;
#pragma unroll
        for (int o = 16; o > 0; o >>= 1) x += __shfl_xor_sync(~0u, x, o);
        if (lane == 0) red[0] = x;
    }
    __syncthreads();
    const float mu = red[0] * (1.0f / DD);
    __syncthreads();

    const float d0 = x0 - mu, d1 = x1 - mu;
    float v = d0 * d0 + d1 * d1;
#pragma unroll
    for (int o = 16; o > 0; o >>= 1) v += __shfl_xor_sync(~0u, v, o);
    if (lane == 0) red[warp] = v;
    __syncthreads();
    if (warp == 0) {
        float x = (lane < 8) ? red[lane] : 0.0f;
#pragma unroll
        for (int o = 16; o > 0; o >>= 1) x += __shfl_xor_sync(~0u, x, o);
        if (lane == 0) red[0] = x;
    }
    __syncthreads();
    const float r = rsqrtf(red[0] * (1.0f / DD) + 1e-5f);

    y[base + t]       = d0 * r * gamma[t]       + beta[t];
    y[base + t + 256] = d1 * r * gamma[t + 256] + beta[t + 256];
}

// ---------------------------------------------------------------------------
extern "C" void kernel_launch(void* const* d_in, const int* in_sizes, int n_in,
                              void* d_out, int out_size)
{
    const float* q    = (const float*)d_in[0];
    const float* k    = (const float*)d_in[1];
    const float* v    = (const float*)d_in[2];
    const float* w_q  = (const float*)d_in[3];
    const float* w_k  = (const float*)d_in[4];
    const float* w_v  = (const float*)d_in[5];
    const float* w_fc = (const float*)d_in[6];
    const float* gam  = (const float*)d_in[7];
    const float* bet  = (const float*)d_in[8];

    float* out  = (float*)d_out;                          // [B,N,D]
    float* attn = out + (long long)BB * NN_ * DD;         // [B,H,N,N]

    float *vp, *rsum;
    __half* eptr;
    cudaGetSymbolAddress((void**)&vp,   g_vp);
    cudaGetSymbolAddress((void**)&rsum, g_rowsum);
    cudaGetSymbolAddress((void**)&eptr, g_e);
    bf16 *xqh, *xql, *xkh, *xkl, *xvh, *xvl;
    bf16 *wqh, *wql, *wkh, *wkl, *wvh, *wvl, *wfh, *wfl;
    bf16 *qph, *qpl, *kph, *kpl, *fth, *ftl;
    __half* vth;
    cudaGetSymbolAddress((void**)&xqh, g_xq_hi); cudaGetSymbolAddress((void**)&xql, g_xq_lo);
    cudaGetSymbolAddress((void**)&xkh, g_xk_hi); cudaGetSymbolAddress((void**)&xkl, g_xk_lo);
    cudaGetSymbolAddress((void**)&xvh, g_xv_hi); cudaGetSymbolAddress((void**)&xvl, g_xv_lo);
    cudaGetSymbolAddress((void**)&wqh, g_wq_hi); cudaGetSymbolAddress((void**)&wql, g_wq_lo);
    cudaGetSymbolAddress((void**)&wkh, g_wk_hi); cudaGetSymbolAddress((void**)&wkl, g_wk_lo);
    cudaGetSymbolAddress((void**)&wvh, g_wv_hi); cudaGetSymbolAddress((void**)&wvl, g_wv_lo);
    cudaGetSymbolAddress((void**)&wfh, g_wf_hi); cudaGetSymbolAddress((void**)&wfl, g_wf_lo);
    cudaGetSymbolAddress((void**)&qph, g_qp_hi); cudaGetSymbolAddress((void**)&qpl, g_qp_lo);
    cudaGetSymbolAddress((void**)&kph, g_kp_hi); cudaGetSymbolAddress((void**)&kpl, g_kp_lo);
    cudaGetSymbolAddress((void**)&vth, g_vpt_h);
    cudaGetSymbolAddress((void**)&fth, g_ft_hi); cudaGetSymbolAddress((void**)&ftl, g_ft_lo);

    cudaFuncSetAttribute(mma_gemm<0>, cudaFuncAttributeMaxDynamicSharedMemorySize, GM_SMEM);
    cudaFuncSetAttribute(mma_gemm<1>, cudaFuncAttributeMaxDynamicSharedMemorySize, GM_SMEM);
    cudaFuncSetAttribute(mma_gemm<2>, cudaFuncAttributeMaxDynamicSharedMemorySize, GM_SMEM);
    cudaFuncSetAttribute(fused_attn, cudaFuncAttributeMaxDynamicSharedMemorySize, FU_SMEM);

    const int M = BB * NN_;          // 8192
    const int n4i = M * DD / 4;
    const int n4w = DD * DD / 4;

    // 1) splits (merged)
    split3<<<dim3((n4i + 255) / 256, 3), 256>>>(q, k, v, xqh, xkh, xvh, xql, xkl, xvl, n4i);
    split4<<<dim3((n4w + 255) / 256, 4), 256>>>(w_q, w_k, w_v, w_fc,
                                                wqh, wkh, wvh, wfh,
                                                wql, wkl, wvl, wfl, n4w);

    // 2) projections on tensor cores (BM=64 tiles)
    {
        dim3 grid(DD / 128, M / 64);
        mma_gemm<2><<<grid, 256, GM_SMEM>>>(xqh, xql, wqh, wql, nullptr, qph, qpl, nullptr);
        mma_gemm<2><<<grid, 256, GM_SMEM>>>(xkh, xkl, wkh, wkl, nullptr, kph, kpl, nullptr);
        mma_gemm<0><<<grid, 256, GM_SMEM>>>(xvh, xvl, wvh, wvl, vp, nullptr, nullptr, nullptr);
    }
    vtrans_f16<<<dim3(NN_ / 32, DD / 32, BB), dim3(32, 8)>>>(vp, vth);

    // 3) fused single-pass attention: E + rowsum + feat hi/lo
    fused_attn<<<dim3(NN_ / 128, BB * HH), 256, FU_SMEM>>>(
        kph, kpl, qph, qpl, vth, eptr, rsum, fth, ftl);

    // 4) normalize attn into output region
    attn_norm<<<BB * HH * NN_, 256>>>(eptr, rsum, attn);

    // 5) fc + residual on tensor cores
    {
        dim3 grid(DD / 128, M / 64);
        mma_gemm<1><<<grid, 256, GM_SMEM>>>(fth, ftl, wfh, wfl, out, nullptr, nullptr, q);
    }

    // 6) LayerNorm
    layernorm_rows<<<M, 256>>>(out, gam, bet);
}

// round 11
// speedup vs baseline: 3.3475x; 1.0868x over previous
#include <cuda_runtime.h>
#include <cuda_bf16.h>
#include <cuda_fp16.h>
#include <math.h>
#include <stdint.h>

#define BB 2
#define NN_ 4096
#define DD 512
#define HH 8
#define DK 64

typedef __nv_bfloat16 bf16;

// ---------------------------------------------------------------------------
// Scratch (device globals — no allocation allowed)
// ---------------------------------------------------------------------------
__device__ float g_vp[BB * NN_ * DD];
__device__ float g_rowsum[BB * HH * NN_];
__device__ __half g_e[(size_t)BB * HH * NN_ * NN_];      // unnormalized exp, fp16

__device__ bf16 g_xq_hi[BB * NN_ * DD]; __device__ bf16 g_xq_lo[BB * NN_ * DD];
__device__ bf16 g_xk_hi[BB * NN_ * DD]; __device__ bf16 g_xk_lo[BB * NN_ * DD];
__device__ bf16 g_xv_hi[BB * NN_ * DD]; __device__ bf16 g_xv_lo[BB * NN_ * DD];
__device__ bf16 g_wq_hi[DD * DD]; __device__ bf16 g_wq_lo[DD * DD];
__device__ bf16 g_wk_hi[DD * DD]; __device__ bf16 g_wk_lo[DD * DD];
__device__ bf16 g_wv_hi[DD * DD]; __device__ bf16 g_wv_lo[DD * DD];
__device__ bf16 g_wf_hi[DD * DD]; __device__ bf16 g_wf_lo[DD * DD];
__device__ __half g_qp_h[BB * NN_ * DD]; __device__ __half g_qp_l[BB * NN_ * DD];
__device__ __half g_kp_h[BB * NN_ * DD]; __device__ __half g_kp_l[BB * NN_ * DD];
__device__ __half g_vpt_h[BB * HH * DK * NN_];           // [bh, d, token] fp16
__device__ bf16 g_ft_hi[BB * NN_ * DD]; __device__ bf16 g_ft_lo[BB * NN_ * DD];

// ---------------------------------------------------------------------------
// PTX helpers
// ---------------------------------------------------------------------------
__device__ __forceinline__ uint32_t smem_u32(const void* p) {
    uint32_t a;
    asm("{ .reg .u64 t; cvta.to.shared.u64 t, %1; cvt.u32.u64 %0, t; }"
        : "=r"(a) : "l"(p));
    return a;
}

#define CP16(dst, src) \
    asm volatile("cp.async.cg.shared.global [%0], [%1], 16;" :: "r"(dst), "l"(src))
#define CP_COMMIT() asm volatile("cp.async.commit_group;" ::: "memory")
#define CP_WAIT0()  asm volatile("cp.async.wait_group 0;" ::: "memory")
#define CP_WAIT1()  asm volatile("cp.async.wait_group 1;" ::: "memory")

__device__ __forceinline__ void ldsm4(uint32_t& r0, uint32_t& r1, uint32_t& r2, uint32_t& r3,
                                      uint32_t addr) {
    asm volatile("ldmatrix.sync.aligned.m8n8.x4.shared.b16 {%0,%1,%2,%3}, [%4];"
                 : "=r"(r0), "=r"(r1), "=r"(r2), "=r"(r3) : "r"(addr));
}

__device__ __forceinline__ void mma16816(float* c,
                                         uint32_t a0, uint32_t a1, uint32_t a2, uint32_t a3,
                                         uint32_t b0, uint32_t b1) {
    asm volatile(
        "mma.sync.aligned.m16n8k16.row.col.f32.bf16.bf16.f32 "
        "{%0,%1,%2,%3}, {%4,%5,%6,%7}, {%8,%9}, {%0,%1,%2,%3};"
        : "+f"(c[0]), "+f"(c[1]), "+f"(c[2]), "+f"(c[3])
        : "r"(a0), "r"(a1), "r"(a2), "r"(a3), "r"(b0), "r"(b1));
}

__device__ __forceinline__ void mma16816h(float* c,
                                          uint32_t a0, uint32_t a1, uint32_t a2, uint32_t a3,
                                          uint32_t b0, uint32_t b1) {
    asm volatile(
        "mma.sync.aligned.m16n8k16.row.col.f32.f16.f16.f32 "
        "{%0,%1,%2,%3}, {%4,%5,%6,%7}, {%8,%9}, {%0,%1,%2,%3};"
        : "+f"(c[0]), "+f"(c[1]), "+f"(c[2]), "+f"(c[3])
        : "r"(a0), "r"(a1), "r"(a2), "r"(a3), "r"(b0), "r"(b1));
}

__device__ __forceinline__ void split1(float x, bf16& h, bf16& l) {
    h = __float2bfloat16(x);
    l = __float2bfloat16(x - __bfloat162float(h));
}

__device__ __forceinline__ void split_body(const float* __restrict__ x,
                                           bf16* __restrict__ hi,
                                           bf16* __restrict__ lo, int i) {
    float4 v = reinterpret_cast<const float4*>(x)[i];
    bf16 h[4], l[4];
    split1(v.x, h[0], l[0]); split1(v.y, h[1], l[1]);
    split1(v.z, h[2], l[2]); split1(v.w, h[3], l[3]);
    uint2 ph, pl;
    ph.x = ((uint32_t)*(uint16_t*)&h[1] << 16) | *(uint16_t*)&h[0];
    ph.y = ((uint32_t)*(uint16_t*)&h[3] << 16) | *(uint16_t*)&h[2];
    pl.x = ((uint32_t)*(uint16_t*)&l[1] << 16) | *(uint16_t*)&l[0];
    pl.y = ((uint32_t)*(uint16_t*)&l[3] << 16) | *(uint16_t*)&l[2];
    reinterpret_cast<uint2*>(hi)[i] = ph;
    reinterpret_cast<uint2*>(lo)[i] = pl;
}

__global__ void split3(const float* x0, const float* x1, const float* x2,
                       bf16* h0, bf16* h1, bf16* h2,
                       bf16* l0, bf16* l1, bf16* l2, int n4)
{
    int i = blockIdx.x * blockDim.x + threadIdx.x;
    if (i >= n4) return;
    int w = blockIdx.y;
    const float* x = (w == 0) ? x0 : (w == 1) ? x1 : x2;
    bf16* hi = (w == 0) ? h0 : (w == 1) ? h1 : h2;
    bf16* lo = (w == 0) ? l0 : (w == 1) ? l1 : l2;
    split_body(x, hi, lo, i);
}

__global__ void split4(const float* x0, const float* x1, const float* x2, const float* x3,
                       bf16* h0, bf16* h1, bf16* h2, bf16* h3,
                       bf16* l0, bf16* l1, bf16* l2, bf16* l3, int n4)
{
    int i = blockIdx.x * blockDim.x + threadIdx.x;
    if (i >= n4) return;
    int w = blockIdx.y;
    const float* x = (w == 0) ? x0 : (w == 1) ? x1 : (w == 2) ? x2 : x3;
    bf16* hi = (w == 0) ? h0 : (w == 1) ? h1 : (w == 2) ? h2 : h3;
    bf16* lo = (w == 0) ? l0 : (w == 1) ? l1 : (w == 2) ? l2 : l3;
    split_body(x, hi, lo, i);
}

// vp [B, N, D] fp32 -> vpT fp16 [B*H, DK, N]
__global__ void vtrans_f16(const float* __restrict__ vp, __half* __restrict__ vt)
{
    __shared__ float tile[32][33];
    const int j0 = blockIdx.x * 32;
    const int c0 = blockIdx.y * 32;
    const int b  = blockIdx.z;
    const int tx = threadIdx.x, ty = threadIdx.y;
    for (int rr = ty; rr < 32; rr += 8)
        tile[rr][tx] = vp[((long long)(b * NN_ + j0 + rr)) * DD + c0 + tx];
    __syncthreads();
    for (int rr = ty; rr < 32; rr += 8) {
        int c = c0 + rr;
        int h = c >> 6, dl = c & 63;
        long long idx = ((long long)(b * HH + h) * DK + dl) * NN_ + j0 + tx;
        vt[idx] = __float2half_rn(tile[tx][rr]);
    }
}

// ---------------------------------------------------------------------------
// Tensor-core GEMM (NT): BM=64, BN=128, BK=32, warp tile 32x32, 2-stage.
// OUTM: 0 fp32; 1 fp32+residual; 2 bf16 hi/lo; 3 fp16 hi/lo.
// ---------------------------------------------------------------------------
#define GM_SMEM 61440
#define GM_STG  30720u

template<int OUTM>
__global__ void __launch_bounds__(256, 2)
mma_gemm(const bf16* __restrict__ Ahi, const bf16* __restrict__ Alo,
         const bf16* __restrict__ Bhi, const bf16* __restrict__ Blo,
         float* __restrict__ Cf, void* __restrict__ Chi_v, void* __restrict__ Clo_v,
         const float* __restrict__ R)
{
    extern __shared__ char smem[];
    const int tid = threadIdx.x;
    const int wid = tid >> 5;
    const int lane = tid & 31;
    const uint32_t sb = smem_u32(smem);
    const int n0 = blockIdx.x * 128;
    const int m0 = blockIdx.y * 64;

    const int wm = (wid >> 2) * 32;
    const int wn = (wid & 3) * 32;

    float acc[2][4][4];
#pragma unroll
    for (int i = 0; i < 2; i++)
#pragma unroll
        for (int j = 0; j < 4; j++)
#pragma unroll
            for (int c = 0; c < 4; c++) acc[i][j][c] = 0.0f;

    auto load_stage = [&](int kt, int s) {
        const int k0 = kt * 32;
        const uint32_t st = sb + (uint32_t)s * GM_STG;
        for (int i = tid; i < 1536; i += 256) {
            if (i < 512) {
                int t = (i >> 8) & 1, r = (i & 255) >> 2, c = i & 3;
                const bf16* src = (t ? Alo : Ahi) + (long long)(m0 + r) * DD + k0 + c * 8;
                CP16(st + (uint32_t)t * 5120u + (uint32_t)(r * 80 + c * 16), (const char*)src);
            } else {
                int j = i - 512;
                int t = j >> 9, r = (j & 511) >> 2, c = j & 3;
                const bf16* src = (t ? Blo : Bhi) + (long long)(n0 + r) * DD + k0 + c * 8;
                CP16(st + 10240u + (uint32_t)t * 10240u + (uint32_t)(r * 80 + c * 16),
                     (const char*)src);
            }
        }
    };

    load_stage(0, 0); CP_COMMIT();

    for (int kt = 0; kt < 16; kt++) {
        if (kt < 15) { load_stage(kt + 1, (kt + 1) & 1); CP_COMMIT(); CP_WAIT1(); }
        else { CP_WAIT0(); }
        __syncthreads();
        const uint32_t st = sb + (uint32_t)(kt & 1) * GM_STG;
#pragma unroll
        for (int prod = 0; prod < 3; prod++) {
            const uint32_t Ab = st + ((prod == 1) ? 5120u : 0u);
            const uint32_t Bb = st + 10240u + ((prod == 2) ? 10240u : 0u);
#pragma unroll
            for (int kc = 0; kc < 2; kc++) {
                const uint32_t colA = (uint32_t)(kc * 32 + ((lane >> 4) & 1) * 16);
                const uint32_t colB = (uint32_t)(kc * 32 + ((lane >> 3) & 1) * 16);
                uint32_t bf[8];
#pragma unroll
                for (int j = 0; j < 2; j++) {
                    int n = wn + j * 16 + ((lane >> 4) & 1) * 8 + (lane & 7);
                    ldsm4(bf[j * 4 + 0], bf[j * 4 + 1], bf[j * 4 + 2], bf[j * 4 + 3],
                          Bb + (uint32_t)(n * 80) + colB);
                }
#pragma unroll
                for (int mi = 0; mi < 2; mi++) {
                    uint32_t a0, a1, a2, a3;
                    int m = wm + mi * 16 + (lane & 15);
                    ldsm4(a0, a1, a2, a3, Ab + (uint32_t)(m * 80) + colA);
#pragma unroll
                    for (int j = 0; j < 2; j++) {
                        mma16816(acc[mi][2 * j],     a0, a1, a2, a3, bf[j * 4 + 0], bf[j * 4 + 1]);
                        mma16816(acc[mi][2 * j + 1], a0, a1, a2, a3, bf[j * 4 + 2], bf[j * 4 + 3]);
                    }
                }
            }
        }
        __syncthreads();
    }

#pragma unroll
    for (int mi = 0; mi < 2; mi++) {
#pragma unroll
        for (int ni = 0; ni < 4; ni++) {
            int r  = wm + mi * 16 + (lane >> 2);
            int cc = wn + ni * 8 + (lane & 3) * 2;
#pragma unroll
            for (int half = 0; half < 2; half++) {
                int row = m0 + r + half * 8;
                int col = n0 + cc;
                float v0 = acc[mi][ni][half * 2 + 0];
                float v1 = acc[mi][ni][half * 2 + 1];
                if (OUTM == 2) {
                    bf16 h0, l0, h1, l1;
                    split1(v0, h0, l0); split1(v1, h1, l1);
                    uint32_t ph = ((uint32_t)*(uint16_t*)&h1 << 16) | *(uint16_t*)&h0;
                    uint32_t pl = ((uint32_t)*(uint16_t*)&l1 << 16) | *(uint16_t*)&l0;
                    *reinterpret_cast<uint32_t*>((bf16*)Chi_v + (long long)row * DD + col) = ph;
                    *reinterpret_cast<uint32_t*>((bf16*)Clo_v + (long long)row * DD + col) = pl;
                } else if (OUTM == 3) {
                    __half h0 = __float2half_rn(v0);
                    __half l0 = __float2half_rn(v0 - __half2float(h0));
                    __half h1 = __float2half_rn(v1);
                    __half l1 = __float2half_rn(v1 - __half2float(h1));
                    uint32_t ph = ((uint32_t)*(uint16_t*)&h1 << 16) | *(uint16_t*)&h0;
                    uint32_t pl = ((uint32_t)*(uint16_t*)&l1 << 16) | *(uint16_t*)&l0;
                    *reinterpret_cast<uint32_t*>((__half*)Chi_v + (long long)row * DD + col) = ph;
                    *reinterpret_cast<uint32_t*>((__half*)Clo_v + (long long)row * DD + col) = pl;
                } else {
                    if (OUTM == 1) {
                        float2 r2 = *reinterpret_cast<const float2*>(R + (long long)row * DD + col);
                        v0 += r2.x; v1 += r2.y;
                    }
                    float2 o; o.x = v0; o.y = v1;
                    *reinterpret_cast<float2*>(Cf + (long long)row * DD + col) = o;
                }
            }
        }
    }
}

// ---------------------------------------------------------------------------
// Fused attention, single pass, fp16 asymmetric scores (2 products):
// S = K_hi@Q_hi^T + K_lo@Q_hi^T   (fp16 mma, fp32 acc)
// e = exp(0.125 S) -> fp16 -> E scratch + P@V (fp16). nb = 64 Q-rows/step.
// smem: K 36KB + Q 2x9KB + V 2x9KB = 72KB -> 2 CTAs/SM.
// ---------------------------------------------------------------------------
#define FU_SMEM 73728
#define FU_KHI 0u
#define FU_KLO 18432u
#define FU_Q0  36864u
#define FU_QST 9216u
#define FU_V0  55296u
#define FU_VST 9216u

__global__ void __launch_bounds__(256, 2)
fused_attn(const __half* __restrict__ Khi, const __half* __restrict__ Klo,
           const __half* __restrict__ Qhi,
           const __half* __restrict__ Vh,
           __half* __restrict__ E, float* __restrict__ rowsum,
           bf16* __restrict__ Fhi, bf16* __restrict__ Flo)
{
    extern __shared__ char smem[];
    const int tid = threadIdx.x;
    const int wid = tid >> 5;
    const int lane = tid & 31;
    const uint32_t sb = smem_u32(smem);

    const int m0 = blockIdx.x * 128;
    const int bh = blockIdx.y;
    const int b = bh >> 3, h = bh & 7;
    const long long arow = (long long)(b * NN_ + m0);
    const int coff = h * DK;
    const long long vrow = (long long)bh * DK;

    // resident K tile (fp16 hi/lo), 144B pitch, 128 rows
    for (int i = tid; i < 2048; i += 256) {
        int t = i >> 10, r = (i & 1023) >> 3, c = i & 7;
        const __half* src = (t ? Klo : Khi) + (arow + r) * DD + coff + c * 8;
        CP16(sb + (uint32_t)t * 18432u + (uint32_t)(r * 144 + c * 16), (const char*)src);
    }

    auto load_Q = [&](int nb, int s) {
        const long long brow = (long long)b * NN_ + (long long)nb * 64;
        const uint32_t st = sb + FU_Q0 + (uint32_t)s * FU_QST;
        for (int i = tid; i < 512; i += 256) {
            int r = i >> 3, c = i & 7;
            const __half* src = Qhi + (brow + r) * DD + coff + c * 8;
            CP16(st + (uint32_t)(r * 144 + c * 16), (const char*)src);
        }
    };
    auto load_V = [&](int nb, int s) {
        const uint32_t st = sb + FU_V0 + (uint32_t)s * FU_VST;
        for (int i = tid; i < 512; i += 256) {
            int r = i >> 3, c = i & 7;
            CP16(st + (uint32_t)(r * 144 + c * 16),
                 (const char*)(Vh + (vrow + r) * NN_ + nb * 64 + c * 8));
        }
    };

    const int gid = lane >> 2, tig = lane & 3;
    const long long ebase = (long long)bh * NN_ * NN_;
    const int mrow = m0 + wid * 16 + gid;

    float rs0 = 0.0f, rs1 = 0.0f;
    float facc[8][4];
#pragma unroll
    for (int i = 0; i < 8; i++)
#pragma unroll
        for (int c = 0; c < 4; c++) facc[i][c] = 0.0f;

    load_Q(0, 0); load_V(0, 0); CP_COMMIT();

    for (int nb = 0; nb < 64; nb++) {
        if (nb < 63) {
            load_Q(nb + 1, (nb + 1) & 1);
            load_V(nb + 1, (nb + 1) & 1);
            CP_COMMIT(); CP_WAIT1();
        } else { CP_WAIT0(); }
        __syncthreads();

        const uint32_t Qst = sb + FU_Q0 + (uint32_t)(nb & 1) * FU_QST;
        const uint32_t Vst = sb + FU_V0 + (uint32_t)(nb & 1) * FU_VST;

        float sacc[8][4];
#pragma unroll
        for (int i = 0; i < 8; i++)
#pragma unroll
            for (int c = 0; c < 4; c++) sacc[i][c] = 0.0f;

        // scores: 2 fp16 products (K_hi + K_lo) x Q_hi
#pragma unroll
        for (int prod = 0; prod < 2; prod++) {
            const uint32_t Ab = sb + ((prod == 1) ? FU_KLO : FU_KHI);
#pragma unroll
            for (int kc = 0; kc < 4; kc++) {
                const uint32_t colA = (uint32_t)(kc * 32 + ((lane >> 4) & 1) * 16);
                const uint32_t colB = (uint32_t)(kc * 32 + ((lane >> 3) & 1) * 16);
                uint32_t a0, a1, a2, a3;
                ldsm4(a0, a1, a2, a3,
                      Ab + (uint32_t)((wid * 16 + (lane & 15)) * 144) + colA);
#pragma unroll
                for (int j = 0; j < 4; j++) {
                    int n = j * 16 + ((lane >> 4) & 1) * 8 + (lane & 7);
                    uint32_t q0, q1, q2, q3;
                    ldsm4(q0, q1, q2, q3, Qst + (uint32_t)(n * 144) + colB);
                    mma16816h(sacc[2 * j],     a0, a1, a2, a3, q0, q1);
                    mma16816h(sacc[2 * j + 1], a0, a1, a2, a3, q2, q3);
                }
            }
        }

        // exp -> fp16 (store to E AND feed P@V), rowsum in registers
#pragma unroll
        for (int kch = 0; kch < 4; kch++) {
            uint32_t a0, a1, a2, a3;
#pragma unroll
            for (int jj = 0; jj < 2; jj++) {
                int j = 2 * kch + jj;
                float e0 = __expf(0.125f * sacc[j][0]);
                float e1 = __expf(0.125f * sacc[j][1]);
                float e2 = __expf(0.125f * sacc[j][2]);
                float e3 = __expf(0.125f * sacc[j][3]);
                rs0 += e0 + e1;
                rs1 += e2 + e3;
                __half2 h01 = __floats2half2_rn(e0, e1);
                __half2 h23 = __floats2half2_rn(e2, e3);
                long long colg = (long long)nb * 64 + j * 8 + tig * 2;
                *reinterpret_cast<uint32_t*>(E + ebase + (long long)mrow * NN_ + colg) =
                    *reinterpret_cast<uint32_t*>(&h01);
                *reinterpret_cast<uint32_t*>(E + ebase + (long long)(mrow + 8) * NN_ + colg) =
                    *reinterpret_cast<uint32_t*>(&h23);
                if (jj == 0) { a0 = *reinterpret_cast<uint32_t*>(&h01);
                               a1 = *reinterpret_cast<uint32_t*>(&h23); }
                else         { a2 = *reinterpret_cast<uint32_t*>(&h01);
                               a3 = *reinterpret_cast<uint32_t*>(&h23); }
            }
            const uint32_t colV = (uint32_t)(kch * 32 + ((lane >> 3) & 1) * 16);
#pragma unroll
            for (int vj = 0; vj < 4; vj++) {
                int n = vj * 16 + ((lane >> 4) & 1) * 8 + (lane & 7);
                uint32_t v0, v1, v2, v3;
                ldsm4(v0, v1, v2, v3, Vst + (uint32_t)(n * 144) + colV);
                mma16816h(facc[2 * vj],     a0, a1, a2, a3, v0, v1);
                mma16816h(facc[2 * vj + 1], a0, a1, a2, a3, v2, v3);
            }
        }
        __syncthreads();
    }

    // rowsum reduce across quad, write to gmem, scale feat
    rs0 += __shfl_xor_sync(~0u, rs0, 1);
    rs0 += __shfl_xor_sync(~0u, rs0, 2);
    rs1 += __shfl_xor_sync(~0u, rs1, 1);
    rs1 += __shfl_xor_sync(~0u, rs1, 2);
    const float inv0 = __frcp_rn(rs0);
    const float inv1 = __frcp_rn(rs1);
    if (tig == 0) {
        rowsum[(long long)bh * NN_ + mrow]     = rs0;
        rowsum[(long long)bh * NN_ + mrow + 8] = rs1;
    }

#pragma unroll
    for (int n8 = 0; n8 < 8; n8++) {
        int col = h * DK + n8 * 8 + tig * 2;
#pragma unroll
        for (int half = 0; half < 2; half++) {
            long long row = (long long)(b * NN_ + mrow + half * 8);
            float inv = half ? inv1 : inv0;
            float v0 = facc[n8][half * 2 + 0] * inv;
            float v1 = facc[n8][half * 2 + 1] * inv;
            bf16 h0, l0, h1, l1;
            split1(v0, h0, l0); split1(v1, h1, l1);
            uint32_t ph = ((uint32_t)*(uint16_t*)&h1 << 16) | *(uint16_t*)&h0;
            uint32_t pl = ((uint32_t)*(uint16_t*)&l1 << 16) | *(uint16_t*)&l0;
            *reinterpret_cast<uint32_t*>(Fhi + row * DD + col) = ph;
            *reinterpret_cast<uint32_t*>(Flo + row * DD + col) = pl;
        }
    }
}

// ---------------------------------------------------------------------------
// attn_norm: attn[row, :] = float(E[row, :]) * rcp(rowsum[row])
// ---------------------------------------------------------------------------
__global__ void __launch_bounds__(256)
attn_norm(const __half* __restrict__ E, const float* __restrict__ rowsum,
          float* __restrict__ A)
{
    const long long row = blockIdx.x;
    const float inv = __frcp_rn(rowsum[row]);
    const uint2* pe = reinterpret_cast<const uint2*>(E + row * (long long)NN_);
    float4* pa = reinterpret_cast<float4*>(A + row * (long long)NN_);
    const int t = threadIdx.x;
#pragma unroll
    for (int i = 0; i < 4; i++) {
        uint2 u = pe[t + i * 256];
        __half2 a = *reinterpret_cast<__half2*>(&u.x);
        __half2 bq = *reinterpret_cast<__half2*>(&u.y);
        float2 fa = __half22float2(a);
        float2 fb = __half22float2(bq);
        float4 o;
        o.x = fa.x * inv; o.y = fa.y * inv;
        o.z = fb.x * inv; o.w = fb.y * inv;
        pa[t + i * 256] = o;
    }
}

// ---------------------------------------------------------------------------
// In-place row LayerNorm
// ---------------------------------------------------------------------------
__global__ void layernorm_rows(float* __restrict__ y,
                               const float* __restrict__ gamma,
                               const float* __restrict__ beta)
{
    const long long base = (long long)blockIdx.x * DD;
    const int t = threadIdx.x;
    const int lane = t & 31, warp = t >> 5;
    __shared__ float red[32];

    float x0 = y[base + t];
    float x1 = y[base + t + 256];

    float s = x0 + x1;
#pragma unroll
    for (int o = 16; o > 0; o >>= 1) s += __shfl_xor_sync(~0u, s, o);
    if (lane == 0) red[warp] = s;
    __syncthreads();
    if (warp == 0) {
        float x = (lane < 8) ? red[lane] : 0.0f;
#pragma unroll
        for (int o = 16; o > 0; o >>= 1) x += __shfl_xor_sync(~0u, x, o);
        if (lane == 0) red[0] = x;
    }
    __syncthreads();
    const float mu = red[0] * (1.0f / DD);
    __syncthreads();

    const float d0 = x0 - mu, d1 = x1 - mu;
    float v = d0 * d0 + d1 * d1;
#pragma unroll
    for (int o = 16; o > 0; o >>= 1) v += __shfl_xor_sync(~0u, v, o);
    if (lane == 0) red[warp] = v;
    __syncthreads();
    if (warp == 0) {
        float x = (lane < 8) ? red[lane] : 0.0f;
#pragma unroll
        for (int o = 16; o > 0; o >>= 1) x += __shfl_xor_sync(~0u, x, o);
        if (lane == 0) red[0] = x;
    }
    __syncthreads();
    const float r = rsqrtf(red[0] * (1.0f / DD) + 1e-5f);

    y[base + t]       = d0 * r * gamma[t]       + beta[t];
    y[base + t + 256] = d1 * r * gamma[t + 256] + beta[t + 256];
}

// ---------------------------------------------------------------------------
extern "C" void kernel_launch(void* const* d_in, const int* in_sizes, int n_in,
                              void* d_out, int out_size)
{
    const float* q    = (const float*)d_in[0];
    const float* k    = (const float*)d_in[1];
    const float* v    = (const float*)d_in[2];
    const float* w_q  = (const float*)d_in[3];
    const float* w_k  = (const float*)d_in[4];
    const float* w_v  = (const float*)d_in[5];
    const float* w_fc = (const float*)d_in[6];
    const float* gam  = (const float*)d_in[7];
    const float* bet  = (const float*)d_in[8];

    float* out  = (float*)d_out;                          // [B,N,D]
    float* attn = out + (long long)BB * NN_ * DD;         // [B,H,N,N]

    float *vp, *rsum;
    __half* eptr;
    cudaGetSymbolAddress((void**)&vp,   g_vp);
    cudaGetSymbolAddress((void**)&rsum, g_rowsum);
    cudaGetSymbolAddress((void**)&eptr, g_e);
    bf16 *xqh, *xql, *xkh, *xkl, *xvh, *xvl;
    bf16 *wqh, *wql, *wkh, *wkl, *wvh, *wvl, *wfh, *wfl;
    bf16 *fth, *ftl;
    __half *qph, *qpl, *kph, *kpl, *vth;
    cudaGetSymbolAddress((void**)&xqh, g_xq_hi); cudaGetSymbolAddress((void**)&xql, g_xq_lo);
    cudaGetSymbolAddress((void**)&xkh, g_xk_hi); cudaGetSymbolAddress((void**)&xkl, g_xk_lo);
    cudaGetSymbolAddress((void**)&xvh, g_xv_hi); cudaGetSymbolAddress((void**)&xvl, g_xv_lo);
    cudaGetSymbolAddress((void**)&wqh, g_wq_hi); cudaGetSymbolAddress((void**)&wql, g_wq_lo);
    cudaGetSymbolAddress((void**)&wkh, g_wk_hi); cudaGetSymbolAddress((void**)&wkl, g_wk_lo);
    cudaGetSymbolAddress((void**)&wvh, g_wv_hi); cudaGetSymbolAddress((void**)&wvl, g_wv_lo);
    cudaGetSymbolAddress((void**)&wfh, g_wf_hi); cudaGetSymbolAddress((void**)&wfl, g_wf_lo);
    cudaGetSymbolAddress((void**)&qph, g_qp_h); cudaGetSymbolAddress((void**)&qpl, g_qp_l);
    cudaGetSymbolAddress((void**)&kph, g_kp_h); cudaGetSymbolAddress((void**)&kpl, g_kp_l);
    cudaGetSymbolAddress((void**)&vth, g_vpt_h);
    cudaGetSymbolAddress((void**)&fth, g_ft_hi); cudaGetSymbolAddress((void**)&ftl, g_ft_lo);

    cudaFuncSetAttribute(mma_gemm<0>, cudaFuncAttributeMaxDynamicSharedMemorySize, GM_SMEM);
    cudaFuncSetAttribute(mma_gemm<1>, cudaFuncAttributeMaxDynamicSharedMemorySize, GM_SMEM);
    cudaFuncSetAttribute(mma_gemm<3>, cudaFuncAttributeMaxDynamicSharedMemorySize, GM_SMEM);
    cudaFuncSetAttribute(fused_attn, cudaFuncAttributeMaxDynamicSharedMemorySize, FU_SMEM);

    const int M = BB * NN_;          // 8192
    const int n4i = M * DD / 4;
    const int n4w = DD * DD / 4;

    // 1) splits (merged)
    split3<<<dim3((n4i + 255) / 256, 3), 256>>>(q, k, v, xqh, xkh, xvh, xql, xkl, xvl, n4i);
    split4<<<dim3((n4w + 255) / 256, 4), 256>>>(w_q, w_k, w_v, w_fc,
                                                wqh, wkh, wvh, wfh,
                                                wql, wkl, wvl, wfl, n4w);

    // 2) projections on tensor cores; Q/K emit fp16 hi/lo, V fp32
    {
        dim3 grid(DD / 128, M / 64);
        mma_gemm<3><<<grid, 256, GM_SMEM>>>(xqh, xql, wqh, wql, nullptr, qph, qpl, nullptr);
        mma_gemm<3><<<grid, 256, GM_SMEM>>>(xkh, xkl, wkh, wkl, nullptr, kph, kpl, nullptr);
        mma_gemm<0><<<grid, 256, GM_SMEM>>>(xvh, xvl, wvh, wvl, vp, nullptr, nullptr, nullptr);
    }
    vtrans_f16<<<dim3(NN_ / 32, DD / 32, BB), dim3(32, 8)>>>(vp, vth);

    // 3) fused single-pass attention (2-product fp16 scores)
    fused_attn<<<dim3(NN_ / 128, BB * HH), 256, FU_SMEM>>>(
        kph, kpl, qph, vth, eptr, rsum, fth, ftl);

    // 4) normalize attn into output region
    attn_norm<<<BB * HH * NN_, 256>>>(eptr, rsum, attn);

    // 5) fc + residual on tensor cores
    {
        dim3 grid(DD / 128, M / 64);
        mma_gemm<1><<<grid, 256, GM_SMEM>>>(fth, ftl, wfh, wfl, out, nullptr, nullptr, q);
    }

    // 6) LayerNorm
    layernorm_rows<<<M, 256>>>(out, gam, bet);
}